// round 2
// baseline (speedup 1.0000x reference)
#include <cuda_runtime.h>
#include <math.h>

#define BB 8
#define NTOK 2048
#define CLIPD 512
#define DD 256
#define BDIM 128
#define NCLS 10
#define ROWS (BB * NTOK)   // 16384

// ---------------- scratch (no cudaMalloc allowed) ----------------
__device__ float g_h  [ROWS * DD];            // 16 MB
__device__ float g_q  [ROWS * DD];
__device__ float g_k  [ROWS * DD];
__device__ float g_v  [ROWS * DD];
__device__ float g_s  [BB * NTOK * NTOK];     // 134 MB scores/attn
__device__ float g_agg[ROWS * DD];
__device__ float g_o  [ROWS * BDIM];          // 8 MB

// ---------------- block reductions ----------------
__device__ __forceinline__ float blk_sum(float v) {
    __shared__ float sh[33];
    int lane = threadIdx.x & 31, w = threadIdx.x >> 5;
#pragma unroll
    for (int o = 16; o; o >>= 1) v += __shfl_xor_sync(0xffffffffu, v, o);
    __syncthreads();
    if (lane == 0) sh[w] = v;
    __syncthreads();
    if (threadIdx.x == 0) {
        float s = 0.f; int nw = (blockDim.x + 31) >> 5;
        for (int i = 0; i < nw; i++) s += sh[i];
        sh[32] = s;
    }
    __syncthreads();
    return sh[32];
}

__device__ __forceinline__ float blk_max(float v) {
    __shared__ float sh[33];
    int lane = threadIdx.x & 31, w = threadIdx.x >> 5;
#pragma unroll
    for (int o = 16; o; o >>= 1) v = fmaxf(v, __shfl_xor_sync(0xffffffffu, v, o));
    __syncthreads();
    if (lane == 0) sh[w] = v;
    __syncthreads();
    if (threadIdx.x == 0) {
        float s = -INFINITY; int nw = (blockDim.x + 31) >> 5;
        for (int i = 0; i < nw; i++) s = fmaxf(s, sh[i]);
        sh[32] = s;
    }
    __syncthreads();
    return sh[32];
}

// ---------------- SGEMM: C = alpha * A @ B(^T) + bias ----------------
// A: M x K row-major. TRANS_B=false: B is K x N row-major. TRANS_B=true: B is N x K row-major.
// 128x128 block tile, K-tile 8, 256 threads, 8x8 per thread. Requires M%128==0, N%128==0, K%8==0.
template <bool TRANS_B>
__global__ void __launch_bounds__(256) sgemm(
    const float* __restrict__ A, const float* __restrict__ B, float* __restrict__ C,
    int M, int N, int K,
    long strideA, long strideB, long strideC,
    float alpha, const float* __restrict__ bias)
{
    __shared__ float As[8][128];
    __shared__ float Bs[8][128];

    const int bz = blockIdx.z;
    A += (long)bz * strideA;
    B += (long)bz * strideB;
    C += (long)bz * strideC;

    const int tid = threadIdx.x;
    const int tx = tid & 15;          // 0..15 -> N microtile
    const int ty = tid >> 4;          // 0..15 -> M microtile
    const int row0 = blockIdx.y * 128;
    const int col0 = blockIdx.x * 128;

    const int ar = tid >> 1;          // 0..127
    const int ak = (tid & 1) * 4;     // 0 or 4

    float acc[8][8];
#pragma unroll
    for (int i = 0; i < 8; i++)
#pragma unroll
        for (int j = 0; j < 8; j++) acc[i][j] = 0.f;

    for (int k0 = 0; k0 < K; k0 += 8) {
        // A tile (128 rows x 8 k), stored transposed As[k][row]
        float4 av = *(const float4*)&A[(long)(row0 + ar) * K + k0 + ak];
        As[ak + 0][ar] = av.x; As[ak + 1][ar] = av.y;
        As[ak + 2][ar] = av.z; As[ak + 3][ar] = av.w;

        if (TRANS_B) {
            // B row-major N x K : Bs[k][n] = B[(col0+n)*K + k0+k]
            float4 bv = *(const float4*)&B[(long)(col0 + ar) * K + k0 + ak];
            Bs[ak + 0][ar] = bv.x; Bs[ak + 1][ar] = bv.y;
            Bs[ak + 2][ar] = bv.z; Bs[ak + 3][ar] = bv.w;
        } else {
            // B row-major K x N : Bs[k][n] = B[(k0+k)*N + col0+n]
            const int br = tid >> 5;          // 0..7
            const int bc = (tid & 31) * 4;    // 0..124
            float4 bv = *(const float4*)&B[(long)(k0 + br) * N + col0 + bc];
            *(float4*)&Bs[br][bc] = bv;
        }
        __syncthreads();

#pragma unroll
        for (int kk = 0; kk < 8; kk++) {
            float a[8], b[8];
            *(float4*)&a[0] = *(const float4*)&As[kk][ty * 8];
            *(float4*)&a[4] = *(const float4*)&As[kk][ty * 8 + 4];
            *(float4*)&b[0] = *(const float4*)&Bs[kk][tx * 8];
            *(float4*)&b[4] = *(const float4*)&Bs[kk][tx * 8 + 4];
#pragma unroll
            for (int i = 0; i < 8; i++)
#pragma unroll
                for (int j = 0; j < 8; j++)
                    acc[i][j] += a[i] * b[j];
        }
        __syncthreads();
    }

#pragma unroll
    for (int i = 0; i < 8; i++) {
        const long r = row0 + ty * 8 + i;
#pragma unroll
        for (int j = 0; j < 8; j += 4) {
            const int c = col0 + tx * 8 + j;
            float4 o;
            o.x = alpha * acc[i][j + 0] + (bias ? bias[c + 0] : 0.f);
            o.y = alpha * acc[i][j + 1] + (bias ? bias[c + 1] : 0.f);
            o.z = alpha * acc[i][j + 2] + (bias ? bias[c + 2] : 0.f);
            o.w = alpha * acc[i][j + 3] + (bias ? bias[c + 3] : 0.f);
            *(float4*)&C[r * N + c] = o;
        }
    }
}

// ---------------- LayerNorm + ReLU (in place), blockDim.x == D ----------------
__global__ void ln_relu_kernel(float* __restrict__ X, const float* __restrict__ g,
                               const float* __restrict__ beta, int D)
{
    const long row = blockIdx.x;
    const int t = threadIdx.x;
    float v = X[row * D + t];
    float mu = blk_sum(v) * (1.f / D);
    float d = v - mu;
    float var = blk_sum(d * d) * (1.f / D);
    float r = d * rsqrtf(var + 1e-5f) * g[t] + beta[t];
    X[row * D + t] = fmaxf(r, 0.f);
}

// ---------------- softmax * spatial_adj * (1 - mask), in place on scores row ----------------
__global__ void __launch_bounds__(256) softmax_adj_kernel(
    float* __restrict__ S, const float* __restrict__ coords,
    const int* __restrict__ mask, const float* __restrict__ gamma)
{
    const int b = blockIdx.y;
    const int n = blockIdx.x;
    float* row = S + ((long)b * NTOK + n) * NTOK;
    const int t = threadIdx.x;  // 256 threads, 8 elems each

    float s[8];
    float mx = -INFINITY;
#pragma unroll
    for (int j = 0; j < 8; j++) {
        s[j] = row[t + j * 256];
        mx = fmaxf(mx, s[j]);
    }
    mx = blk_max(mx);

    float lsum = 0.f;
#pragma unroll
    for (int j = 0; j < 8; j++) {
        s[j] = __expf(s[j] - mx);
        lsum += s[j];
    }
    float inv = 1.f / blk_sum(lsum);

    const float ga = fabsf(gamma[0]);
    const float xn = coords[((long)b * NTOK + n) * 2 + 0];
    const float yn = coords[((long)b * NTOK + n) * 2 + 1];
    const float sqn = xn * xn + yn * yn;

#pragma unroll
    for (int j = 0; j < 8; j++) {
        const int m = t + j * 256;
        const float xm = coords[((long)b * NTOK + m) * 2 + 0];
        const float ym = coords[((long)b * NTOK + m) * 2 + 1];
        float d2 = sqn + xm * xm + ym * ym - 2.f * (xn * xm + yn * ym);
        float dist = sqrtf(fmaxf(d2, 0.f));
        float adj = __expf(-dist * ga);
        float w = mask[b * NTOK + m] ? 0.f : s[j] * inv * adj;
        row[m] = w;
    }
}

// ---------------- masked mean pool: pooled[b, d] ----------------
__global__ void pool_kernel(const float* __restrict__ out,
                            const int* __restrict__ mask,
                            float* __restrict__ pooled)
{
    const int b = blockIdx.x;
    const int t = threadIdx.x;  // 128
    __shared__ float sc[128];
    float c = 0.f;
    for (int n = t; n < NTOK; n += 128) c += mask[b * NTOK + n] ? 0.f : 1.f;
    sc[t] = c;
    __syncthreads();
    for (int o = 64; o; o >>= 1) { if (t < o) sc[t] += sc[t + o]; __syncthreads(); }
    const float cnt = fmaxf(sc[0], 1e-9f);

    float s = 0.f;
    const float* base = out + (long)b * NTOK * BDIM + t;
    const int* mb = mask + b * NTOK;
    for (int n = 0; n < NTOK; n++) {
        float val = base[(long)n * BDIM];
        s += mb[n] ? 0.f : val;
    }
    pooled[b * BDIM + t] = s / cnt;
}

// ---------------- head MLP: logits[b] ----------------
__global__ void head_kernel(const float* __restrict__ pooled,
                            const float* __restrict__ c1w, const float* __restrict__ c1b,
                            const float* __restrict__ c2w, const float* __restrict__ c2b,
                            float* __restrict__ logits)
{
    const int b = blockIdx.x;
    const int t = threadIdx.x;  // 64
    __shared__ float sp[BDIM];
    __shared__ float hid[64];
    for (int i = t; i < BDIM; i += 64) sp[i] = pooled[b * BDIM + i];
    __syncthreads();
    float s = c1b[t];
    for (int i = 0; i < BDIM; i++) s += sp[i] * c1w[i * 64 + t];
    hid[t] = fmaxf(s, 0.f);
    __syncthreads();
    if (t < NCLS) {
        float l = c2b[t];
        for (int j = 0; j < 64; j++) l += hid[j] * c2w[j * NCLS + t];
        logits[b * NCLS + t] = l;
    }
}

// ---------------- launch ----------------
extern "C" void kernel_launch(void* const* d_in, const int* in_sizes, int n_in,
                              void* d_out, int out_size)
{
    const float* local_feat = (const float*)d_in[0];
    const float* coords     = (const float*)d_in[1];
    const int*   mask       = (const int*)d_in[2];
    const float* enc_w      = (const float*)d_in[3];
    const float* enc_b      = (const float*)d_in[4];
    const float* enc_g      = (const float*)d_in[5];
    const float* enc_beta   = (const float*)d_in[6];
    const float* gamma      = (const float*)d_in[7];
    const float* wq         = (const float*)d_in[8];
    const float* bq         = (const float*)d_in[9];
    const float* wk         = (const float*)d_in[10];
    const float* bk         = (const float*)d_in[11];
    const float* wv         = (const float*)d_in[12];
    const float* bv         = (const float*)d_in[13];
    const float* bn_w       = (const float*)d_in[14];
    const float* bn_b       = (const float*)d_in[15];
    const float* bn_g       = (const float*)d_in[16];
    const float* bn_beta    = (const float*)d_in[17];
    const float* c1_w       = (const float*)d_in[18];
    const float* c1_b       = (const float*)d_in[19];
    const float* c2_w       = (const float*)d_in[20];
    const float* c2_b       = (const float*)d_in[21];

    float *h, *q, *k, *v, *s, *agg, *o;
    cudaGetSymbolAddress((void**)&h,   g_h);
    cudaGetSymbolAddress((void**)&q,   g_q);
    cudaGetSymbolAddress((void**)&k,   g_k);
    cudaGetSymbolAddress((void**)&v,   g_v);
    cudaGetSymbolAddress((void**)&s,   g_s);
    cudaGetSymbolAddress((void**)&agg, g_agg);
    cudaGetSymbolAddress((void**)&o,   g_o);

    // 1) enc GEMM + bias : h = local_feat @ enc_w + enc_b
    sgemm<false><<<dim3(DD / 128, ROWS / 128, 1), 256>>>(
        local_feat, enc_w, h, ROWS, DD, CLIPD, 0, 0, 0, 1.f, enc_b);
    // 2) LN + relu (in place)
    ln_relu_kernel<<<ROWS, DD>>>(h, enc_g, enc_beta, DD);

    // 3) q, k, v
    sgemm<false><<<dim3(DD / 128, ROWS / 128, 1), 256>>>(h, wq, q, ROWS, DD, DD, 0, 0, 0, 1.f, bq);
    sgemm<false><<<dim3(DD / 128, ROWS / 128, 1), 256>>>(h, wk, k, ROWS, DD, DD, 0, 0, 0, 1.f, bk);
    sgemm<false><<<dim3(DD / 128, ROWS / 128, 1), 256>>>(h, wv, v, ROWS, DD, DD, 0, 0, 0, 1.f, bv);

    // 4) scores = q @ k^T / sqrt(D), batched over B
    sgemm<true><<<dim3(NTOK / 128, NTOK / 128, BB), 256>>>(
        q, k, s, NTOK, NTOK, DD,
        (long)NTOK * DD, (long)NTOK * DD, (long)NTOK * NTOK,
        0.0625f, nullptr);

    // 5) softmax * spatial_adj * notmask, in place
    softmax_adj_kernel<<<dim3(NTOK, BB), 256>>>(s, coords, mask, gamma);

    // 6) agg = attn @ v, batched
    sgemm<false><<<dim3(DD / 128, NTOK / 128, BB), 256>>>(
        s, v, agg, NTOK, DD, NTOK,
        (long)NTOK * NTOK, (long)NTOK * DD, (long)NTOK * DD,
        1.f, nullptr);

    // 7) bn GEMM + bias : o = agg @ bn_w + bn_b
    sgemm<false><<<dim3(BDIM / 128, ROWS / 128, 1), 256>>>(
        agg, bn_w, o, ROWS, BDIM, DD, 0, 0, 0, 1.f, bn_b);
    // 8) LN + relu (in place)
    ln_relu_kernel<<<ROWS, BDIM>>>(o, bn_g, bn_beta, BDIM);

    // 9) masked mean pool -> d_out[80 : 80+1024]
    float* out_f = (float*)d_out;
    pool_kernel<<<BB, BDIM>>>(o, mask, out_f + BB * NCLS);

    // 10) MLP head -> d_out[0 : 80]
    head_kernel<<<BB, 64>>>(out_f + BB * NCLS, c1_w, c1_b, c2_w, c2_b, out_f);
}

// round 4
// speedup vs baseline: 1.6432x; 1.6432x over previous
#include <cuda_runtime.h>
#include <cuda_bf16.h>
#include <math.h>
#include <stdint.h>

#define BB 8
#define NTOK 2048
#define CLIPD 512
#define DD 256
#define BDIM 128
#define NCLS 10
#define ROWS (BB * NTOK)   // 16384

typedef __nv_bfloat16 bf16;

// ---------------- scratch (no cudaMalloc allowed) ----------------
__device__ float g_s   [BB * NTOK * NTOK];     // 134 MB scores fp32
__device__ bf16  g_ahi [BB * NTOK * NTOK];     // attn split
__device__ bf16  g_alo [BB * NTOK * NTOK];
__device__ bf16  g_lfhi[ROWS * CLIPD], g_lflo[ROWS * CLIPD];
__device__ float g_hf  [ROWS * DD];            // enc out fp32
__device__ bf16  g_hhi [ROWS * DD], g_hlo[ROWS * DD];
__device__ bf16  g_qhi [ROWS * DD], g_qlo[ROWS * DD];
__device__ bf16  g_khi [ROWS * DD], g_klo[ROWS * DD];
__device__ float g_v   [ROWS * DD];
__device__ bf16  g_vthi[ROWS * DD], g_vtlo[ROWS * DD];   // v transposed [b][d][m]
__device__ bf16  g_gghi[ROWS * DD], g_gglo[ROWS * DD];   // agg split
__device__ float g_o   [ROWS * BDIM];
__device__ bf16  g_enthi[DD * CLIPD], g_entlo[DD * CLIPD]; // enc_w^T
__device__ bf16  g_wqthi[DD * DD], g_wqtlo[DD * DD];
__device__ bf16  g_wkthi[DD * DD], g_wktlo[DD * DD];
__device__ bf16  g_wvthi[DD * DD], g_wvtlo[DD * DD];
__device__ bf16  g_bnthi[BDIM * DD], g_bntlo[BDIM * DD];

// ---------------- mma / ldmatrix helpers (sm_80+ HMMA path) ----------------
__device__ __forceinline__ uint32_t smem_u32(const void* p) {
    uint32_t a;
    asm("{ .reg .u64 t; cvta.to.shared.u64 t, %1; cvt.u32.u64 %0, t; }" : "=r"(a) : "l"(p));
    return a;
}

__device__ __forceinline__ void ldsm4(uint32_t* r, uint32_t addr) {
    asm volatile("ldmatrix.sync.aligned.m8n8.x4.shared.b16 {%0,%1,%2,%3}, [%4];"
                 : "=r"(r[0]), "=r"(r[1]), "=r"(r[2]), "=r"(r[3]) : "r"(addr));
}

__device__ __forceinline__ void mma_bf16(float* d, const uint32_t* a, const uint32_t* b) {
    asm volatile(
        "mma.sync.aligned.m16n8k16.row.col.f32.bf16.bf16.f32 "
        "{%0,%1,%2,%3}, {%4,%5,%6,%7}, {%8,%9}, {%0,%1,%2,%3};"
        : "+f"(d[0]), "+f"(d[1]), "+f"(d[2]), "+f"(d[3])
        : "r"(a[0]), "r"(a[1]), "r"(a[2]), "r"(a[3]), "r"(b[0]), "r"(b[1]));
}

// ---------------- HMMA GEMM with bf16x3 split ----------------
// C[M,N] = alpha * (A @ B^T) + bias ; A = Ahi+Alo [M,K], B = Bhi+Blo [N,K], K-major bf16.
// Computes Ahi*Bhi + Ahi*Blo + Alo*Bhi with fp32 register accumulation.
// Block tile 128x128, BK=32, 256 threads (8 warps 4Mx2N, warp tile 32x64).
// Requires M%128==0, N%128==0, K%32==0.
#define LDSR 40   // smem row stride in bf16 elements (32 + 8 pad = 80 bytes)

template <bool SPLIT>
__global__ void __launch_bounds__(256) gemm_mma(
    const bf16* __restrict__ Ahi, const bf16* __restrict__ Alo,
    const bf16* __restrict__ Bhi, const bf16* __restrict__ Blo,
    float* __restrict__ C, bf16* __restrict__ Chi, bf16* __restrict__ Clo,
    int N, int K,
    long sA, long sB, long sC,
    float alpha, const float* __restrict__ bias)
{
    __shared__ bf16 As[2][128 * LDSR];
    __shared__ bf16 Bs[2][128 * LDSR];

    const int bz = blockIdx.z;
    Ahi += bz * sA; Alo += bz * sA;
    Bhi += bz * sB; Blo += bz * sB;
    const long cOff = (long)bz * sC;

    const int tid = threadIdx.x;
    const int wid = tid >> 5, lid = tid & 31;
    const int wm = wid & 3, wn = wid >> 2;     // warp coords: 4 x 2
    const int row0 = blockIdx.y * 128;
    const int col0 = blockIdx.x * 128;

    const int KT = K / 32;
    const int T = 3 * KT;

    // global loader: each thread loads 32 contiguous bytes of one A row + one B row
    const int lr = tid >> 1;            // 0..127
    const int lk = (tid & 1) * 16;      // element offset 0 / 16

    auto gload = [&](int it, uint4& a0, uint4& a1, uint4& b0, uint4& b1) {
        const int pass = it / KT;
        const int k0 = (it - pass * KT) * 32;
        const bf16* Ap = (pass == 2) ? Alo : Ahi;
        const bf16* Bp = (pass == 1) ? Blo : Bhi;
        const bf16* ap = Ap + (long)(row0 + lr) * K + k0 + lk;
        const bf16* bp = Bp + (long)(col0 + lr) * K + k0 + lk;
        a0 = *(const uint4*)ap; a1 = *(const uint4*)(ap + 8);
        b0 = *(const uint4*)bp; b1 = *(const uint4*)(bp + 8);
    };
    auto sstore = [&](int buf, uint4 a0, uint4 a1, uint4 b0, uint4 b1) {
        bf16* as = &As[buf][lr * LDSR + lk];
        *(uint4*)as = a0; *(uint4*)(as + 8) = a1;
        bf16* bs = &Bs[buf][lr * LDSR + lk];
        *(uint4*)bs = b0; *(uint4*)(bs + 8) = b1;
    };

    float acc[2][8][4];
#pragma unroll
    for (int i = 0; i < 2; i++)
#pragma unroll
        for (int j = 0; j < 8; j++)
#pragma unroll
            for (int e = 0; e < 4; e++) acc[i][j][e] = 0.f;

    {
        uint4 a0, a1, b0, b1;
        gload(0, a0, a1, b0, b1);
        sstore(0, a0, a1, b0, b1);
    }
    __syncthreads();

    const uint32_t sAb = smem_u32(As);
    const uint32_t sBb = smem_u32(Bs);
    // per-lane ldmatrix source rows (constant across iterations)
    const int arow = wm * 32 + (lid & 15);
    const int akof = (lid >> 4) * 8;
    const int brow = wn * 64 + (lid & 7) + (lid >> 4) * 8;
    const int bkof = ((lid >> 3) & 1) * 8;

    for (int it = 0; it < T; ++it) {
        const int cur = it & 1;
        uint4 na0, na1, nb0, nb1;
        if (it + 1 < T) gload(it + 1, na0, na1, nb0, nb1);

        const uint32_t aBase = sAb + cur * (128 * LDSR * 2);
        const uint32_t bBase = sBb + cur * (128 * LDSR * 2);
#pragma unroll
        for (int ks = 0; ks < 2; ks++) {
            uint32_t af[2][4], bfr[4][4];
#pragma unroll
            for (int mt = 0; mt < 2; mt++)
                ldsm4(af[mt], aBase + (uint32_t)(((arow + mt * 16) * LDSR + ks * 16 + akof) * 2));
#pragma unroll
            for (int p = 0; p < 4; p++)
                ldsm4(bfr[p], bBase + (uint32_t)(((brow + p * 16) * LDSR + ks * 16 + bkof) * 2));
#pragma unroll
            for (int mt = 0; mt < 2; mt++)
#pragma unroll
                for (int nt = 0; nt < 8; nt++)
                    mma_bf16(acc[mt][nt], af[mt], &bfr[nt >> 1][(nt & 1) * 2]);
        }

        if (it + 1 < T) {
            __syncthreads();
            sstore(cur ^ 1, na0, na1, nb0, nb1);
            __syncthreads();
        }
    }

    // epilogue: D fragment -> global
    const int mrow = row0 + wm * 32;
    const int ncol = col0 + wn * 64;
    const int r4 = lid >> 2, c2 = (lid & 3) * 2;
#pragma unroll
    for (int mt = 0; mt < 2; mt++) {
#pragma unroll
        for (int half = 0; half < 2; half++) {
            const long r = mrow + mt * 16 + r4 + half * 8;
#pragma unroll
            for (int nt = 0; nt < 8; nt++) {
                const int c = ncol + nt * 8 + c2;
                float v0 = alpha * acc[mt][nt][half * 2 + 0] + (bias ? bias[c + 0] : 0.f);
                float v1 = alpha * acc[mt][nt][half * 2 + 1] + (bias ? bias[c + 1] : 0.f);
                if (SPLIT) {
                    bf16 h0 = __float2bfloat16(v0);
                    bf16 h1 = __float2bfloat16(v1);
                    __nv_bfloat162 hh; hh.x = h0; hh.y = h1;
                    __nv_bfloat162 ll;
                    ll.x = __float2bfloat16(v0 - __bfloat162float(h0));
                    ll.y = __float2bfloat16(v1 - __bfloat162float(h1));
                    *(__nv_bfloat162*)&Chi[cOff + r * N + c] = hh;
                    *(__nv_bfloat162*)&Clo[cOff + r * N + c] = ll;
                } else {
                    float2 o; o.x = v0; o.y = v1;
                    *(float2*)&C[cOff + r * N + c] = o;
                }
            }
        }
    }
}

// ---------------- elementwise fp32 -> bf16 hi/lo split ----------------
__global__ void split_convert(const float* __restrict__ X, bf16* __restrict__ hi,
                              bf16* __restrict__ lo, int n4)
{
    int i = blockIdx.x * blockDim.x + threadIdx.x;
    if (i >= n4) return;
    float4 v = ((const float4*)X)[i];
    bf16 h0 = __float2bfloat16(v.x), h1 = __float2bfloat16(v.y);
    bf16 h2 = __float2bfloat16(v.z), h3 = __float2bfloat16(v.w);
    __nv_bfloat162 ha; ha.x = h0; ha.y = h1;
    __nv_bfloat162 hb; hb.x = h2; hb.y = h3;
    __nv_bfloat162 la; la.x = __float2bfloat16(v.x - __bfloat162float(h0));
                       la.y = __float2bfloat16(v.y - __bfloat162float(h1));
    __nv_bfloat162 lb; lb.x = __float2bfloat16(v.z - __bfloat162float(h2));
                       lb.y = __float2bfloat16(v.w - __bfloat162float(h3));
    ((__nv_bfloat162*)hi)[i * 2 + 0] = ha;
    ((__nv_bfloat162*)hi)[i * 2 + 1] = hb;
    ((__nv_bfloat162*)lo)[i * 2 + 0] = la;
    ((__nv_bfloat162*)lo)[i * 2 + 1] = lb;
}

// ---------------- batched transpose + split: X[b][R][Cc] -> T[b][Cc][R] ----------------
__global__ void transpose_split(const float* __restrict__ X, bf16* __restrict__ Thi,
                                bf16* __restrict__ Tlo, int R, int Cc)
{
    __shared__ float t[32][33];
    const long boff = (long)blockIdx.z * R * Cc;
    X += boff; Thi += boff; Tlo += boff;
    const int c0 = blockIdx.x * 32, r0 = blockIdx.y * 32;
    for (int i = threadIdx.y; i < 32; i += 8)
        t[i][threadIdx.x] = X[(long)(r0 + i) * Cc + c0 + threadIdx.x];
    __syncthreads();
    for (int i = threadIdx.y; i < 32; i += 8) {
        float v = t[threadIdx.x][i];
        bf16 h = __float2bfloat16(v);
        bf16 l = __float2bfloat16(v - __bfloat162float(h));
        long o = (long)(c0 + i) * R + r0 + threadIdx.x;
        Thi[o] = h; Tlo[o] = l;
    }
}

// ---------------- block reductions ----------------
__device__ __forceinline__ float blk_sum(float v) {
    __shared__ float sh[33];
    int lane = threadIdx.x & 31, w = threadIdx.x >> 5;
#pragma unroll
    for (int o = 16; o; o >>= 1) v += __shfl_xor_sync(0xffffffffu, v, o);
    __syncthreads();
    if (lane == 0) sh[w] = v;
    __syncthreads();
    if (threadIdx.x == 0) {
        float s = 0.f; int nw = (blockDim.x + 31) >> 5;
        for (int i = 0; i < nw; i++) s += sh[i];
        sh[32] = s;
    }
    __syncthreads();
    return sh[32];
}
__device__ __forceinline__ float blk_max(float v) {
    __shared__ float sh[33];
    int lane = threadIdx.x & 31, w = threadIdx.x >> 5;
#pragma unroll
    for (int o = 16; o; o >>= 1) v = fmaxf(v, __shfl_xor_sync(0xffffffffu, v, o));
    __syncthreads();
    if (lane == 0) sh[w] = v;
    __syncthreads();
    if (threadIdx.x == 0) {
        float s = -INFINITY; int nw = (blockDim.x + 31) >> 5;
        for (int i = 0; i < nw; i++) s = fmaxf(s, sh[i]);
        sh[32] = s;
    }
    __syncthreads();
    return sh[32];
}

// ---------------- LayerNorm + ReLU ----------------
// if hi != null: write bf16 split outputs only; else write X in place (fp32)
__global__ void ln_relu_kernel(float* __restrict__ X, const float* __restrict__ g,
                               const float* __restrict__ beta, int D,
                               bf16* __restrict__ hi, bf16* __restrict__ lo)
{
    const long row = blockIdx.x;
    const int t = threadIdx.x;
    float v = X[row * D + t];
    float mu = blk_sum(v) * (1.f / D);
    float d = v - mu;
    float var = blk_sum(d * d) * (1.f / D);
    float r = d * rsqrtf(var + 1e-5f) * g[t] + beta[t];
    r = fmaxf(r, 0.f);
    if (hi) {
        bf16 h = __float2bfloat16(r);
        hi[row * D + t] = h;
        lo[row * D + t] = __float2bfloat16(r - __bfloat162float(h));
    } else {
        X[row * D + t] = r;
    }
}

// ---------------- softmax * spatial_adj * notmask -> bf16 hi/lo splits ----------------
__global__ void __launch_bounds__(256) softmax_adj_kernel(
    const float* __restrict__ S, const float* __restrict__ coords,
    const int* __restrict__ mask, const float* __restrict__ gamma,
    bf16* __restrict__ Ahi, bf16* __restrict__ Alo)
{
    const int b = blockIdx.y;
    const int n = blockIdx.x;
    const long roff = ((long)b * NTOK + n) * NTOK;
    const float* row = S + roff;
    const int t = threadIdx.x;

    float s[8];
    float mx = -INFINITY;
#pragma unroll
    for (int j = 0; j < 8; j++) {
        s[j] = row[t + j * 256];
        mx = fmaxf(mx, s[j]);
    }
    mx = blk_max(mx);

    float lsum = 0.f;
#pragma unroll
    for (int j = 0; j < 8; j++) {
        s[j] = __expf(s[j] - mx);
        lsum += s[j];
    }
    float inv = 1.f / blk_sum(lsum);

    const float ga = fabsf(gamma[0]);
    const float xn = coords[((long)b * NTOK + n) * 2 + 0];
    const float yn = coords[((long)b * NTOK + n) * 2 + 1];
    const float sqn = xn * xn + yn * yn;

#pragma unroll
    for (int j = 0; j < 8; j++) {
        const int m = t + j * 256;
        const float xm = coords[((long)b * NTOK + m) * 2 + 0];
        const float ym = coords[((long)b * NTOK + m) * 2 + 1];
        float d2 = sqn + xm * xm + ym * ym - 2.f * (xn * xm + yn * ym);
        float dist = sqrtf(fmaxf(d2, 0.f));
        float adj = __expf(-dist * ga);
        float w = mask[b * NTOK + m] ? 0.f : s[j] * inv * adj;
        bf16 h = __float2bfloat16(w);
        Ahi[roff + m] = h;
        Alo[roff + m] = __float2bfloat16(w - __bfloat162float(h));
    }
}

// ---------------- masked mean pool ----------------
__global__ void pool_kernel(const float* __restrict__ out, const int* __restrict__ mask,
                            float* __restrict__ pooled)
{
    const int b = blockIdx.x;
    const int t = threadIdx.x;  // 128
    __shared__ float sc[128];
    float c = 0.f;
    for (int n = t; n < NTOK; n += 128) c += mask[b * NTOK + n] ? 0.f : 1.f;
    sc[t] = c;
    __syncthreads();
    for (int o = 64; o; o >>= 1) { if (t < o) sc[t] += sc[t + o]; __syncthreads(); }
    const float cnt = fmaxf(sc[0], 1e-9f);

    float s = 0.f;
    const float* base = out + (long)b * NTOK * BDIM + t;
    const int* mb = mask + b * NTOK;
    for (int n = 0; n < NTOK; n++) {
        float val = base[(long)n * BDIM];
        s += mb[n] ? 0.f : val;
    }
    pooled[b * BDIM + t] = s / cnt;
}

// ---------------- head MLP ----------------
__global__ void head_kernel(const float* __restrict__ pooled,
                            const float* __restrict__ c1w, const float* __restrict__ c1b,
                            const float* __restrict__ c2w, const float* __restrict__ c2b,
                            float* __restrict__ logits)
{
    const int b = blockIdx.x;
    const int t = threadIdx.x;  // 64
    __shared__ float sp[BDIM];
    __shared__ float hid[64];
    for (int i = t; i < BDIM; i += 64) sp[i] = pooled[b * BDIM + i];
    __syncthreads();
    float s = c1b[t];
    for (int i = 0; i < BDIM; i++) s += sp[i] * c1w[i * 64 + t];
    hid[t] = fmaxf(s, 0.f);
    __syncthreads();
    if (t < NCLS) {
        float l = c2b[t];
        for (int j = 0; j < 64; j++) l += hid[j] * c2w[j * NCLS + t];
        logits[b * NCLS + t] = l;
    }
}

// ---------------- launch ----------------
extern "C" void kernel_launch(void* const* d_in, const int* in_sizes, int n_in,
                              void* d_out, int out_size)
{
    const float* local_feat = (const float*)d_in[0];
    const float* coords     = (const float*)d_in[1];
    const int*   mask       = (const int*)d_in[2];
    const float* enc_w      = (const float*)d_in[3];
    const float* enc_b      = (const float*)d_in[4];
    const float* enc_g      = (const float*)d_in[5];
    const float* enc_beta   = (const float*)d_in[6];
    const float* gamma      = (const float*)d_in[7];
    const float* wq         = (const float*)d_in[8];
    const float* bq         = (const float*)d_in[9];
    const float* wk         = (const float*)d_in[10];
    const float* bk         = (const float*)d_in[11];
    const float* wv         = (const float*)d_in[12];
    const float* bv         = (const float*)d_in[13];
    const float* bn_w       = (const float*)d_in[14];
    const float* bn_b       = (const float*)d_in[15];
    const float* bn_g       = (const float*)d_in[16];
    const float* bn_beta    = (const float*)d_in[17];
    const float* c1_w       = (const float*)d_in[18];
    const float* c1_b       = (const float*)d_in[19];
    const float* c2_w       = (const float*)d_in[20];
    const float* c2_b       = (const float*)d_in[21];

    float *s, *hf, *v, *o;
    bf16 *ahi, *alo, *lfhi, *lflo, *hhi, *hlo, *qhi, *qlo, *khi, *klo;
    bf16 *vthi, *vtlo, *gghi, *gglo;
    bf16 *enthi, *entlo, *wqthi, *wqtlo, *wkthi, *wktlo, *wvthi, *wvtlo, *bnthi, *bntlo;
    cudaGetSymbolAddress((void**)&s,     g_s);
    cudaGetSymbolAddress((void**)&ahi,   g_ahi);
    cudaGetSymbolAddress((void**)&alo,   g_alo);
    cudaGetSymbolAddress((void**)&lfhi,  g_lfhi);
    cudaGetSymbolAddress((void**)&lflo,  g_lflo);
    cudaGetSymbolAddress((void**)&hf,    g_hf);
    cudaGetSymbolAddress((void**)&hhi,   g_hhi);
    cudaGetSymbolAddress((void**)&hlo,   g_hlo);
    cudaGetSymbolAddress((void**)&qhi,   g_qhi);
    cudaGetSymbolAddress((void**)&qlo,   g_qlo);
    cudaGetSymbolAddress((void**)&khi,   g_khi);
    cudaGetSymbolAddress((void**)&klo,   g_klo);
    cudaGetSymbolAddress((void**)&v,     g_v);
    cudaGetSymbolAddress((void**)&vthi,  g_vthi);
    cudaGetSymbolAddress((void**)&vtlo,  g_vtlo);
    cudaGetSymbolAddress((void**)&gghi,  g_gghi);
    cudaGetSymbolAddress((void**)&gglo,  g_gglo);
    cudaGetSymbolAddress((void**)&o,     g_o);
    cudaGetSymbolAddress((void**)&enthi, g_enthi);
    cudaGetSymbolAddress((void**)&entlo, g_entlo);
    cudaGetSymbolAddress((void**)&wqthi, g_wqthi);
    cudaGetSymbolAddress((void**)&wqtlo, g_wqtlo);
    cudaGetSymbolAddress((void**)&wkthi, g_wkthi);
    cudaGetSymbolAddress((void**)&wktlo, g_wktlo);
    cudaGetSymbolAddress((void**)&wvthi, g_wvthi);
    cudaGetSymbolAddress((void**)&wvtlo, g_wvtlo);
    cudaGetSymbolAddress((void**)&bnthi, g_bnthi);
    cudaGetSymbolAddress((void**)&bntlo, g_bntlo);

    // 0) input conversions
    split_convert<<<(ROWS * CLIPD / 4 + 255) / 256, 256>>>(local_feat, lfhi, lflo, ROWS * CLIPD / 4);
    transpose_split<<<dim3(DD / 32, CLIPD / 32, 1), dim3(32, 8)>>>(enc_w, enthi, entlo, CLIPD, DD);
    transpose_split<<<dim3(DD / 32, DD / 32, 1),    dim3(32, 8)>>>(wq, wqthi, wqtlo, DD, DD);
    transpose_split<<<dim3(DD / 32, DD / 32, 1),    dim3(32, 8)>>>(wk, wkthi, wktlo, DD, DD);
    transpose_split<<<dim3(DD / 32, DD / 32, 1),    dim3(32, 8)>>>(wv, wvthi, wvtlo, DD, DD);
    transpose_split<<<dim3(BDIM / 32, DD / 32, 1),  dim3(32, 8)>>>(bn_w, bnthi, bntlo, DD, BDIM);

    // 1) enc GEMM: hf = lf @ enc_w + enc_b   (M=16384, N=256, K=512)
    gemm_mma<false><<<dim3(DD / 128, ROWS / 128, 1), 256>>>(
        lfhi, lflo, enthi, entlo, hf, nullptr, nullptr, DD, CLIPD, 0, 0, 0, 1.f, enc_b);
    // 2) LN + relu -> h splits
    ln_relu_kernel<<<ROWS, DD>>>(hf, enc_g, enc_beta, DD, hhi, hlo);

    // 3) q, k (split out), v (fp32 out, needs transpose)
    gemm_mma<true><<<dim3(DD / 128, ROWS / 128, 1), 256>>>(
        hhi, hlo, wqthi, wqtlo, nullptr, qhi, qlo, DD, DD, 0, 0, 0, 1.f, bq);
    gemm_mma<true><<<dim3(DD / 128, ROWS / 128, 1), 256>>>(
        hhi, hlo, wkthi, wktlo, nullptr, khi, klo, DD, DD, 0, 0, 0, 1.f, bk);
    gemm_mma<false><<<dim3(DD / 128, ROWS / 128, 1), 256>>>(
        hhi, hlo, wvthi, wvtlo, v, nullptr, nullptr, DD, DD, 0, 0, 0, 1.f, bv);
    // v -> vT splits per batch:  [b][m][d] -> [b][d][m]
    transpose_split<<<dim3(DD / 32, NTOK / 32, BB), dim3(32, 8)>>>(v, vthi, vtlo, NTOK, DD);

    // 4) scores = q @ k^T / 16, batched  (M=2048, N=2048, K=256)
    gemm_mma<false><<<dim3(NTOK / 128, NTOK / 128, BB), 256>>>(
        qhi, qlo, khi, klo, s, nullptr, nullptr, NTOK, DD,
        (long)NTOK * DD, (long)NTOK * DD, (long)NTOK * NTOK, 0.0625f, nullptr);

    // 5) softmax * adj * notmask -> attn splits
    softmax_adj_kernel<<<dim3(NTOK, BB), 256>>>(s, coords, mask, gamma, ahi, alo);

    // 6) agg = attn @ v (split out), batched  (M=2048, N=256, K=2048)
    gemm_mma<true><<<dim3(DD / 128, NTOK / 128, BB), 256>>>(
        ahi, alo, vthi, vtlo, nullptr, gghi, gglo, DD, NTOK,
        (long)NTOK * NTOK, (long)DD * NTOK, (long)NTOK * DD, 1.f, nullptr);

    // 7) bn GEMM: o = agg @ bn_w + bn_b  (M=16384, N=128, K=256)
    gemm_mma<false><<<dim3(BDIM / 128, ROWS / 128, 1), 256>>>(
        gghi, gglo, bnthi, bntlo, o, nullptr, nullptr, BDIM, DD, 0, 0, 0, 1.f, bn_b);
    // 8) LN + relu fp32 in place
    ln_relu_kernel<<<ROWS, BDIM>>>(o, bn_g, bn_beta, BDIM, nullptr, nullptr);

    // 9) masked mean pool -> d_out[80 : 80+1024]
    float* out_f = (float*)d_out;
    pool_kernel<<<BB, BDIM>>>(o, mask, out_f + BB * NCLS);

    // 10) MLP head -> d_out[0 : 80]
    head_kernel<<<BB, 64>>>(out_f + BB * NCLS, c1_w, c1_b, c2_w, c2_b, out_f);
}

// round 5
// speedup vs baseline: 1.7378x; 1.0576x over previous
#include <cuda_runtime.h>
#include <cuda_bf16.h>
#include <math.h>
#include <stdint.h>

#define BB 8
#define NTOK 2048
#define CLIPD 512
#define DD 256
#define BDIM 128
#define NCLS 10
#define ROWS (BB * NTOK)   // 16384

typedef __nv_bfloat16 bf16;

// ---------------- scratch (no cudaMalloc allowed) ----------------
__device__ float g_s   [BB * NTOK * NTOK];     // 134 MB scores fp32
__device__ bf16  g_ahi [BB * NTOK * NTOK];     // attn split
__device__ bf16  g_alo [BB * NTOK * NTOK];
__device__ bf16  g_lfhi[ROWS * CLIPD], g_lflo[ROWS * CLIPD];
__device__ float g_hf  [ROWS * DD];            // enc out fp32
__device__ bf16  g_hhi [ROWS * DD], g_hlo[ROWS * DD];
__device__ bf16  g_qhi [ROWS * DD], g_qlo[ROWS * DD];
__device__ bf16  g_khi [ROWS * DD], g_klo[ROWS * DD];
__device__ float g_v   [ROWS * DD];
__device__ bf16  g_vthi[ROWS * DD], g_vtlo[ROWS * DD];   // v transposed [b][d][m]
__device__ bf16  g_gghi[ROWS * DD], g_gglo[ROWS * DD];   // agg split
__device__ float g_o   [ROWS * BDIM];
__device__ bf16  g_enthi[DD * CLIPD], g_entlo[DD * CLIPD]; // enc_w^T
__device__ bf16  g_wqthi[DD * DD], g_wqtlo[DD * DD];
__device__ bf16  g_wkthi[DD * DD], g_wktlo[DD * DD];
__device__ bf16  g_wvthi[DD * DD], g_wvtlo[DD * DD];
__device__ bf16  g_bnthi[BDIM * DD], g_bntlo[BDIM * DD];

// ---------------- mma / ldmatrix / cp.async helpers ----------------
__device__ __forceinline__ uint32_t smem_u32(const void* p) {
    uint32_t a;
    asm("{ .reg .u64 t; cvta.to.shared.u64 t, %1; cvt.u32.u64 %0, t; }" : "=r"(a) : "l"(p));
    return a;
}

__device__ __forceinline__ void ldsm4(uint32_t* r, uint32_t addr) {
    asm volatile("ldmatrix.sync.aligned.m8n8.x4.shared.b16 {%0,%1,%2,%3}, [%4];"
                 : "=r"(r[0]), "=r"(r[1]), "=r"(r[2]), "=r"(r[3]) : "r"(addr));
}

__device__ __forceinline__ void mma_bf16(float* d, const uint32_t* a, const uint32_t* b) {
    asm volatile(
        "mma.sync.aligned.m16n8k16.row.col.f32.bf16.bf16.f32 "
        "{%0,%1,%2,%3}, {%4,%5,%6,%7}, {%8,%9}, {%0,%1,%2,%3};"
        : "+f"(d[0]), "+f"(d[1]), "+f"(d[2]), "+f"(d[3])
        : "r"(a[0]), "r"(a[1]), "r"(a[2]), "r"(a[3]), "r"(b[0]), "r"(b[1]));
}

__device__ __forceinline__ void cp16(uint32_t dst, const void* src) {
    asm volatile("cp.async.cg.shared.global [%0], [%1], 16;" :: "r"(dst), "l"(src));
}
#define CP_COMMIT() asm volatile("cp.async.commit_group;" ::: "memory")
#define CP_WAIT1()  asm volatile("cp.async.wait_group 1;" ::: "memory")

// ---------------- HMMA GEMM with bf16x3 split, 3-stage cp.async pipeline ----------------
// C[M,N] = alpha * (A @ B^T) + bias ; A = Ahi+Alo [M,K], B = Bhi+Blo [N,K], K-major bf16.
// Computes Ahi*Bhi + Ahi*Blo + Alo*Bhi with fp32 register accumulation.
// Block tile 128x128, BK=32, 256 threads (8 warps 4Mx2N, warp tile 32x64).
// Requires M%128==0, N%128==0, K%32==0.
#define LDSR 40                       // smem row stride in bf16 (32 + 8 pad = 80 bytes)
#define STAGE_B (128 * LDSR * 2)      // 10240 bytes per stage per matrix
#define GEMM_SMEM (6 * STAGE_B)       // 3 stages x (A+B) = 61440

template <bool SPLIT>
__global__ void __launch_bounds__(256) gemm_mma(
    const bf16* __restrict__ Ahi, const bf16* __restrict__ Alo,
    const bf16* __restrict__ Bhi, const bf16* __restrict__ Blo,
    float* __restrict__ C, bf16* __restrict__ Chi, bf16* __restrict__ Clo,
    int N, int K,
    long sA, long sB, long sC,
    float alpha, const float* __restrict__ bias)
{
    extern __shared__ char smem[];

    const int bz = blockIdx.z;
    Ahi += bz * sA; Alo += bz * sA;
    Bhi += bz * sB; Blo += bz * sB;
    const long cOff = (long)bz * sC;

    const int tid = threadIdx.x;
    const int wid = tid >> 5, lid = tid & 31;
    const int wm = wid & 3, wn = wid >> 2;     // warp coords: 4 x 2
    const int row0 = blockIdx.y * 128;
    const int col0 = blockIdx.x * 128;

    const int KT = K / 32;
    const int T = 3 * KT;

    // loader lanes: each thread owns 16 elements (32 bytes) of one A row and one B row
    const int lr = tid >> 1;            // 0..127
    const int lk = (tid & 1) * 16;      // element offset 0 / 16

    const uint32_t sBase = smem_u32(smem);
    const uint32_t aS = sBase;                    // A stages at [0, 3*STAGE_B)
    const uint32_t bS = sBase + 3 * STAGE_B;      // B stages
    const uint32_t dstOff = (uint32_t)(lr * LDSR + lk) * 2;

    auto issue = [&](int it, int buf) {
        const int pass = it / KT;
        const int k0 = (it - pass * KT) * 32;
        const bf16* Ap = (pass == 2) ? Alo : Ahi;
        const bf16* Bp = (pass == 1) ? Blo : Bhi;
        const bf16* ap = Ap + (long)(row0 + lr) * K + k0 + lk;
        const bf16* bp = Bp + (long)(col0 + lr) * K + k0 + lk;
        const uint32_t ad = aS + buf * STAGE_B + dstOff;
        const uint32_t bd = bS + buf * STAGE_B + dstOff;
        cp16(ad, ap); cp16(ad + 16, ap + 8);
        cp16(bd, bp); cp16(bd + 16, bp + 8);
    };

    float acc[2][8][4];
#pragma unroll
    for (int i = 0; i < 2; i++)
#pragma unroll
        for (int j = 0; j < 8; j++)
#pragma unroll
            for (int e = 0; e < 4; e++) acc[i][j][e] = 0.f;

    // prologue: 2 stages in flight
    issue(0, 0); CP_COMMIT();
    issue(1, 1); CP_COMMIT();

    // per-lane ldmatrix source rows (constant across iterations)
    const int arow = wm * 32 + (lid & 15);
    const int akof = (lid >> 4) * 8;
    const int brow = wn * 64 + (lid & 7) + (lid >> 4) * 8;
    const int bkof = ((lid >> 3) & 1) * 8;

    int buf = 0;
    for (int it = 0; it < T; ++it) {
        CP_WAIT1();              // stage `it` landed
        __syncthreads();

        // prefetch stage it+2 into the buffer freed at iteration it-1
        if (it + 2 < T) issue(it + 2, (buf + 2 >= 3) ? buf - 1 : buf + 2);
        CP_COMMIT();

        const uint32_t aBase = aS + buf * STAGE_B;
        const uint32_t bBase = bS + buf * STAGE_B;
#pragma unroll
        for (int ks = 0; ks < 2; ks++) {
            uint32_t af[2][4], bfr[4][4];
#pragma unroll
            for (int mt = 0; mt < 2; mt++)
                ldsm4(af[mt], aBase + (uint32_t)(((arow + mt * 16) * LDSR + ks * 16 + akof) * 2));
#pragma unroll
            for (int p = 0; p < 4; p++)
                ldsm4(bfr[p], bBase + (uint32_t)(((brow + p * 16) * LDSR + ks * 16 + bkof) * 2));
#pragma unroll
            for (int mt = 0; mt < 2; mt++)
#pragma unroll
                for (int nt = 0; nt < 8; nt++)
                    mma_bf16(acc[mt][nt], af[mt], &bfr[nt >> 1][(nt & 1) * 2]);
        }
        buf = (buf + 1 >= 3) ? 0 : buf + 1;
    }

    // epilogue: D fragment -> global
    const int mrow = row0 + wm * 32;
    const int ncol = col0 + wn * 64;
    const int r4 = lid >> 2, c2 = (lid & 3) * 2;
#pragma unroll
    for (int mt = 0; mt < 2; mt++) {
#pragma unroll
        for (int half = 0; half < 2; half++) {
            const long r = mrow + mt * 16 + r4 + half * 8;
#pragma unroll
            for (int nt = 0; nt < 8; nt++) {
                const int c = ncol + nt * 8 + c2;
                float v0 = alpha * acc[mt][nt][half * 2 + 0] + (bias ? bias[c + 0] : 0.f);
                float v1 = alpha * acc[mt][nt][half * 2 + 1] + (bias ? bias[c + 1] : 0.f);
                if (SPLIT) {
                    bf16 h0 = __float2bfloat16(v0);
                    bf16 h1 = __float2bfloat16(v1);
                    __nv_bfloat162 hh; hh.x = h0; hh.y = h1;
                    __nv_bfloat162 ll;
                    ll.x = __float2bfloat16(v0 - __bfloat162float(h0));
                    ll.y = __float2bfloat16(v1 - __bfloat162float(h1));
                    *(__nv_bfloat162*)&Chi[cOff + r * N + c] = hh;
                    *(__nv_bfloat162*)&Clo[cOff + r * N + c] = ll;
                } else {
                    float2 o; o.x = v0; o.y = v1;
                    *(float2*)&C[cOff + r * N + c] = o;
                }
            }
        }
    }
}

// ---------------- elementwise fp32 -> bf16 hi/lo split ----------------
__global__ void split_convert(const float* __restrict__ X, bf16* __restrict__ hi,
                              bf16* __restrict__ lo, int n4)
{
    int i = blockIdx.x * blockDim.x + threadIdx.x;
    if (i >= n4) return;
    float4 v = ((const float4*)X)[i];
    bf16 h0 = __float2bfloat16(v.x), h1 = __float2bfloat16(v.y);
    bf16 h2 = __float2bfloat16(v.z), h3 = __float2bfloat16(v.w);
    __nv_bfloat162 ha; ha.x = h0; ha.y = h1;
    __nv_bfloat162 hb; hb.x = h2; hb.y = h3;
    __nv_bfloat162 la; la.x = __float2bfloat16(v.x - __bfloat162float(h0));
                       la.y = __float2bfloat16(v.y - __bfloat162float(h1));
    __nv_bfloat162 lb; lb.x = __float2bfloat16(v.z - __bfloat162float(h2));
                       lb.y = __float2bfloat16(v.w - __bfloat162float(h3));
    ((__nv_bfloat162*)hi)[i * 2 + 0] = ha;
    ((__nv_bfloat162*)hi)[i * 2 + 1] = hb;
    ((__nv_bfloat162*)lo)[i * 2 + 0] = la;
    ((__nv_bfloat162*)lo)[i * 2 + 1] = lb;
}

// ---------------- batched transpose + split: X[b][R][Cc] -> T[b][Cc][R] ----------------
__global__ void transpose_split(const float* __restrict__ X, bf16* __restrict__ Thi,
                                bf16* __restrict__ Tlo, int R, int Cc)
{
    __shared__ float t[32][33];
    const long boff = (long)blockIdx.z * R * Cc;
    X += boff; Thi += boff; Tlo += boff;
    const int c0 = blockIdx.x * 32, r0 = blockIdx.y * 32;
    for (int i = threadIdx.y; i < 32; i += 8)
        t[i][threadIdx.x] = X[(long)(r0 + i) * Cc + c0 + threadIdx.x];
    __syncthreads();
    for (int i = threadIdx.y; i < 32; i += 8) {
        float v = t[threadIdx.x][i];
        bf16 h = __float2bfloat16(v);
        bf16 l = __float2bfloat16(v - __bfloat162float(h));
        long o = (long)(c0 + i) * R + r0 + threadIdx.x;
        Thi[o] = h; Tlo[o] = l;
    }
}

// ---------------- block reductions ----------------
__device__ __forceinline__ float blk_sum(float v) {
    __shared__ float sh[33];
    int lane = threadIdx.x & 31, w = threadIdx.x >> 5;
#pragma unroll
    for (int o = 16; o; o >>= 1) v += __shfl_xor_sync(0xffffffffu, v, o);
    __syncthreads();
    if (lane == 0) sh[w] = v;
    __syncthreads();
    if (threadIdx.x == 0) {
        float s = 0.f; int nw = (blockDim.x + 31) >> 5;
        for (int i = 0; i < nw; i++) s += sh[i];
        sh[32] = s;
    }
    __syncthreads();
    return sh[32];
}
__device__ __forceinline__ float blk_max(float v) {
    __shared__ float sh[33];
    int lane = threadIdx.x & 31, w = threadIdx.x >> 5;
#pragma unroll
    for (int o = 16; o; o >>= 1) v = fmaxf(v, __shfl_xor_sync(0xffffffffu, v, o));
    __syncthreads();
    if (lane == 0) sh[w] = v;
    __syncthreads();
    if (threadIdx.x == 0) {
        float s = -INFINITY; int nw = (blockDim.x + 31) >> 5;
        for (int i = 0; i < nw; i++) s = fmaxf(s, sh[i]);
        sh[32] = s;
    }
    __syncthreads();
    return sh[32];
}

// ---------------- LayerNorm + ReLU ----------------
__global__ void ln_relu_kernel(float* __restrict__ X, const float* __restrict__ g,
                               const float* __restrict__ beta, int D,
                               bf16* __restrict__ hi, bf16* __restrict__ lo)
{
    const long row = blockIdx.x;
    const int t = threadIdx.x;
    float v = X[row * D + t];
    float mu = blk_sum(v) * (1.f / D);
    float d = v - mu;
    float var = blk_sum(d * d) * (1.f / D);
    float r = d * rsqrtf(var + 1e-5f) * g[t] + beta[t];
    r = fmaxf(r, 0.f);
    if (hi) {
        bf16 h = __float2bfloat16(r);
        hi[row * D + t] = h;
        lo[row * D + t] = __float2bfloat16(r - __bfloat162float(h));
    } else {
        X[row * D + t] = r;
    }
}

// ---------------- softmax * spatial_adj * notmask -> bf16 hi/lo splits ----------------
__global__ void __launch_bounds__(256) softmax_adj_kernel(
    const float* __restrict__ S, const float* __restrict__ coords,
    const int* __restrict__ mask, const float* __restrict__ gamma,
    bf16* __restrict__ Ahi, bf16* __restrict__ Alo)
{
    const int b = blockIdx.y;
    const int n = blockIdx.x;
    const long roff = ((long)b * NTOK + n) * NTOK;
    const float* row = S + roff;
    const int t = threadIdx.x;

    float s[8];
    float mx = -INFINITY;
#pragma unroll
    for (int j = 0; j < 8; j++) {
        s[j] = row[t + j * 256];
        mx = fmaxf(mx, s[j]);
    }
    mx = blk_max(mx);

    float lsum = 0.f;
#pragma unroll
    for (int j = 0; j < 8; j++) {
        s[j] = __expf(s[j] - mx);
        lsum += s[j];
    }
    float inv = 1.f / blk_sum(lsum);

    const float ga = fabsf(gamma[0]);
    const float xn = coords[((long)b * NTOK + n) * 2 + 0];
    const float yn = coords[((long)b * NTOK + n) * 2 + 1];
    const float sqn = xn * xn + yn * yn;

#pragma unroll
    for (int j = 0; j < 8; j++) {
        const int m = t + j * 256;
        const float xm = coords[((long)b * NTOK + m) * 2 + 0];
        const float ym = coords[((long)b * NTOK + m) * 2 + 1];
        float d2 = sqn + xm * xm + ym * ym - 2.f * (xn * xm + yn * ym);
        float dist = sqrtf(fmaxf(d2, 0.f));
        float adj = __expf(-dist * ga);
        float w = mask[b * NTOK + m] ? 0.f : s[j] * inv * adj;
        bf16 h = __float2bfloat16(w);
        Ahi[roff + m] = h;
        Alo[roff + m] = __float2bfloat16(w - __bfloat162float(h));
    }
}

// ---------------- masked mean pool ----------------
__global__ void pool_kernel(const float* __restrict__ out, const int* __restrict__ mask,
                            float* __restrict__ pooled)
{
    const int b = blockIdx.x;
    const int t = threadIdx.x;  // 128
    __shared__ float sc[128];
    float c = 0.f;
    for (int n = t; n < NTOK; n += 128) c += mask[b * NTOK + n] ? 0.f : 1.f;
    sc[t] = c;
    __syncthreads();
    for (int o = 64; o; o >>= 1) { if (t < o) sc[t] += sc[t + o]; __syncthreads(); }
    const float cnt = fmaxf(sc[0], 1e-9f);

    float s = 0.f;
    const float* base = out + (long)b * NTOK * BDIM + t;
    const int* mb = mask + b * NTOK;
    for (int n = 0; n < NTOK; n++) {
        float val = base[(long)n * BDIM];
        s += mb[n] ? 0.f : val;
    }
    pooled[b * BDIM + t] = s / cnt;
}

// ---------------- head MLP ----------------
__global__ void head_kernel(const float* __restrict__ pooled,
                            const float* __restrict__ c1w, const float* __restrict__ c1b,
                            const float* __restrict__ c2w, const float* __restrict__ c2b,
                            float* __restrict__ logits)
{
    const int b = blockIdx.x;
    const int t = threadIdx.x;  // 64
    __shared__ float sp[BDIM];
    __shared__ float hid[64];
    for (int i = t; i < BDIM; i += 64) sp[i] = pooled[b * BDIM + i];
    __syncthreads();
    float s = c1b[t];
    for (int i = 0; i < BDIM; i++) s += sp[i] * c1w[i * 64 + t];
    hid[t] = fmaxf(s, 0.f);
    __syncthreads();
    if (t < NCLS) {
        float l = c2b[t];
        for (int j = 0; j < 64; j++) l += hid[j] * c2w[j * NCLS + t];
        logits[b * NCLS + t] = l;
    }
}

// ---------------- launch ----------------
extern "C" void kernel_launch(void* const* d_in, const int* in_sizes, int n_in,
                              void* d_out, int out_size)
{
    const float* local_feat = (const float*)d_in[0];
    const float* coords     = (const float*)d_in[1];
    const int*   mask       = (const int*)d_in[2];
    const float* enc_w      = (const float*)d_in[3];
    const float* enc_b      = (const float*)d_in[4];
    const float* enc_g      = (const float*)d_in[5];
    const float* enc_beta   = (const float*)d_in[6];
    const float* gamma      = (const float*)d_in[7];
    const float* wq         = (const float*)d_in[8];
    const float* bq         = (const float*)d_in[9];
    const float* wk         = (const float*)d_in[10];
    const float* bk         = (const float*)d_in[11];
    const float* wv         = (const float*)d_in[12];
    const float* bv         = (const float*)d_in[13];
    const float* bn_w       = (const float*)d_in[14];
    const float* bn_b       = (const float*)d_in[15];
    const float* bn_g       = (const float*)d_in[16];
    const float* bn_beta    = (const float*)d_in[17];
    const float* c1_w       = (const float*)d_in[18];
    const float* c1_b       = (const float*)d_in[19];
    const float* c2_w       = (const float*)d_in[20];
    const float* c2_b       = (const float*)d_in[21];

    float *s, *hf, *v, *o;
    bf16 *ahi, *alo, *lfhi, *lflo, *hhi, *hlo, *qhi, *qlo, *khi, *klo;
    bf16 *vthi, *vtlo, *gghi, *gglo;
    bf16 *enthi, *entlo, *wqthi, *wqtlo, *wkthi, *wktlo, *wvthi, *wvtlo, *bnthi, *bntlo;
    cudaGetSymbolAddress((void**)&s,     g_s);
    cudaGetSymbolAddress((void**)&ahi,   g_ahi);
    cudaGetSymbolAddress((void**)&alo,   g_alo);
    cudaGetSymbolAddress((void**)&lfhi,  g_lfhi);
    cudaGetSymbolAddress((void**)&lflo,  g_lflo);
    cudaGetSymbolAddress((void**)&hf,    g_hf);
    cudaGetSymbolAddress((void**)&hhi,   g_hhi);
    cudaGetSymbolAddress((void**)&hlo,   g_hlo);
    cudaGetSymbolAddress((void**)&qhi,   g_qhi);
    cudaGetSymbolAddress((void**)&qlo,   g_qlo);
    cudaGetSymbolAddress((void**)&khi,   g_khi);
    cudaGetSymbolAddress((void**)&klo,   g_klo);
    cudaGetSymbolAddress((void**)&v,     g_v);
    cudaGetSymbolAddress((void**)&vthi,  g_vthi);
    cudaGetSymbolAddress((void**)&vtlo,  g_vtlo);
    cudaGetSymbolAddress((void**)&gghi,  g_gghi);
    cudaGetSymbolAddress((void**)&gglo,  g_gglo);
    cudaGetSymbolAddress((void**)&o,     g_o);
    cudaGetSymbolAddress((void**)&enthi, g_enthi);
    cudaGetSymbolAddress((void**)&entlo, g_entlo);
    cudaGetSymbolAddress((void**)&wqthi, g_wqthi);
    cudaGetSymbolAddress((void**)&wqtlo, g_wqtlo);
    cudaGetSymbolAddress((void**)&wkthi, g_wkthi);
    cudaGetSymbolAddress((void**)&wktlo, g_wktlo);
    cudaGetSymbolAddress((void**)&wvthi, g_wvthi);
    cudaGetSymbolAddress((void**)&wvtlo, g_wvtlo);
    cudaGetSymbolAddress((void**)&bnthi, g_bnthi);
    cudaGetSymbolAddress((void**)&bntlo, g_bntlo);

    cudaFuncSetAttribute(gemm_mma<false>, cudaFuncAttributeMaxDynamicSharedMemorySize, GEMM_SMEM);
    cudaFuncSetAttribute(gemm_mma<true>,  cudaFuncAttributeMaxDynamicSharedMemorySize, GEMM_SMEM);

    // 0) input conversions
    split_convert<<<(ROWS * CLIPD / 4 + 255) / 256, 256>>>(local_feat, lfhi, lflo, ROWS * CLIPD / 4);
    transpose_split<<<dim3(DD / 32, CLIPD / 32, 1), dim3(32, 8)>>>(enc_w, enthi, entlo, CLIPD, DD);
    transpose_split<<<dim3(DD / 32, DD / 32, 1),    dim3(32, 8)>>>(wq, wqthi, wqtlo, DD, DD);
    transpose_split<<<dim3(DD / 32, DD / 32, 1),    dim3(32, 8)>>>(wk, wkthi, wktlo, DD, DD);
    transpose_split<<<dim3(DD / 32, DD / 32, 1),    dim3(32, 8)>>>(wv, wvthi, wvtlo, DD, DD);
    transpose_split<<<dim3(BDIM / 32, DD / 32, 1),  dim3(32, 8)>>>(bn_w, bnthi, bntlo, DD, BDIM);

    // 1) enc GEMM: hf = lf @ enc_w + enc_b   (M=16384, N=256, K=512)
    gemm_mma<false><<<dim3(DD / 128, ROWS / 128, 1), 256, GEMM_SMEM>>>(
        lfhi, lflo, enthi, entlo, hf, nullptr, nullptr, DD, CLIPD, 0, 0, 0, 1.f, enc_b);
    // 2) LN + relu -> h splits
    ln_relu_kernel<<<ROWS, DD>>>(hf, enc_g, enc_beta, DD, hhi, hlo);

    // 3) q, k (split out), v (fp32 out, needs transpose)
    gemm_mma<true><<<dim3(DD / 128, ROWS / 128, 1), 256, GEMM_SMEM>>>(
        hhi, hlo, wqthi, wqtlo, nullptr, qhi, qlo, DD, DD, 0, 0, 0, 1.f, bq);
    gemm_mma<true><<<dim3(DD / 128, ROWS / 128, 1), 256, GEMM_SMEM>>>(
        hhi, hlo, wkthi, wktlo, nullptr, khi, klo, DD, DD, 0, 0, 0, 1.f, bk);
    gemm_mma<false><<<dim3(DD / 128, ROWS / 128, 1), 256, GEMM_SMEM>>>(
        hhi, hlo, wvthi, wvtlo, v, nullptr, nullptr, DD, DD, 0, 0, 0, 1.f, bv);
    // v -> vT splits per batch:  [b][m][d] -> [b][d][m]
    transpose_split<<<dim3(DD / 32, NTOK / 32, BB), dim3(32, 8)>>>(v, vthi, vtlo, NTOK, DD);

    // 4) scores = q @ k^T / 16, batched  (M=2048, N=2048, K=256)
    gemm_mma<false><<<dim3(NTOK / 128, NTOK / 128, BB), 256, GEMM_SMEM>>>(
        qhi, qlo, khi, klo, s, nullptr, nullptr, NTOK, DD,
        (long)NTOK * DD, (long)NTOK * DD, (long)NTOK * NTOK, 0.0625f, nullptr);

    // 5) softmax * adj * notmask -> attn splits
    softmax_adj_kernel<<<dim3(NTOK, BB), 256>>>(s, coords, mask, gamma, ahi, alo);

    // 6) agg = attn @ v (split out), batched  (M=2048, N=256, K=2048)
    gemm_mma<true><<<dim3(DD / 128, NTOK / 128, BB), 256, GEMM_SMEM>>>(
        ahi, alo, vthi, vtlo, nullptr, gghi, gglo, DD, NTOK,
        (long)NTOK * NTOK, (long)DD * NTOK, (long)NTOK * DD, 1.f, nullptr);

    // 7) bn GEMM: o = agg @ bn_w + bn_b  (M=16384, N=128, K=256)
    gemm_mma<false><<<dim3(BDIM / 128, ROWS / 128, 1), 256, GEMM_SMEM>>>(
        gghi, gglo, bnthi, bntlo, o, nullptr, nullptr, BDIM, DD, 0, 0, 0, 1.f, bn_b);
    // 8) LN + relu fp32 in place
    ln_relu_kernel<<<ROWS, BDIM>>>(o, bn_g, bn_beta, BDIM, nullptr, nullptr);

    // 9) masked mean pool -> d_out[80 : 80+1024]
    float* out_f = (float*)d_out;
    pool_kernel<<<BB, BDIM>>>(o, mask, out_f + BB * NCLS);

    // 10) MLP head -> d_out[0 : 80]
    head_kernel<<<BB, 64>>>(out_f + BB * NCLS, c1_w, c1_b, c2_w, c2_b, out_f);
}

// round 6
// speedup vs baseline: 1.7409x; 1.0018x over previous
#include <cuda_runtime.h>
#include <cuda_bf16.h>
#include <math.h>
#include <stdint.h>

#define BB 8
#define NTOK 2048
#define CLIPD 512
#define DD 256
#define BDIM 128
#define NCLS 10
#define ROWS (BB * NTOK)   // 16384

typedef __nv_bfloat16 bf16;

// ---------------- scratch (no cudaMalloc allowed) ----------------
__device__ float g_s   [BB * NTOK * NTOK];     // 134 MB scores fp32
__device__ bf16  g_ahi [BB * NTOK * NTOK];     // attn split
__device__ bf16  g_alo [BB * NTOK * NTOK];
__device__ bf16  g_lfhi[ROWS * CLIPD], g_lflo[ROWS * CLIPD];
__device__ float g_hf  [ROWS * DD];            // enc out fp32
__device__ bf16  g_hhi [ROWS * DD], g_hlo[ROWS * DD];
__device__ bf16  g_qhi [ROWS * DD], g_qlo[ROWS * DD];
__device__ bf16  g_khi [ROWS * DD], g_klo[ROWS * DD];
__device__ float g_v   [ROWS * DD];
__device__ bf16  g_vthi[ROWS * DD], g_vtlo[ROWS * DD];   // v transposed [b][d][m]
__device__ bf16  g_gghi[ROWS * DD], g_gglo[ROWS * DD];   // agg split
__device__ float g_o   [ROWS * BDIM];
__device__ bf16  g_enthi[DD * CLIPD], g_entlo[DD * CLIPD]; // enc_w^T
__device__ bf16  g_wqthi[DD * DD], g_wqtlo[DD * DD];
__device__ bf16  g_wkthi[DD * DD], g_wktlo[DD * DD];
__device__ bf16  g_wvthi[DD * DD], g_wvtlo[DD * DD];
__device__ bf16  g_bnthi[BDIM * DD], g_bntlo[BDIM * DD];

// ---------------- mma / ldmatrix / cp.async helpers ----------------
__device__ __forceinline__ uint32_t smem_u32(const void* p) {
    uint32_t a;
    asm("{ .reg .u64 t; cvta.to.shared.u64 t, %1; cvt.u32.u64 %0, t; }" : "=r"(a) : "l"(p));
    return a;
}

__device__ __forceinline__ void ldsm4(uint32_t* r, uint32_t addr) {
    asm volatile("ldmatrix.sync.aligned.m8n8.x4.shared.b16 {%0,%1,%2,%3}, [%4];"
                 : "=r"(r[0]), "=r"(r[1]), "=r"(r[2]), "=r"(r[3]) : "r"(addr));
}

__device__ __forceinline__ void mma_bf16(float* d, const uint32_t* a, const uint32_t* b) {
    asm volatile(
        "mma.sync.aligned.m16n8k16.row.col.f32.bf16.bf16.f32 "
        "{%0,%1,%2,%3}, {%4,%5,%6,%7}, {%8,%9}, {%0,%1,%2,%3};"
        : "+f"(d[0]), "+f"(d[1]), "+f"(d[2]), "+f"(d[3])
        : "r"(a[0]), "r"(a[1]), "r"(a[2]), "r"(a[3]), "r"(b[0]), "r"(b[1]));
}

__device__ __forceinline__ void cp16(uint32_t dst, const void* src) {
    asm volatile("cp.async.cg.shared.global [%0], [%1], 16;" :: "r"(dst), "l"(src));
}
#define CP_COMMIT() asm volatile("cp.async.commit_group;" ::: "memory")
#define CP_WAIT1()  asm volatile("cp.async.wait_group 1;" ::: "memory")

// ---------------- HMMA GEMM with bf16x3 split, 3-stage cp.async pipeline ----------------
// C[M,N] = alpha * (A @ B^T) + bias ; A = Ahi+Alo [M,K], B = Bhi+Blo [N,K], K-major bf16.
// Computes Ahi*Bhi + Ahi*Blo + Alo*Bhi with fp32 register accumulation.
// Block tile 128x128, BK=32, 256 threads (8 warps 4Mx2N, warp tile 32x64).
// Requires M%128==0, N%128==0, K%32==0.
#define LDSR 40                       // smem row stride in bf16 (32 + 8 pad = 80 bytes)
#define STAGE_B (128 * LDSR * 2)      // 10240 bytes per stage per matrix
#define GEMM_SMEM (6 * STAGE_B)       // 3 stages x (A+B) = 61440

template <bool SPLIT>
__global__ void __launch_bounds__(256) gemm_mma(
    const bf16* __restrict__ Ahi, const bf16* __restrict__ Alo,
    const bf16* __restrict__ Bhi, const bf16* __restrict__ Blo,
    float* __restrict__ C, bf16* __restrict__ Chi, bf16* __restrict__ Clo,
    int N, int K,
    long sA, long sB, long sC,
    float alpha, const float* __restrict__ bias)
{
    extern __shared__ char smem[];

    const int bz = blockIdx.z;
    Ahi += bz * sA; Alo += bz * sA;
    Bhi += bz * sB; Blo += bz * sB;
    const long cOff = (long)bz * sC;

    const int tid = threadIdx.x;
    const int wid = tid >> 5, lid = tid & 31;
    const int wm = wid & 3, wn = wid >> 2;     // warp coords: 4 x 2
    const int row0 = blockIdx.y * 128;
    const int col0 = blockIdx.x * 128;

    const int KT = K / 32;
    const int T = 3 * KT;

    // loader lanes: each thread owns 16 elements (32 bytes) of one A row and one B row
    const int lr = tid >> 1;            // 0..127
    const int lk = (tid & 1) * 16;      // element offset 0 / 16

    const uint32_t sBase = smem_u32(smem);
    const uint32_t aS = sBase;                    // A stages at [0, 3*STAGE_B)
    const uint32_t bS = sBase + 3 * STAGE_B;      // B stages
    const uint32_t dstOff = (uint32_t)(lr * LDSR + lk) * 2;

    auto issue = [&](int it, int buf) {
        const int pass = it / KT;
        const int k0 = (it - pass * KT) * 32;
        const bf16* Ap = (pass == 2) ? Alo : Ahi;
        const bf16* Bp = (pass == 1) ? Blo : Bhi;
        const bf16* ap = Ap + (long)(row0 + lr) * K + k0 + lk;
        const bf16* bp = Bp + (long)(col0 + lr) * K + k0 + lk;
        const uint32_t ad = aS + buf * STAGE_B + dstOff;
        const uint32_t bd = bS + buf * STAGE_B + dstOff;
        cp16(ad, ap); cp16(ad + 16, ap + 8);
        cp16(bd, bp); cp16(bd + 16, bp + 8);
    };

    float acc[2][8][4];
#pragma unroll
    for (int i = 0; i < 2; i++)
#pragma unroll
        for (int j = 0; j < 8; j++)
#pragma unroll
            for (int e = 0; e < 4; e++) acc[i][j][e] = 0.f;

    // prologue: 2 stages in flight
    issue(0, 0); CP_COMMIT();
    issue(1, 1); CP_COMMIT();

    // per-lane ldmatrix source rows (constant across iterations)
    const int arow = wm * 32 + (lid & 15);
    const int akof = (lid >> 4) * 8;
    const int brow = wn * 64 + (lid & 7) + (lid >> 4) * 8;
    const int bkof = ((lid >> 3) & 1) * 8;

    int buf = 0;
    for (int it = 0; it < T; ++it) {
        CP_WAIT1();              // stage `it` landed
        __syncthreads();

        // prefetch stage it+2 into the buffer freed at iteration it-1
        if (it + 2 < T) issue(it + 2, (buf + 2 >= 3) ? buf - 1 : buf + 2);
        CP_COMMIT();

        const uint32_t aBase = aS + buf * STAGE_B;
        const uint32_t bBase = bS + buf * STAGE_B;
#pragma unroll
        for (int ks = 0; ks < 2; ks++) {
            uint32_t af[2][4], bfr[4][4];
#pragma unroll
            for (int mt = 0; mt < 2; mt++)
                ldsm4(af[mt], aBase + (uint32_t)(((arow + mt * 16) * LDSR + ks * 16 + akof) * 2));
#pragma unroll
            for (int p = 0; p < 4; p++)
                ldsm4(bfr[p], bBase + (uint32_t)(((brow + p * 16) * LDSR + ks * 16 + bkof) * 2));
#pragma unroll
            for (int mt = 0; mt < 2; mt++)
#pragma unroll
                for (int nt = 0; nt < 8; nt++)
                    mma_bf16(acc[mt][nt], af[mt], &bfr[nt >> 1][(nt & 1) * 2]);
        }
        buf = (buf + 1 >= 3) ? 0 : buf + 1;
    }

    // epilogue: D fragment -> global
    const int mrow = row0 + wm * 32;
    const int ncol = col0 + wn * 64;
    const int r4 = lid >> 2, c2 = (lid & 3) * 2;
#pragma unroll
    for (int mt = 0; mt < 2; mt++) {
#pragma unroll
        for (int half = 0; half < 2; half++) {
            const long r = mrow + mt * 16 + r4 + half * 8;
#pragma unroll
            for (int nt = 0; nt < 8; nt++) {
                const int c = ncol + nt * 8 + c2;
                float v0 = alpha * acc[mt][nt][half * 2 + 0] + (bias ? bias[c + 0] : 0.f);
                float v1 = alpha * acc[mt][nt][half * 2 + 1] + (bias ? bias[c + 1] : 0.f);
                if (SPLIT) {
                    bf16 h0 = __float2bfloat16(v0);
                    bf16 h1 = __float2bfloat16(v1);
                    __nv_bfloat162 hh; hh.x = h0; hh.y = h1;
                    __nv_bfloat162 ll;
                    ll.x = __float2bfloat16(v0 - __bfloat162float(h0));
                    ll.y = __float2bfloat16(v1 - __bfloat162float(h1));
                    *(__nv_bfloat162*)&Chi[cOff + r * N + c] = hh;
                    *(__nv_bfloat162*)&Clo[cOff + r * N + c] = ll;
                } else {
                    float2 o; o.x = v0; o.y = v1;
                    *(float2*)&C[cOff + r * N + c] = o;
                }
            }
        }
    }
}

// ---------------- elementwise fp32 -> bf16 hi/lo split ----------------
__global__ void split_convert(const float* __restrict__ X, bf16* __restrict__ hi,
                              bf16* __restrict__ lo, int n4)
{
    int i = blockIdx.x * blockDim.x + threadIdx.x;
    if (i >= n4) return;
    float4 v = ((const float4*)X)[i];
    bf16 h0 = __float2bfloat16(v.x), h1 = __float2bfloat16(v.y);
    bf16 h2 = __float2bfloat16(v.z), h3 = __float2bfloat16(v.w);
    __nv_bfloat162 ha; ha.x = h0; ha.y = h1;
    __nv_bfloat162 hb; hb.x = h2; hb.y = h3;
    __nv_bfloat162 la; la.x = __float2bfloat16(v.x - __bfloat162float(h0));
                       la.y = __float2bfloat16(v.y - __bfloat162float(h1));
    __nv_bfloat162 lb; lb.x = __float2bfloat16(v.z - __bfloat162float(h2));
                       lb.y = __float2bfloat16(v.w - __bfloat162float(h3));
    ((__nv_bfloat162*)hi)[i * 2 + 0] = ha;
    ((__nv_bfloat162*)hi)[i * 2 + 1] = hb;
    ((__nv_bfloat162*)lo)[i * 2 + 0] = la;
    ((__nv_bfloat162*)lo)[i * 2 + 1] = lb;
}

// ---------------- batched transpose + split: X[b][R][Cc] -> T[b][Cc][R] ----------------
__global__ void transpose_split(const float* __restrict__ X, bf16* __restrict__ Thi,
                                bf16* __restrict__ Tlo, int R, int Cc)
{
    __shared__ float t[32][33];
    const long boff = (long)blockIdx.z * R * Cc;
    X += boff; Thi += boff; Tlo += boff;
    const int c0 = blockIdx.x * 32, r0 = blockIdx.y * 32;
    for (int i = threadIdx.y; i < 32; i += 8)
        t[i][threadIdx.x] = X[(long)(r0 + i) * Cc + c0 + threadIdx.x];
    __syncthreads();
    for (int i = threadIdx.y; i < 32; i += 8) {
        float v = t[threadIdx.x][i];
        bf16 h = __float2bfloat16(v);
        bf16 l = __float2bfloat16(v - __bfloat162float(h));
        long o = (long)(c0 + i) * R + r0 + threadIdx.x;
        Thi[o] = h; Tlo[o] = l;
    }
}

// ---------------- block reductions ----------------
__device__ __forceinline__ float blk_sum(float v) {
    __shared__ float sh[33];
    int lane = threadIdx.x & 31, w = threadIdx.x >> 5;
#pragma unroll
    for (int o = 16; o; o >>= 1) v += __shfl_xor_sync(0xffffffffu, v, o);
    __syncthreads();
    if (lane == 0) sh[w] = v;
    __syncthreads();
    if (threadIdx.x == 0) {
        float s = 0.f; int nw = (blockDim.x + 31) >> 5;
        for (int i = 0; i < nw; i++) s += sh[i];
        sh[32] = s;
    }
    __syncthreads();
    return sh[32];
}
__device__ __forceinline__ float blk_max(float v) {
    __shared__ float sh[33];
    int lane = threadIdx.x & 31, w = threadIdx.x >> 5;
#pragma unroll
    for (int o = 16; o; o >>= 1) v = fmaxf(v, __shfl_xor_sync(0xffffffffu, v, o));
    __syncthreads();
    if (lane == 0) sh[w] = v;
    __syncthreads();
    if (threadIdx.x == 0) {
        float s = -INFINITY; int nw = (blockDim.x + 31) >> 5;
        for (int i = 0; i < nw; i++) s = fmaxf(s, sh[i]);
        sh[32] = s;
    }
    __syncthreads();
    return sh[32];
}

// ---------------- LayerNorm + ReLU ----------------
__global__ void ln_relu_kernel(float* __restrict__ X, const float* __restrict__ g,
                               const float* __restrict__ beta, int D,
                               bf16* __restrict__ hi, bf16* __restrict__ lo)
{
    const long row = blockIdx.x;
    const int t = threadIdx.x;
    float v = X[row * D + t];
    float mu = blk_sum(v) * (1.f / D);
    float d = v - mu;
    float var = blk_sum(d * d) * (1.f / D);
    float r = d * rsqrtf(var + 1e-5f) * g[t] + beta[t];
    r = fmaxf(r, 0.f);
    if (hi) {
        bf16 h = __float2bfloat16(r);
        hi[row * D + t] = h;
        lo[row * D + t] = __float2bfloat16(r - __bfloat162float(h));
    } else {
        X[row * D + t] = r;
    }
}

// ---------------- softmax * spatial_adj * notmask -> bf16 hi/lo splits ----------------
__global__ void __launch_bounds__(256) softmax_adj_kernel(
    const float* __restrict__ S, const float* __restrict__ coords,
    const int* __restrict__ mask, const float* __restrict__ gamma,
    bf16* __restrict__ Ahi, bf16* __restrict__ Alo)
{
    const int b = blockIdx.y;
    const int n = blockIdx.x;
    const long roff = ((long)b * NTOK + n) * NTOK;
    const float* row = S + roff;
    const int t = threadIdx.x;

    float s[8];
    float mx = -INFINITY;
#pragma unroll
    for (int j = 0; j < 8; j++) {
        s[j] = row[t + j * 256];
        mx = fmaxf(mx, s[j]);
    }
    mx = blk_max(mx);

    float lsum = 0.f;
#pragma unroll
    for (int j = 0; j < 8; j++) {
        s[j] = __expf(s[j] - mx);
        lsum += s[j];
    }
    float inv = 1.f / blk_sum(lsum);

    const float ga = fabsf(gamma[0]);
    const float xn = coords[((long)b * NTOK + n) * 2 + 0];
    const float yn = coords[((long)b * NTOK + n) * 2 + 1];
    const float sqn = xn * xn + yn * yn;

#pragma unroll
    for (int j = 0; j < 8; j++) {
        const int m = t + j * 256;
        const float xm = coords[((long)b * NTOK + m) * 2 + 0];
        const float ym = coords[((long)b * NTOK + m) * 2 + 1];
        float d2 = sqn + xm * xm + ym * ym - 2.f * (xn * xm + yn * ym);
        float dist = sqrtf(fmaxf(d2, 0.f));
        float adj = __expf(-dist * ga);
        float w = mask[b * NTOK + m] ? 0.f : s[j] * inv * adj;
        bf16 h = __float2bfloat16(w);
        Ahi[roff + m] = h;
        Alo[roff + m] = __float2bfloat16(w - __bfloat162float(h));
    }
}

// ---------------- masked mean pool ----------------
__global__ void pool_kernel(const float* __restrict__ out, const int* __restrict__ mask,
                            float* __restrict__ pooled)
{
    const int b = blockIdx.x;
    const int t = threadIdx.x;  // 128
    __shared__ float sc[128];
    float c = 0.f;
    for (int n = t; n < NTOK; n += 128) c += mask[b * NTOK + n] ? 0.f : 1.f;
    sc[t] = c;
    __syncthreads();
    for (int o = 64; o; o >>= 1) { if (t < o) sc[t] += sc[t + o]; __syncthreads(); }
    const float cnt = fmaxf(sc[0], 1e-9f);

    float s = 0.f;
    const float* base = out + (long)b * NTOK * BDIM + t;
    const int* mb = mask + b * NTOK;
    for (int n = 0; n < NTOK; n++) {
        float val = base[(long)n * BDIM];
        s += mb[n] ? 0.f : val;
    }
    pooled[b * BDIM + t] = s / cnt;
}

// ---------------- head MLP ----------------
__global__ void head_kernel(const float* __restrict__ pooled,
                            const float* __restrict__ c1w, const float* __restrict__ c1b,
                            const float* __restrict__ c2w, const float* __restrict__ c2b,
                            float* __restrict__ logits)
{
    const int b = blockIdx.x;
    const int t = threadIdx.x;  // 64
    __shared__ float sp[BDIM];
    __shared__ float hid[64];
    for (int i = t; i < BDIM; i += 64) sp[i] = pooled[b * BDIM + i];
    __syncthreads();
    float s = c1b[t];
    for (int i = 0; i < BDIM; i++) s += sp[i] * c1w[i * 64 + t];
    hid[t] = fmaxf(s, 0.f);
    __syncthreads();
    if (t < NCLS) {
        float l = c2b[t];
        for (int j = 0; j < 64; j++) l += hid[j] * c2w[j * NCLS + t];
        logits[b * NCLS + t] = l;
    }
}

// ---------------- launch ----------------
extern "C" void kernel_launch(void* const* d_in, const int* in_sizes, int n_in,
                              void* d_out, int out_size)
{
    const float* local_feat = (const float*)d_in[0];
    const float* coords     = (const float*)d_in[1];
    const int*   mask       = (const int*)d_in[2];
    const float* enc_w      = (const float*)d_in[3];
    const float* enc_b      = (const float*)d_in[4];
    const float* enc_g      = (const float*)d_in[5];
    const float* enc_beta   = (const float*)d_in[6];
    const float* gamma      = (const float*)d_in[7];
    const float* wq         = (const float*)d_in[8];
    const float* bq         = (const float*)d_in[9];
    const float* wk         = (const float*)d_in[10];
    const float* bk         = (const float*)d_in[11];
    const float* wv         = (const float*)d_in[12];
    const float* bv         = (const float*)d_in[13];
    const float* bn_w       = (const float*)d_in[14];
    const float* bn_b       = (const float*)d_in[15];
    const float* bn_g       = (const float*)d_in[16];
    const float* bn_beta    = (const float*)d_in[17];
    const float* c1_w       = (const float*)d_in[18];
    const float* c1_b       = (const float*)d_in[19];
    const float* c2_w       = (const float*)d_in[20];
    const float* c2_b       = (const float*)d_in[21];

    float *s, *hf, *v, *o;
    bf16 *ahi, *alo, *lfhi, *lflo, *hhi, *hlo, *qhi, *qlo, *khi, *klo;
    bf16 *vthi, *vtlo, *gghi, *gglo;
    bf16 *enthi, *entlo, *wqthi, *wqtlo, *wkthi, *wktlo, *wvthi, *wvtlo, *bnthi, *bntlo;
    cudaGetSymbolAddress((void**)&s,     g_s);
    cudaGetSymbolAddress((void**)&ahi,   g_ahi);
    cudaGetSymbolAddress((void**)&alo,   g_alo);
    cudaGetSymbolAddress((void**)&lfhi,  g_lfhi);
    cudaGetSymbolAddress((void**)&lflo,  g_lflo);
    cudaGetSymbolAddress((void**)&hf,    g_hf);
    cudaGetSymbolAddress((void**)&hhi,   g_hhi);
    cudaGetSymbolAddress((void**)&hlo,   g_hlo);
    cudaGetSymbolAddress((void**)&qhi,   g_qhi);
    cudaGetSymbolAddress((void**)&qlo,   g_qlo);
    cudaGetSymbolAddress((void**)&khi,   g_khi);
    cudaGetSymbolAddress((void**)&klo,   g_klo);
    cudaGetSymbolAddress((void**)&v,     g_v);
    cudaGetSymbolAddress((void**)&vthi,  g_vthi);
    cudaGetSymbolAddress((void**)&vtlo,  g_vtlo);
    cudaGetSymbolAddress((void**)&gghi,  g_gghi);
    cudaGetSymbolAddress((void**)&gglo,  g_gglo);
    cudaGetSymbolAddress((void**)&o,     g_o);
    cudaGetSymbolAddress((void**)&enthi, g_enthi);
    cudaGetSymbolAddress((void**)&entlo, g_entlo);
    cudaGetSymbolAddress((void**)&wqthi, g_wqthi);
    cudaGetSymbolAddress((void**)&wqtlo, g_wqtlo);
    cudaGetSymbolAddress((void**)&wkthi, g_wkthi);
    cudaGetSymbolAddress((void**)&wktlo, g_wktlo);
    cudaGetSymbolAddress((void**)&wvthi, g_wvthi);
    cudaGetSymbolAddress((void**)&wvtlo, g_wvtlo);
    cudaGetSymbolAddress((void**)&bnthi, g_bnthi);
    cudaGetSymbolAddress((void**)&bntlo, g_bntlo);

    cudaFuncSetAttribute(gemm_mma<false>, cudaFuncAttributeMaxDynamicSharedMemorySize, GEMM_SMEM);
    cudaFuncSetAttribute(gemm_mma<true>,  cudaFuncAttributeMaxDynamicSharedMemorySize, GEMM_SMEM);

    // 0) input conversions
    split_convert<<<(ROWS * CLIPD / 4 + 255) / 256, 256>>>(local_feat, lfhi, lflo, ROWS * CLIPD / 4);
    transpose_split<<<dim3(DD / 32, CLIPD / 32, 1), dim3(32, 8)>>>(enc_w, enthi, entlo, CLIPD, DD);
    transpose_split<<<dim3(DD / 32, DD / 32, 1),    dim3(32, 8)>>>(wq, wqthi, wqtlo, DD, DD);
    transpose_split<<<dim3(DD / 32, DD / 32, 1),    dim3(32, 8)>>>(wk, wkthi, wktlo, DD, DD);
    transpose_split<<<dim3(DD / 32, DD / 32, 1),    dim3(32, 8)>>>(wv, wvthi, wvtlo, DD, DD);
    transpose_split<<<dim3(BDIM / 32, DD / 32, 1),  dim3(32, 8)>>>(bn_w, bnthi, bntlo, DD, BDIM);

    // 1) enc GEMM: hf = lf @ enc_w + enc_b   (M=16384, N=256, K=512)
    gemm_mma<false><<<dim3(DD / 128, ROWS / 128, 1), 256, GEMM_SMEM>>>(
        lfhi, lflo, enthi, entlo, hf, nullptr, nullptr, DD, CLIPD, 0, 0, 0, 1.f, enc_b);
    // 2) LN + relu -> h splits
    ln_relu_kernel<<<ROWS, DD>>>(hf, enc_g, enc_beta, DD, hhi, hlo);

    // 3) q, k (split out), v (fp32 out, needs transpose)
    gemm_mma<true><<<dim3(DD / 128, ROWS / 128, 1), 256, GEMM_SMEM>>>(
        hhi, hlo, wqthi, wqtlo, nullptr, qhi, qlo, DD, DD, 0, 0, 0, 1.f, bq);
    gemm_mma<true><<<dim3(DD / 128, ROWS / 128, 1), 256, GEMM_SMEM>>>(
        hhi, hlo, wkthi, wktlo, nullptr, khi, klo, DD, DD, 0, 0, 0, 1.f, bk);
    gemm_mma<false><<<dim3(DD / 128, ROWS / 128, 1), 256, GEMM_SMEM>>>(
        hhi, hlo, wvthi, wvtlo, v, nullptr, nullptr, DD, DD, 0, 0, 0, 1.f, bv);
    // v -> vT splits per batch:  [b][m][d] -> [b][d][m]
    transpose_split<<<dim3(DD / 32, NTOK / 32, BB), dim3(32, 8)>>>(v, vthi, vtlo, NTOK, DD);

    // 4) scores = q @ k^T / 16, batched  (M=2048, N=2048, K=256)
    gemm_mma<false><<<dim3(NTOK / 128, NTOK / 128, BB), 256, GEMM_SMEM>>>(
        qhi, qlo, khi, klo, s, nullptr, nullptr, NTOK, DD,
        (long)NTOK * DD, (long)NTOK * DD, (long)NTOK * NTOK, 0.0625f, nullptr);

    // 5) softmax * adj * notmask -> attn splits
    softmax_adj_kernel<<<dim3(NTOK, BB), 256>>>(s, coords, mask, gamma, ahi, alo);

    // 6) agg = attn @ v (split out), batched  (M=2048, N=256, K=2048)
    gemm_mma<true><<<dim3(DD / 128, NTOK / 128, BB), 256, GEMM_SMEM>>>(
        ahi, alo, vthi, vtlo, nullptr, gghi, gglo, DD, NTOK,
        (long)NTOK * NTOK, (long)DD * NTOK, (long)NTOK * DD, 1.f, nullptr);

    // 7) bn GEMM: o = agg @ bn_w + bn_b  (M=16384, N=128, K=256)
    gemm_mma<false><<<dim3(BDIM / 128, ROWS / 128, 1), 256, GEMM_SMEM>>>(
        gghi, gglo, bnthi, bntlo, o, nullptr, nullptr, BDIM, DD, 0, 0, 0, 1.f, bn_b);
    // 8) LN + relu fp32 in place
    ln_relu_kernel<<<ROWS, BDIM>>>(o, bn_g, bn_beta, BDIM, nullptr, nullptr);

    // 9) masked mean pool -> d_out[80 : 80+1024]
    float* out_f = (float*)d_out;
    pool_kernel<<<BB, BDIM>>>(o, mask, out_f + BB * NCLS);

    // 10) MLP head -> d_out[0 : 80]
    head_kernel<<<BB, 64>>>(out_f + BB * NCLS, c1_w, c1_b, c2_w, c2_b, out_f);
}

// round 7
// speedup vs baseline: 3.3278x; 1.9115x over previous
#include <cuda_runtime.h>
#include <cuda_fp16.h>
#include <math.h>
#include <stdint.h>

#define BB 8
#define NTOK 2048
#define CLIPD 512
#define DD 256
#define BDIM 128
#define NCLS 10
#define ROWS (BB * NTOK)   // 16384

// ---------------- scratch (no cudaMalloc allowed) ----------------
__device__ float  g_s  [BB * NTOK * NTOK];     // 134 MB scores fp32
__device__ __half g_a16[BB * NTOK * NTOK];     // attn fp16
__device__ __half g_lf [ROWS * CLIPD];
__device__ float  g_hf [ROWS * DD];            // enc out fp32
__device__ __half g_h16[ROWS * DD];
__device__ __half g_q16[ROWS * DD];
__device__ __half g_k16[ROWS * DD];
__device__ float  g_v  [ROWS * DD];
__device__ __half g_vt [ROWS * DD];            // v transposed [b][d][m]
__device__ __half g_gg [ROWS * DD];            // agg fp16
__device__ float  g_o  [ROWS * BDIM];
__device__ __half g_ent[DD * CLIPD];           // enc_w^T
__device__ __half g_wqt[DD * DD];
__device__ __half g_wkt[DD * DD];
__device__ __half g_wvt[DD * DD];
__device__ __half g_bnt[BDIM * DD];

// ---------------- mma / ldmatrix / cp.async helpers ----------------
__device__ __forceinline__ uint32_t smem_u32(const void* p) {
    uint32_t a;
    asm("{ .reg .u64 t; cvta.to.shared.u64 t, %1; cvt.u32.u64 %0, t; }" : "=r"(a) : "l"(p));
    return a;
}

__device__ __forceinline__ void ldsm4(uint32_t* r, uint32_t addr) {
    asm volatile("ldmatrix.sync.aligned.m8n8.x4.shared.b16 {%0,%1,%2,%3}, [%4];"
                 : "=r"(r[0]), "=r"(r[1]), "=r"(r[2]), "=r"(r[3]) : "r"(addr));
}

__device__ __forceinline__ void mma_f16(float* d, const uint32_t* a, const uint32_t* b) {
    asm volatile(
        "mma.sync.aligned.m16n8k16.row.col.f32.f16.f16.f32 "
        "{%0,%1,%2,%3}, {%4,%5,%6,%7}, {%8,%9}, {%0,%1,%2,%3};"
        : "+f"(d[0]), "+f"(d[1]), "+f"(d[2]), "+f"(d[3])
        : "r"(a[0]), "r"(a[1]), "r"(a[2]), "r"(a[3]), "r"(b[0]), "r"(b[1]));
}

__device__ __forceinline__ void cp16(uint32_t dst, const void* src) {
    asm volatile("cp.async.cg.shared.global [%0], [%1], 16;" :: "r"(dst), "l"(src));
}
#define CP_COMMIT() asm volatile("cp.async.commit_group;" ::: "memory")
#define CP_WAIT1()  asm volatile("cp.async.wait_group 1;" ::: "memory")

// ---------------- fp16 HMMA GEMM, single pass, 3-stage cp.async pipeline ----------------
// C[M,N] = alpha * (A @ B^T) + bias ; A [M,K], B [N,K], K-major fp16, fp32 accumulation.
// Block tile 128x128, BK=32, 256 threads (8 warps 4Mx2N, warp tile 32x64).
// Requires M%128==0, N%128==0, K%32==0, K>=96.
#define LDSR 40                       // smem row stride in fp16 (32 + 8 pad = 80 bytes)
#define STAGE_B (128 * LDSR * 2)      // 10240 bytes per stage per matrix
#define GEMM_SMEM (6 * STAGE_B)       // 3 stages x (A+B) = 61440

template <bool HALF_OUT>
__global__ void __launch_bounds__(256) gemm_mma(
    const __half* __restrict__ A, const __half* __restrict__ B,
    float* __restrict__ C, __half* __restrict__ Ch,
    int N, int K,
    long sA, long sB, long sC,
    float alpha, const float* __restrict__ bias)
{
    extern __shared__ char smem[];

    const int bz = blockIdx.z;
    A += bz * sA; B += bz * sB;
    const long cOff = (long)bz * sC;

    const int tid = threadIdx.x;
    const int wid = tid >> 5, lid = tid & 31;
    const int wm = wid & 3, wn = wid >> 2;     // warp coords: 4 x 2
    const int row0 = blockIdx.y * 128;
    const int col0 = blockIdx.x * 128;

    const int T = K / 32;

    // loader lanes: each thread owns 16 elements (32 bytes) of one A row and one B row
    const int lr = tid >> 1;            // 0..127
    const int lk = (tid & 1) * 16;      // element offset 0 / 16

    const uint32_t sBase = smem_u32(smem);
    const uint32_t aS = sBase;                    // A stages
    const uint32_t bS = sBase + 3 * STAGE_B;      // B stages
    const uint32_t dstOff = (uint32_t)(lr * LDSR + lk) * 2;

    const __half* ag = A + (long)(row0 + lr) * K + lk;
    const __half* bg = B + (long)(col0 + lr) * K + lk;

    auto issue = [&](int it, int buf) {
        const __half* ap = ag + it * 32;
        const __half* bp = bg + it * 32;
        const uint32_t ad = aS + buf * STAGE_B + dstOff;
        const uint32_t bd = bS + buf * STAGE_B + dstOff;
        cp16(ad, ap); cp16(ad + 16, ap + 8);
        cp16(bd, bp); cp16(bd + 16, bp + 8);
    };

    float acc[2][8][4];
#pragma unroll
    for (int i = 0; i < 2; i++)
#pragma unroll
        for (int j = 0; j < 8; j++)
#pragma unroll
            for (int e = 0; e < 4; e++) acc[i][j][e] = 0.f;

    // prologue: 2 stages in flight
    issue(0, 0); CP_COMMIT();
    issue(1, 1); CP_COMMIT();

    // per-lane ldmatrix source rows (constant across iterations)
    const int arow = wm * 32 + (lid & 15);
    const int akof = (lid >> 4) * 8;
    const int brow = wn * 64 + (lid & 7) + (lid >> 4) * 8;
    const int bkof = ((lid >> 3) & 1) * 8;

    int buf = 0;
    for (int it = 0; it < T; ++it) {
        CP_WAIT1();              // stage `it` landed
        __syncthreads();

        // prefetch stage it+2 into the buffer freed at iteration it-1
        if (it + 2 < T) issue(it + 2, (buf + 2 >= 3) ? buf - 1 : buf + 2);
        CP_COMMIT();

        const uint32_t aBase = aS + buf * STAGE_B;
        const uint32_t bBase = bS + buf * STAGE_B;
#pragma unroll
        for (int ks = 0; ks < 2; ks++) {
            uint32_t af[2][4], bfr[4][4];
#pragma unroll
            for (int mt = 0; mt < 2; mt++)
                ldsm4(af[mt], aBase + (uint32_t)(((arow + mt * 16) * LDSR + ks * 16 + akof) * 2));
#pragma unroll
            for (int p = 0; p < 4; p++)
                ldsm4(bfr[p], bBase + (uint32_t)(((brow + p * 16) * LDSR + ks * 16 + bkof) * 2));
#pragma unroll
            for (int mt = 0; mt < 2; mt++)
#pragma unroll
                for (int nt = 0; nt < 8; nt++)
                    mma_f16(acc[mt][nt], af[mt], &bfr[nt >> 1][(nt & 1) * 2]);
        }
        buf = (buf + 1 >= 3) ? 0 : buf + 1;
    }

    // epilogue: D fragment -> global
    const int mrow = row0 + wm * 32;
    const int ncol = col0 + wn * 64;
    const int r4 = lid >> 2, c2 = (lid & 3) * 2;
#pragma unroll
    for (int mt = 0; mt < 2; mt++) {
#pragma unroll
        for (int half = 0; half < 2; half++) {
            const long r = mrow + mt * 16 + r4 + half * 8;
#pragma unroll
            for (int nt = 0; nt < 8; nt++) {
                const int c = ncol + nt * 8 + c2;
                float v0 = alpha * acc[mt][nt][half * 2 + 0] + (bias ? bias[c + 0] : 0.f);
                float v1 = alpha * acc[mt][nt][half * 2 + 1] + (bias ? bias[c + 1] : 0.f);
                if (HALF_OUT) {
                    __half2 hh; hh.x = __float2half(v0); hh.y = __float2half(v1);
                    *(__half2*)&Ch[cOff + r * N + c] = hh;
                } else {
                    float2 o; o.x = v0; o.y = v1;
                    *(float2*)&C[cOff + r * N + c] = o;
                }
            }
        }
    }
}

// ---------------- elementwise fp32 -> fp16 convert ----------------
__global__ void convert_half(const float* __restrict__ X, __half* __restrict__ Y, int n4)
{
    int i = blockIdx.x * blockDim.x + threadIdx.x;
    if (i >= n4) return;
    float4 v = ((const float4*)X)[i];
    __half2 a; a.x = __float2half(v.x); a.y = __float2half(v.y);
    __half2 b; b.x = __float2half(v.z); b.y = __float2half(v.w);
    ((__half2*)Y)[i * 2 + 0] = a;
    ((__half2*)Y)[i * 2 + 1] = b;
}

// ---------------- batched transpose + convert: X[b][R][Cc] -> T[b][Cc][R] fp16 ----------------
__global__ void transpose_half(const float* __restrict__ X, __half* __restrict__ Tt,
                               int R, int Cc)
{
    __shared__ float t[32][33];
    const long boff = (long)blockIdx.z * R * Cc;
    X += boff; Tt += boff;
    const int c0 = blockIdx.x * 32, r0 = blockIdx.y * 32;
    for (int i = threadIdx.y; i < 32; i += 8)
        t[i][threadIdx.x] = X[(long)(r0 + i) * Cc + c0 + threadIdx.x];
    __syncthreads();
    for (int i = threadIdx.y; i < 32; i += 8) {
        long o = (long)(c0 + i) * R + r0 + threadIdx.x;
        Tt[o] = __float2half(t[threadIdx.x][i]);
    }
}

// ---------------- block reductions ----------------
__device__ __forceinline__ float blk_sum(float v) {
    __shared__ float sh[33];
    int lane = threadIdx.x & 31, w = threadIdx.x >> 5;
#pragma unroll
    for (int o = 16; o; o >>= 1) v += __shfl_xor_sync(0xffffffffu, v, o);
    __syncthreads();
    if (lane == 0) sh[w] = v;
    __syncthreads();
    if (threadIdx.x == 0) {
        float s = 0.f; int nw = (blockDim.x + 31) >> 5;
        for (int i = 0; i < nw; i++) s += sh[i];
        sh[32] = s;
    }
    __syncthreads();
    return sh[32];
}
__device__ __forceinline__ float blk_max(float v) {
    __shared__ float sh[33];
    int lane = threadIdx.x & 31, w = threadIdx.x >> 5;
#pragma unroll
    for (int o = 16; o; o >>= 1) v = fmaxf(v, __shfl_xor_sync(0xffffffffu, v, o));
    __syncthreads();
    if (lane == 0) sh[w] = v;
    __syncthreads();
    if (threadIdx.x == 0) {
        float s = -INFINITY; int nw = (blockDim.x + 31) >> 5;
        for (int i = 0; i < nw; i++) s = fmaxf(s, sh[i]);
        sh[32] = s;
    }
    __syncthreads();
    return sh[32];
}

// ---------------- LayerNorm + ReLU ----------------
// if h16 != null: write fp16 output; else write X in place (fp32)
__global__ void ln_relu_kernel(float* __restrict__ X, const float* __restrict__ g,
                               const float* __restrict__ beta, int D,
                               __half* __restrict__ h16)
{
    const long row = blockIdx.x;
    const int t = threadIdx.x;
    float v = X[row * D + t];
    float mu = blk_sum(v) * (1.f / D);
    float d = v - mu;
    float var = blk_sum(d * d) * (1.f / D);
    float r = d * rsqrtf(var + 1e-5f) * g[t] + beta[t];
    r = fmaxf(r, 0.f);
    if (h16) h16[row * D + t] = __float2half(r);
    else     X[row * D + t] = r;
}

// ---------------- softmax * spatial_adj * notmask -> fp16 ----------------
__global__ void __launch_bounds__(256) softmax_adj_kernel(
    const float* __restrict__ S, const float* __restrict__ coords,
    const int* __restrict__ mask, const float* __restrict__ gamma,
    __half* __restrict__ A16)
{
    const int b = blockIdx.y;
    const int n = blockIdx.x;
    const long roff = ((long)b * NTOK + n) * NTOK;
    const float* row = S + roff;
    const int t = threadIdx.x;

    float s[8];
    float mx = -INFINITY;
#pragma unroll
    for (int j = 0; j < 8; j++) {
        s[j] = row[t + j * 256];
        mx = fmaxf(mx, s[j]);
    }
    mx = blk_max(mx);

    float lsum = 0.f;
#pragma unroll
    for (int j = 0; j < 8; j++) {
        s[j] = __expf(s[j] - mx);
        lsum += s[j];
    }
    float inv = 1.f / blk_sum(lsum);

    const float ga = fabsf(gamma[0]);
    const float xn = coords[((long)b * NTOK + n) * 2 + 0];
    const float yn = coords[((long)b * NTOK + n) * 2 + 1];
    const float sqn = xn * xn + yn * yn;

#pragma unroll
    for (int j = 0; j < 8; j++) {
        const int m = t + j * 256;
        const float xm = coords[((long)b * NTOK + m) * 2 + 0];
        const float ym = coords[((long)b * NTOK + m) * 2 + 1];
        float d2 = sqn + xm * xm + ym * ym - 2.f * (xn * xm + yn * ym);
        float dist = sqrtf(fmaxf(d2, 0.f));
        float adj = __expf(-dist * ga);
        float w = mask[b * NTOK + m] ? 0.f : s[j] * inv * adj;
        A16[roff + m] = __float2half(w);
    }
}

// ---------------- masked mean pool ----------------
__global__ void pool_kernel(const float* __restrict__ out, const int* __restrict__ mask,
                            float* __restrict__ pooled)
{
    const int b = blockIdx.x;
    const int t = threadIdx.x;  // 128
    __shared__ float sc[128];
    float c = 0.f;
    for (int n = t; n < NTOK; n += 128) c += mask[b * NTOK + n] ? 0.f : 1.f;
    sc[t] = c;
    __syncthreads();
    for (int o = 64; o; o >>= 1) { if (t < o) sc[t] += sc[t + o]; __syncthreads(); }
    const float cnt = fmaxf(sc[0], 1e-9f);

    float s = 0.f;
    const float* base = out + (long)b * NTOK * BDIM + t;
    const int* mb = mask + b * NTOK;
    for (int n = 0; n < NTOK; n++) {
        float val = base[(long)n * BDIM];
        s += mb[n] ? 0.f : val;
    }
    pooled[b * BDIM + t] = s / cnt;
}

// ---------------- head MLP ----------------
__global__ void head_kernel(const float* __restrict__ pooled,
                            const float* __restrict__ c1w, const float* __restrict__ c1b,
                            const float* __restrict__ c2w, const float* __restrict__ c2b,
                            float* __restrict__ logits)
{
    const int b = blockIdx.x;
    const int t = threadIdx.x;  // 64
    __shared__ float sp[BDIM];
    __shared__ float hid[64];
    for (int i = t; i < BDIM; i += 64) sp[i] = pooled[b * BDIM + i];
    __syncthreads();
    float s = c1b[t];
    for (int i = 0; i < BDIM; i++) s += sp[i] * c1w[i * 64 + t];
    hid[t] = fmaxf(s, 0.f);
    __syncthreads();
    if (t < NCLS) {
        float l = c2b[t];
        for (int j = 0; j < 64; j++) l += hid[j] * c2w[j * NCLS + t];
        logits[b * NCLS + t] = l;
    }
}

// ---------------- launch ----------------
extern "C" void kernel_launch(void* const* d_in, const int* in_sizes, int n_in,
                              void* d_out, int out_size)
{
    const float* local_feat = (const float*)d_in[0];
    const float* coords     = (const float*)d_in[1];
    const int*   mask       = (const int*)d_in[2];
    const float* enc_w      = (const float*)d_in[3];
    const float* enc_b      = (const float*)d_in[4];
    const float* enc_g      = (const float*)d_in[5];
    const float* enc_beta   = (const float*)d_in[6];
    const float* gamma      = (const float*)d_in[7];
    const float* wq         = (const float*)d_in[8];
    const float* bq         = (const float*)d_in[9];
    const float* wk         = (const float*)d_in[10];
    const float* bk         = (const float*)d_in[11];
    const float* wv         = (const float*)d_in[12];
    const float* bv         = (const float*)d_in[13];
    const float* bn_w       = (const float*)d_in[14];
    const float* bn_b       = (const float*)d_in[15];
    const float* bn_g       = (const float*)d_in[16];
    const float* bn_beta    = (const float*)d_in[17];
    const float* c1_w       = (const float*)d_in[18];
    const float* c1_b       = (const float*)d_in[19];
    const float* c2_w       = (const float*)d_in[20];
    const float* c2_b       = (const float*)d_in[21];

    float *s, *hf, *v, *o;
    __half *a16, *lf, *h16, *q16, *k16, *vt, *gg, *ent, *wqt, *wkt, *wvt, *bnt;
    cudaGetSymbolAddress((void**)&s,   g_s);
    cudaGetSymbolAddress((void**)&a16, g_a16);
    cudaGetSymbolAddress((void**)&lf,  g_lf);
    cudaGetSymbolAddress((void**)&hf,  g_hf);
    cudaGetSymbolAddress((void**)&h16, g_h16);
    cudaGetSymbolAddress((void**)&q16, g_q16);
    cudaGetSymbolAddress((void**)&k16, g_k16);
    cudaGetSymbolAddress((void**)&v,   g_v);
    cudaGetSymbolAddress((void**)&vt,  g_vt);
    cudaGetSymbolAddress((void**)&gg,  g_gg);
    cudaGetSymbolAddress((void**)&o,   g_o);
    cudaGetSymbolAddress((void**)&ent, g_ent);
    cudaGetSymbolAddress((void**)&wqt, g_wqt);
    cudaGetSymbolAddress((void**)&wkt, g_wkt);
    cudaGetSymbolAddress((void**)&wvt, g_wvt);
    cudaGetSymbolAddress((void**)&bnt, g_bnt);

    cudaFuncSetAttribute(gemm_mma<false>, cudaFuncAttributeMaxDynamicSharedMemorySize, GEMM_SMEM);
    cudaFuncSetAttribute(gemm_mma<true>,  cudaFuncAttributeMaxDynamicSharedMemorySize, GEMM_SMEM);

    // 0) input conversions
    convert_half<<<(ROWS * CLIPD / 4 + 255) / 256, 256>>>(local_feat, lf, ROWS * CLIPD / 4);
    transpose_half<<<dim3(DD / 32, CLIPD / 32, 1), dim3(32, 8)>>>(enc_w, ent, CLIPD, DD);
    transpose_half<<<dim3(DD / 32, DD / 32, 1),    dim3(32, 8)>>>(wq, wqt, DD, DD);
    transpose_half<<<dim3(DD / 32, DD / 32, 1),    dim3(32, 8)>>>(wk, wkt, DD, DD);
    transpose_half<<<dim3(DD / 32, DD / 32, 1),    dim3(32, 8)>>>(wv, wvt, DD, DD);
    transpose_half<<<dim3(BDIM / 32, DD / 32, 1),  dim3(32, 8)>>>(bn_w, bnt, DD, BDIM);

    // 1) enc GEMM: hf = lf @ enc_w + enc_b   (M=16384, N=256, K=512)
    gemm_mma<false><<<dim3(DD / 128, ROWS / 128, 1), 256, GEMM_SMEM>>>(
        lf, ent, hf, nullptr, DD, CLIPD, 0, 0, 0, 1.f, enc_b);
    // 2) LN + relu -> h fp16
    ln_relu_kernel<<<ROWS, DD>>>(hf, enc_g, enc_beta, DD, h16);

    // 3) q, k (fp16 out), v (fp32 out, needs transpose)
    gemm_mma<true><<<dim3(DD / 128, ROWS / 128, 1), 256, GEMM_SMEM>>>(
        h16, wqt, nullptr, q16, DD, DD, 0, 0, 0, 1.f, bq);
    gemm_mma<true><<<dim3(DD / 128, ROWS / 128, 1), 256, GEMM_SMEM>>>(
        h16, wkt, nullptr, k16, DD, DD, 0, 0, 0, 1.f, bk);
    gemm_mma<false><<<dim3(DD / 128, ROWS / 128, 1), 256, GEMM_SMEM>>>(
        h16, wvt, v, nullptr, DD, DD, 0, 0, 0, 1.f, bv);
    // v -> vT fp16 per batch:  [b][m][d] -> [b][d][m]
    transpose_half<<<dim3(DD / 32, NTOK / 32, BB), dim3(32, 8)>>>(v, vt, NTOK, DD);

    // 4) scores = q @ k^T / 16, batched  (M=2048, N=2048, K=256)
    gemm_mma<false><<<dim3(NTOK / 128, NTOK / 128, BB), 256, GEMM_SMEM>>>(
        q16, k16, s, nullptr, NTOK, DD,
        (long)NTOK * DD, (long)NTOK * DD, (long)NTOK * NTOK, 0.0625f, nullptr);

    // 5) softmax * adj * notmask -> attn fp16
    softmax_adj_kernel<<<dim3(NTOK, BB), 256>>>(s, coords, mask, gamma, a16);

    // 6) agg = attn @ v (fp16 out), batched  (M=2048, N=256, K=2048)
    gemm_mma<true><<<dim3(DD / 128, NTOK / 128, BB), 256, GEMM_SMEM>>>(
        a16, vt, nullptr, gg, DD, NTOK,
        (long)NTOK * NTOK, (long)DD * NTOK, (long)NTOK * DD, 1.f, nullptr);

    // 7) bn GEMM: o = agg @ bn_w + bn_b  (M=16384, N=128, K=256)
    gemm_mma<false><<<dim3(BDIM / 128, ROWS / 128, 1), 256, GEMM_SMEM>>>(
        gg, bnt, o, nullptr, BDIM, DD, 0, 0, 0, 1.f, bn_b);
    // 8) LN + relu fp32 in place
    ln_relu_kernel<<<ROWS, BDIM>>>(o, bn_g, bn_beta, BDIM, nullptr);

    // 9) masked mean pool -> d_out[80 : 80+1024]
    float* out_f = (float*)d_out;
    pool_kernel<<<BB, BDIM>>>(o, mask, out_f + BB * NCLS);

    // 10) MLP head -> d_out[0 : 80]
    head_kernel<<<BB, 64>>>(out_f + BB * NCLS, c1_w, c1_b, c2_w, c2_b, out_f);
}

// round 8
// speedup vs baseline: 3.6421x; 1.0945x over previous
#include <cuda_runtime.h>
#include <cuda_fp16.h>
#include <math.h>
#include <stdint.h>

#define BB 8
#define NTOK 2048
#define CLIPD 512
#define DD 256
#define BDIM 128
#define NCLS 10
#define ROWS (BB * NTOK)   // 16384

// ---------------- scratch (no cudaMalloc allowed) ----------------
__device__ __half g_lf [ROWS * CLIPD];
__device__ float  g_hf [ROWS * DD];            // enc out fp32
__device__ __half g_h16[ROWS * DD];
__device__ __half g_q16[ROWS * DD];
__device__ __half g_k16[ROWS * DD];
__device__ float  g_v  [ROWS * DD];
__device__ __half g_vt [ROWS * DD];            // v transposed [b][d][m]
__device__ __half g_gg [ROWS * DD];            // agg fp16
__device__ float  g_o  [ROWS * BDIM];
__device__ __half g_ent[DD * CLIPD];           // enc_w^T
__device__ __half g_wqt[DD * DD];
__device__ __half g_wkt[DD * DD];
__device__ __half g_wvt[DD * DD];
__device__ __half g_bnt[BDIM * DD];
__device__ float  g_pp [BB * 16 * BDIM];       // pool partials
__device__ float  g_pc [BB * 16];

// ---------------- mma / ldmatrix / cp.async helpers ----------------
__device__ __forceinline__ uint32_t smem_u32(const void* p) {
    uint32_t a;
    asm("{ .reg .u64 t; cvta.to.shared.u64 t, %1; cvt.u32.u64 %0, t; }" : "=r"(a) : "l"(p));
    return a;
}
__device__ __forceinline__ void ldsm4(uint32_t* r, uint32_t addr) {
    asm volatile("ldmatrix.sync.aligned.m8n8.x4.shared.b16 {%0,%1,%2,%3}, [%4];"
                 : "=r"(r[0]), "=r"(r[1]), "=r"(r[2]), "=r"(r[3]) : "r"(addr));
}
__device__ __forceinline__ void mma_f16(float* d, const uint32_t* a, const uint32_t* b) {
    asm volatile(
        "mma.sync.aligned.m16n8k16.row.col.f32.f16.f16.f32 "
        "{%0,%1,%2,%3}, {%4,%5,%6,%7}, {%8,%9}, {%0,%1,%2,%3};"
        : "+f"(d[0]), "+f"(d[1]), "+f"(d[2]), "+f"(d[3])
        : "r"(a[0]), "r"(a[1]), "r"(a[2]), "r"(a[3]), "r"(b[0]), "r"(b[1]));
}
__device__ __forceinline__ void cp16(uint32_t dst, const void* src) {
    asm volatile("cp.async.cg.shared.global [%0], [%1], 16;" :: "r"(dst), "l"(src));
}
#define CP_COMMIT() asm volatile("cp.async.commit_group;" ::: "memory")
#define CP_WAIT1()  asm volatile("cp.async.wait_group 1;" ::: "memory")

// ---------------- fp16 HMMA GEMM, 3-stage cp.async pipeline ----------------
#define LDSR 40
#define STAGE_B (128 * LDSR * 2)
#define GEMM_SMEM (6 * STAGE_B)

template <bool HALF_OUT>
__global__ void __launch_bounds__(256) gemm_mma(
    const __half* __restrict__ A, const __half* __restrict__ B,
    float* __restrict__ C, __half* __restrict__ Ch,
    int N, int K, long sA, long sB, long sC,
    float alpha, const float* __restrict__ bias)
{
    extern __shared__ char smem[];
    const int bz = blockIdx.z;
    A += bz * sA; B += bz * sB;
    const long cOff = (long)bz * sC;

    const int tid = threadIdx.x;
    const int wid = tid >> 5, lid = tid & 31;
    const int wm = wid & 3, wn = wid >> 2;
    const int row0 = blockIdx.y * 128;
    const int col0 = blockIdx.x * 128;
    const int T = K / 32;

    const int lr = tid >> 1;
    const int lk = (tid & 1) * 16;

    const uint32_t sBase = smem_u32(smem);
    const uint32_t aS = sBase;
    const uint32_t bS = sBase + 3 * STAGE_B;
    const uint32_t dstOff = (uint32_t)(lr * LDSR + lk) * 2;

    const __half* ag = A + (long)(row0 + lr) * K + lk;
    const __half* bg = B + (long)(col0 + lr) * K + lk;

    auto issue = [&](int it, int buf) {
        const __half* ap = ag + it * 32;
        const __half* bp = bg + it * 32;
        const uint32_t ad = aS + buf * STAGE_B + dstOff;
        const uint32_t bd = bS + buf * STAGE_B + dstOff;
        cp16(ad, ap); cp16(ad + 16, ap + 8);
        cp16(bd, bp); cp16(bd + 16, bp + 8);
    };

    float acc[2][8][4];
#pragma unroll
    for (int i = 0; i < 2; i++)
#pragma unroll
        for (int j = 0; j < 8; j++)
#pragma unroll
            for (int e = 0; e < 4; e++) acc[i][j][e] = 0.f;

    issue(0, 0); CP_COMMIT();
    issue(1, 1); CP_COMMIT();

    const int arow = wm * 32 + (lid & 15);
    const int akof = (lid >> 4) * 8;
    const int brow = wn * 64 + (lid & 7) + (lid >> 4) * 8;
    const int bkof = ((lid >> 3) & 1) * 8;

    int buf = 0;
    for (int it = 0; it < T; ++it) {
        CP_WAIT1();
        __syncthreads();
        if (it + 2 < T) issue(it + 2, (buf + 2 >= 3) ? buf - 1 : buf + 2);
        CP_COMMIT();

        const uint32_t aBase = aS + buf * STAGE_B;
        const uint32_t bBase = bS + buf * STAGE_B;
#pragma unroll
        for (int ks = 0; ks < 2; ks++) {
            uint32_t af[2][4], bfr[4][4];
#pragma unroll
            for (int mt = 0; mt < 2; mt++)
                ldsm4(af[mt], aBase + (uint32_t)(((arow + mt * 16) * LDSR + ks * 16 + akof) * 2));
#pragma unroll
            for (int p = 0; p < 4; p++)
                ldsm4(bfr[p], bBase + (uint32_t)(((brow + p * 16) * LDSR + ks * 16 + bkof) * 2));
#pragma unroll
            for (int mt = 0; mt < 2; mt++)
#pragma unroll
                for (int nt = 0; nt < 8; nt++)
                    mma_f16(acc[mt][nt], af[mt], &bfr[nt >> 1][(nt & 1) * 2]);
        }
        buf = (buf + 1 >= 3) ? 0 : buf + 1;
    }

    const int mrow = row0 + wm * 32;
    const int ncol = col0 + wn * 64;
    const int r4 = lid >> 2, c2 = (lid & 3) * 2;
#pragma unroll
    for (int mt = 0; mt < 2; mt++) {
#pragma unroll
        for (int half = 0; half < 2; half++) {
            const long r = mrow + mt * 16 + r4 + half * 8;
#pragma unroll
            for (int nt = 0; nt < 8; nt++) {
                const int c = ncol + nt * 8 + c2;
                float v0 = alpha * acc[mt][nt][half * 2 + 0] + (bias ? bias[c + 0] : 0.f);
                float v1 = alpha * acc[mt][nt][half * 2 + 1] + (bias ? bias[c + 1] : 0.f);
                if (HALF_OUT) {
                    __half2 hh; hh.x = __float2half(v0); hh.y = __float2half(v1);
                    *(__half2*)&Ch[cOff + r * N + c] = hh;
                } else {
                    float2 o; o.x = v0; o.y = v1;
                    *(float2*)&C[cOff + r * N + c] = o;
                }
            }
        }
    }
}

// ---------------- fused flash attention ----------------
// Per CTA: q-tile 128 rows of batch b. Loop kv tiles of 64.
// agg[b, n, :] = sum_m [ exp(s_nm - M_n - ga*dist_nm) * notmask_m * v_m ] / sum_m exp(s_nm - M_n)
// Q smem [128][256], K tile [64][256], V tile (from vt) [256 d][64 kv], double-buffered.
#define QSTR 528       // Q/K smem row stride in BYTES (264 halves)
#define VSTR 144       // V smem row stride in BYTES (72 halves)
#define FA_QS   0
#define FA_KS0  67584
#define FA_KS1  101376
#define FA_VS0  135168
#define FA_VS1  172032
#define FA_META 208896
#define FA_SMEM 210944

__global__ void __launch_bounds__(256) flash_attn(
    const __half* __restrict__ q16, const __half* __restrict__ k16,
    const __half* __restrict__ vt,  const float* __restrict__ coords,
    const int* __restrict__ mask,   const float* __restrict__ gamma,
    __half* __restrict__ gg)
{
    extern __shared__ char sm[];
    const int b = blockIdx.y;
    const int q0 = blockIdx.x * 128;
    const int tid = threadIdx.x, wid = tid >> 5, lid = tid & 31;

    const uint32_t S = smem_u32(sm);
    const uint32_t Qs = S + FA_QS;
    const uint32_t KsB[2] = {S + FA_KS0, S + FA_KS1};
    const uint32_t VsB[2] = {S + FA_VS0, S + FA_VS1};
    float4* meta = (float4*)(sm + FA_META);   // [2][64] : x, y, sq, notmask

    // ---- issue Q + KV0 (group 0), KV1 (group 1) ----
    {
        const int row = tid >> 1, h = tid & 1;
        const __half* src = q16 + (long)(b * NTOK + q0 + row) * DD + h * 128;
        const uint32_t dst = Qs + row * QSTR + h * 256;
#pragma unroll
        for (int i = 0; i < 16; i++) cp16(dst + i * 16, src + i * 8);
    }
    auto issueKV = [&](int t, int bufi) {
        const int kv0 = t * 64;
        {
            const int row = tid >> 2, q4 = tid & 3;
            const __half* src = k16 + (long)(b * NTOK + kv0 + row) * DD + q4 * 64;
            const uint32_t dst = KsB[bufi] + row * QSTR + q4 * 128;
#pragma unroll
            for (int i = 0; i < 8; i++) cp16(dst + i * 16, src + i * 8);
        }
        {
            const __half* src = vt + ((long)b * DD + tid) * NTOK + kv0;
            const uint32_t dst = VsB[bufi] + tid * VSTR;
#pragma unroll
            for (int i = 0; i < 8; i++) cp16(dst + i * 16, src + i * 8);
        }
    };
    auto metaStore = [&](int t, int bufi) {
        if (tid < 64) {
            const int idx = b * NTOK + t * 64 + tid;
            float2 xy = ((const float2*)coords)[idx];
            int mk = mask[idx];
            meta[bufi * 64 + tid] = make_float4(xy.x, xy.y, xy.x * xy.x + xy.y * xy.y,
                                                mk ? 0.f : 1.f);
        }
    };
    issueKV(0, 0); CP_COMMIT();
    issueKV(1, 1); CP_COMMIT();
    metaStore(0, 0);
    metaStore(1, 1);

    // per-thread row metadata (rows r and r+8 of warp tile)
    const int qrow = q0 + wid * 16 + (lid >> 2);
    const float ga = fabsf(gamma[0]);
    float2 c0v = ((const float2*)coords)[b * NTOK + qrow];
    float2 c1v = ((const float2*)coords)[b * NTOK + qrow + 8];
    const float xn0 = c0v.x, yn0 = c0v.y, sqn0 = c0v.x * c0v.x + c0v.y * c0v.y;
    const float xn1 = c1v.x, yn1 = c1v.y, sqn1 = c1v.x * c1v.x + c1v.y * c1v.y;

    float M0 = -INFINITY, M1 = -INFINITY, Z0 = 0.f, Z1 = 0.f;
    float o[32][4];
#pragma unroll
    for (int i = 0; i < 32; i++)
#pragma unroll
        for (int e = 0; e < 4; e++) o[i][e] = 0.f;

    const int arow = wid * 16 + (lid & 15);
    const int akof = (lid >> 4) * 8;
    const int nrw = (lid & 7) + (lid >> 4) * 8;
    const int nkof = ((lid >> 3) & 1) * 8;

    for (int t = 0; t < 32; ++t) {
        const int cur = t & 1;
        CP_WAIT1();
        __syncthreads();

        // ---- S = Q @ K^T (warp: 16 rows x 64 kv) ----
        float s[8][4];
#pragma unroll
        for (int j = 0; j < 8; j++)
#pragma unroll
            for (int e = 0; e < 4; e++) s[j][e] = 0.f;
        const uint32_t kb = KsB[cur];
#pragma unroll
        for (int ks = 0; ks < 16; ks++) {
            uint32_t af[4], bfr[4][4];
            ldsm4(af, Qs + (uint32_t)(arow * QSTR + (ks * 16 + akof) * 2));
#pragma unroll
            for (int p = 0; p < 4; p++)
                ldsm4(bfr[p], kb + (uint32_t)((p * 16 + nrw) * QSTR + (ks * 16 + nkof) * 2));
#pragma unroll
            for (int nt = 0; nt < 8; nt++)
                mma_f16(s[nt], af, &bfr[nt >> 1][(nt & 1) * 2]);
        }

        // ---- online softmax update ----
        float mx0 = -INFINITY, mx1 = -INFINITY;
#pragma unroll
        for (int j = 0; j < 8; j++) {
            s[j][0] *= 0.0625f; s[j][1] *= 0.0625f; s[j][2] *= 0.0625f; s[j][3] *= 0.0625f;
            mx0 = fmaxf(mx0, fmaxf(s[j][0], s[j][1]));
            mx1 = fmaxf(mx1, fmaxf(s[j][2], s[j][3]));
        }
        mx0 = fmaxf(mx0, __shfl_xor_sync(0xffffffffu, mx0, 1));
        mx0 = fmaxf(mx0, __shfl_xor_sync(0xffffffffu, mx0, 2));
        mx1 = fmaxf(mx1, __shfl_xor_sync(0xffffffffu, mx1, 1));
        mx1 = fmaxf(mx1, __shfl_xor_sync(0xffffffffu, mx1, 2));
        const float Mn0 = fmaxf(M0, mx0), Mn1 = fmaxf(M1, mx1);
        const float sc0 = __expf(M0 - Mn0), sc1 = __expf(M1 - Mn1);
        M0 = Mn0; M1 = Mn1;
        Z0 *= sc0; Z1 *= sc1;
#pragma unroll
        for (int nt = 0; nt < 32; nt++) {
            o[nt][0] *= sc0; o[nt][1] *= sc0; o[nt][2] *= sc1; o[nt][3] *= sc1;
        }

        // ---- P = exp(s - M - ga*dist) * notmask ; Z += exp(s - M) ----
        uint32_t pf[16];
        const float4* mt = meta + cur * 64;
#pragma unroll
        for (int j = 0; j < 8; j++) {
            const int cc = 8 * j + (lid & 3) * 2;
            float4 ma = mt[cc], mb = mt[cc + 1];
            float e00 = __expf(s[j][0] - Mn0), e01 = __expf(s[j][1] - Mn0);
            float e10 = __expf(s[j][2] - Mn1), e11 = __expf(s[j][3] - Mn1);
            Z0 += e00 + e01; Z1 += e10 + e11;
            float d2a0 = fmaxf(sqn0 + ma.z - 2.f * (xn0 * ma.x + yn0 * ma.y), 0.f);
            float d2b0 = fmaxf(sqn0 + mb.z - 2.f * (xn0 * mb.x + yn0 * mb.y), 0.f);
            float d2a1 = fmaxf(sqn1 + ma.z - 2.f * (xn1 * ma.x + yn1 * ma.y), 0.f);
            float d2b1 = fmaxf(sqn1 + mb.z - 2.f * (xn1 * mb.x + yn1 * mb.y), 0.f);
            float n00 = e00 * __expf(-ga * sqrtf(d2a0)) * ma.w;
            float n01 = e01 * __expf(-ga * sqrtf(d2b0)) * mb.w;
            float n10 = e10 * __expf(-ga * sqrtf(d2a1)) * ma.w;
            float n11 = e11 * __expf(-ga * sqrtf(d2b1)) * mb.w;
            __half2 p0; p0.x = __float2half(n00); p0.y = __float2half(n01);
            __half2 p1; p1.x = __float2half(n10); p1.y = __float2half(n11);
            pf[2 * j + 0] = *(uint32_t*)&p0;
            pf[2 * j + 1] = *(uint32_t*)&p1;
        }

        // ---- O += P @ V ----
        const uint32_t vb = VsB[cur];
#pragma unroll
        for (int ks = 0; ks < 4; ks++) {
            uint32_t a[4] = {pf[4 * ks + 0], pf[4 * ks + 1], pf[4 * ks + 2], pf[4 * ks + 3]};
#pragma unroll
            for (int p = 0; p < 16; p++) {
                uint32_t bf4[4];
                ldsm4(bf4, vb + (uint32_t)((p * 16 + nrw) * VSTR + (ks * 16 + nkof) * 2));
                mma_f16(o[2 * p + 0], a, &bf4[0]);
                mma_f16(o[2 * p + 1], a, &bf4[2]);
            }
        }

        __syncthreads();
        if (t + 2 < 32) {
            issueKV(t + 2, cur); CP_COMMIT();
            metaStore(t + 2, cur);
        } else {
            CP_COMMIT();
        }
    }

    // ---- epilogue: normalize by Z, write fp16 agg ----
    Z0 += __shfl_xor_sync(0xffffffffu, Z0, 1);
    Z0 += __shfl_xor_sync(0xffffffffu, Z0, 2);
    Z1 += __shfl_xor_sync(0xffffffffu, Z1, 1);
    Z1 += __shfl_xor_sync(0xffffffffu, Z1, 2);
    const float i0 = 1.f / Z0, i1 = 1.f / Z1;
    const long r0 = (long)(b * NTOK + qrow) * DD;
    const long r1 = (long)(b * NTOK + qrow + 8) * DD;
#pragma unroll
    for (int nt = 0; nt < 32; nt++) {
        const int c = nt * 8 + (lid & 3) * 2;
        __half2 h0; h0.x = __float2half(o[nt][0] * i0); h0.y = __float2half(o[nt][1] * i0);
        __half2 h1; h1.x = __float2half(o[nt][2] * i1); h1.y = __float2half(o[nt][3] * i1);
        *(__half2*)&gg[r0 + c] = h0;
        *(__half2*)&gg[r1 + c] = h1;
    }
}

// ---------------- elementwise fp32 -> fp16 convert ----------------
__global__ void convert_half(const float* __restrict__ X, __half* __restrict__ Y, int n4)
{
    int i = blockIdx.x * blockDim.x + threadIdx.x;
    if (i >= n4) return;
    float4 v = ((const float4*)X)[i];
    __half2 a; a.x = __float2half(v.x); a.y = __float2half(v.y);
    __half2 b; b.x = __float2half(v.z); b.y = __float2half(v.w);
    ((__half2*)Y)[i * 2 + 0] = a;
    ((__half2*)Y)[i * 2 + 1] = b;
}

// ---------------- batched transpose + convert ----------------
__global__ void transpose_half(const float* __restrict__ X, __half* __restrict__ Tt,
                               int R, int Cc)
{
    __shared__ float t[32][33];
    const long boff = (long)blockIdx.z * R * Cc;
    X += boff; Tt += boff;
    const int c0 = blockIdx.x * 32, r0 = blockIdx.y * 32;
    for (int i = threadIdx.y; i < 32; i += 8)
        t[i][threadIdx.x] = X[(long)(r0 + i) * Cc + c0 + threadIdx.x];
    __syncthreads();
    for (int i = threadIdx.y; i < 32; i += 8) {
        long o = (long)(c0 + i) * R + r0 + threadIdx.x;
        Tt[o] = __float2half(t[threadIdx.x][i]);
    }
}

// ---------------- block reductions ----------------
__device__ __forceinline__ float blk_sum(float v) {
    __shared__ float sh[33];
    int lane = threadIdx.x & 31, w = threadIdx.x >> 5;
#pragma unroll
    for (int o = 16; o; o >>= 1) v += __shfl_xor_sync(0xffffffffu, v, o);
    __syncthreads();
    if (lane == 0) sh[w] = v;
    __syncthreads();
    if (threadIdx.x == 0) {
        float s = 0.f; int nw = (blockDim.x + 31) >> 5;
        for (int i = 0; i < nw; i++) s += sh[i];
        sh[32] = s;
    }
    __syncthreads();
    return sh[32];
}

// ---------------- LayerNorm + ReLU ----------------
__global__ void ln_relu_kernel(float* __restrict__ X, const float* __restrict__ g,
                               const float* __restrict__ beta, int D,
                               __half* __restrict__ h16)
{
    const long row = blockIdx.x;
    const int t = threadIdx.x;
    float v = X[row * D + t];
    float mu = blk_sum(v) * (1.f / D);
    float d = v - mu;
    float var = blk_sum(d * d) * (1.f / D);
    float r = d * rsqrtf(var + 1e-5f) * g[t] + beta[t];
    r = fmaxf(r, 0.f);
    if (h16) h16[row * D + t] = __float2half(r);
    else     X[row * D + t] = r;
}

// ---------------- masked mean pool: two stage ----------------
__global__ void pool_part(const float* __restrict__ out, const int* __restrict__ mask,
                          float* __restrict__ pp, float* __restrict__ pc)
{
    const int b = blockIdx.y, ch = blockIdx.x;
    const int t = threadIdx.x;  // 128
    const float* base = out + ((long)b * NTOK + ch * 128) * BDIM;
    const int* mb = mask + b * NTOK + ch * 128;
    float s = 0.f; int cnt = 0;
#pragma unroll 4
    for (int n = 0; n < 128; n++) {
        int mk = mb[n];
        float val = base[(long)n * BDIM + t];
        if (!mk) { s += val; cnt++; }
    }
    pp[(b * 16 + ch) * BDIM + t] = s;
    if (t == 0) pc[b * 16 + ch] = (float)cnt;
}
__global__ void pool_final(const float* __restrict__ pp, const float* __restrict__ pc,
                           float* __restrict__ pooled)
{
    const int b = blockIdx.x, t = threadIdx.x;  // 128
    float s = 0.f, c = 0.f;
#pragma unroll
    for (int ch = 0; ch < 16; ch++) {
        s += pp[(b * 16 + ch) * BDIM + t];
        c += pc[b * 16 + ch];
    }
    pooled[b * BDIM + t] = s / fmaxf(c, 1e-9f);
}

// ---------------- head MLP ----------------
__global__ void head_kernel(const float* __restrict__ pooled,
                            const float* __restrict__ c1w, const float* __restrict__ c1b,
                            const float* __restrict__ c2w, const float* __restrict__ c2b,
                            float* __restrict__ logits)
{
    const int b = blockIdx.x;
    const int t = threadIdx.x;  // 64
    __shared__ float sp[BDIM];
    __shared__ float hid[64];
    for (int i = t; i < BDIM; i += 64) sp[i] = pooled[b * BDIM + i];
    __syncthreads();
    float s = c1b[t];
    for (int i = 0; i < BDIM; i++) s += sp[i] * c1w[i * 64 + t];
    hid[t] = fmaxf(s, 0.f);
    __syncthreads();
    if (t < NCLS) {
        float l = c2b[t];
        for (int j = 0; j < 64; j++) l += hid[j] * c2w[j * NCLS + t];
        logits[b * NCLS + t] = l;
    }
}

// ---------------- launch ----------------
extern "C" void kernel_launch(void* const* d_in, const int* in_sizes, int n_in,
                              void* d_out, int out_size)
{
    const float* local_feat = (const float*)d_in[0];
    const float* coords     = (const float*)d_in[1];
    const int*   mask       = (const int*)d_in[2];
    const float* enc_w      = (const float*)d_in[3];
    const float* enc_b      = (const float*)d_in[4];
    const float* enc_g      = (const float*)d_in[5];
    const float* enc_beta   = (const float*)d_in[6];
    const float* gamma      = (const float*)d_in[7];
    const float* wq         = (const float*)d_in[8];
    const float* bq         = (const float*)d_in[9];
    const float* wk         = (const float*)d_in[10];
    const float* bk         = (const float*)d_in[11];
    const float* wv         = (const float*)d_in[12];
    const float* bv         = (const float*)d_in[13];
    const float* bn_w       = (const float*)d_in[14];
    const float* bn_b       = (const float*)d_in[15];
    const float* bn_g       = (const float*)d_in[16];
    const float* bn_beta    = (const float*)d_in[17];
    const float* c1_w       = (const float*)d_in[18];
    const float* c1_b       = (const float*)d_in[19];
    const float* c2_w       = (const float*)d_in[20];
    const float* c2_b       = (const float*)d_in[21];

    float *hf, *v, *o, *pp, *pc;
    __half *lf, *h16, *q16, *k16, *vt, *gg, *ent, *wqt, *wkt, *wvt, *bnt;
    cudaGetSymbolAddress((void**)&lf,  g_lf);
    cudaGetSymbolAddress((void**)&hf,  g_hf);
    cudaGetSymbolAddress((void**)&h16, g_h16);
    cudaGetSymbolAddress((void**)&q16, g_q16);
    cudaGetSymbolAddress((void**)&k16, g_k16);
    cudaGetSymbolAddress((void**)&v,   g_v);
    cudaGetSymbolAddress((void**)&vt,  g_vt);
    cudaGetSymbolAddress((void**)&gg,  g_gg);
    cudaGetSymbolAddress((void**)&o,   g_o);
    cudaGetSymbolAddress((void**)&ent, g_ent);
    cudaGetSymbolAddress((void**)&wqt, g_wqt);
    cudaGetSymbolAddress((void**)&wkt, g_wkt);
    cudaGetSymbolAddress((void**)&wvt, g_wvt);
    cudaGetSymbolAddress((void**)&bnt, g_bnt);
    cudaGetSymbolAddress((void**)&pp,  g_pp);
    cudaGetSymbolAddress((void**)&pc,  g_pc);

    cudaFuncSetAttribute(gemm_mma<false>, cudaFuncAttributeMaxDynamicSharedMemorySize, GEMM_SMEM);
    cudaFuncSetAttribute(gemm_mma<true>,  cudaFuncAttributeMaxDynamicSharedMemorySize, GEMM_SMEM);
    cudaFuncSetAttribute(flash_attn,      cudaFuncAttributeMaxDynamicSharedMemorySize, FA_SMEM);

    // 0) input conversions
    convert_half<<<(ROWS * CLIPD / 4 + 255) / 256, 256>>>(local_feat, lf, ROWS * CLIPD / 4);
    transpose_half<<<dim3(DD / 32, CLIPD / 32, 1), dim3(32, 8)>>>(enc_w, ent, CLIPD, DD);
    transpose_half<<<dim3(DD / 32, DD / 32, 1),    dim3(32, 8)>>>(wq, wqt, DD, DD);
    transpose_half<<<dim3(DD / 32, DD / 32, 1),    dim3(32, 8)>>>(wk, wkt, DD, DD);
    transpose_half<<<dim3(DD / 32, DD / 32, 1),    dim3(32, 8)>>>(wv, wvt, DD, DD);
    transpose_half<<<dim3(BDIM / 32, DD / 32, 1),  dim3(32, 8)>>>(bn_w, bnt, DD, BDIM);

    // 1) enc GEMM + LN
    gemm_mma<false><<<dim3(DD / 128, ROWS / 128, 1), 256, GEMM_SMEM>>>(
        lf, ent, hf, nullptr, DD, CLIPD, 0, 0, 0, 1.f, enc_b);
    ln_relu_kernel<<<ROWS, DD>>>(hf, enc_g, enc_beta, DD, h16);

    // 2) q, k, v
    gemm_mma<true><<<dim3(DD / 128, ROWS / 128, 1), 256, GEMM_SMEM>>>(
        h16, wqt, nullptr, q16, DD, DD, 0, 0, 0, 1.f, bq);
    gemm_mma<true><<<dim3(DD / 128, ROWS / 128, 1), 256, GEMM_SMEM>>>(
        h16, wkt, nullptr, k16, DD, DD, 0, 0, 0, 1.f, bk);
    gemm_mma<false><<<dim3(DD / 128, ROWS / 128, 1), 256, GEMM_SMEM>>>(
        h16, wvt, v, nullptr, DD, DD, 0, 0, 0, 1.f, bv);
    transpose_half<<<dim3(DD / 32, NTOK / 32, BB), dim3(32, 8)>>>(v, vt, NTOK, DD);

    // 3) fused attention -> agg fp16
    flash_attn<<<dim3(NTOK / 128, BB), 256, FA_SMEM>>>(
        q16, k16, vt, coords, mask, gamma, gg);

    // 4) bn GEMM + LN
    gemm_mma<false><<<dim3(BDIM / 128, ROWS / 128, 1), 256, GEMM_SMEM>>>(
        gg, bnt, o, nullptr, BDIM, DD, 0, 0, 0, 1.f, bn_b);
    ln_relu_kernel<<<ROWS, BDIM>>>(o, bn_g, bn_beta, BDIM, nullptr);

    // 5) masked mean pool -> d_out[80 : 80+1024]
    float* out_f = (float*)d_out;
    pool_part<<<dim3(16, BB), 128>>>(o, mask, pp, pc);
    pool_final<<<BB, 128>>>(pp, pc, out_f + BB * NCLS);

    // 6) MLP head -> d_out[0 : 80]
    head_kernel<<<BB, 64>>>(out_f + BB * NCLS, c1_w, c1_b, c2_w, c2_b, out_f);
}

// round 9
// speedup vs baseline: 3.6492x; 1.0019x over previous
#include <cuda_runtime.h>
#include <cuda_fp16.h>
#include <math.h>
#include <stdint.h>

#define BB 8
#define NTOK 2048
#define CLIPD 512
#define DD 256
#define BDIM 128
#define NCLS 10
#define ROWS (BB * NTOK)   // 16384

// ---------------- scratch (no cudaMalloc allowed) ----------------
__device__ __half g_lf [ROWS * CLIPD];
__device__ float  g_hf [ROWS * DD];            // enc out fp32
__device__ __half g_h16[ROWS * DD];
__device__ __half g_q16[ROWS * DD];
__device__ __half g_k16[ROWS * DD];
__device__ float  g_v  [ROWS * DD];
__device__ __half g_vt [ROWS * DD];            // v transposed [b][d][m]
__device__ __half g_gg [ROWS * DD];            // agg fp16
__device__ float  g_o  [ROWS * BDIM];
__device__ __half g_ent[DD * CLIPD];           // enc_w^T
__device__ __half g_wqt[DD * DD];
__device__ __half g_wkt[DD * DD];
__device__ __half g_wvt[DD * DD];
__device__ __half g_bnt[BDIM * DD];
__device__ float  g_pp [BB * 16 * BDIM];       // pool partials
__device__ float  g_pc [BB * 16];

// ---------------- mma / ldmatrix / cp.async helpers ----------------
__device__ __forceinline__ uint32_t smem_u32(const void* p) {
    uint32_t a;
    asm("{ .reg .u64 t; cvta.to.shared.u64 t, %1; cvt.u32.u64 %0, t; }" : "=r"(a) : "l"(p));
    return a;
}
__device__ __forceinline__ void ldsm4(uint32_t* r, uint32_t addr) {
    asm volatile("ldmatrix.sync.aligned.m8n8.x4.shared.b16 {%0,%1,%2,%3}, [%4];"
                 : "=r"(r[0]), "=r"(r[1]), "=r"(r[2]), "=r"(r[3]) : "r"(addr));
}
__device__ __forceinline__ void mma_f16(float* d, const uint32_t* a, const uint32_t* b) {
    asm volatile(
        "mma.sync.aligned.m16n8k16.row.col.f32.f16.f16.f32 "
        "{%0,%1,%2,%3}, {%4,%5,%6,%7}, {%8,%9}, {%0,%1,%2,%3};"
        : "+f"(d[0]), "+f"(d[1]), "+f"(d[2]), "+f"(d[3])
        : "r"(a[0]), "r"(a[1]), "r"(a[2]), "r"(a[3]), "r"(b[0]), "r"(b[1]));
}
__device__ __forceinline__ void cp16(uint32_t dst, const void* src) {
    asm volatile("cp.async.cg.shared.global [%0], [%1], 16;" :: "r"(dst), "l"(src));
}
#define CP_COMMIT() asm volatile("cp.async.commit_group;" ::: "memory")
#define CP_WAIT1()  asm volatile("cp.async.wait_group 1;" ::: "memory")

// ---------------- fp16 HMMA GEMM, 3-stage cp.async pipeline ----------------
#define LDSR 40
#define STAGE_B (128 * LDSR * 2)
#define GEMM_SMEM (6 * STAGE_B)

template <bool HALF_OUT>
__global__ void __launch_bounds__(256) gemm_mma(
    const __half* __restrict__ A, const __half* __restrict__ B,
    float* __restrict__ C, __half* __restrict__ Ch,
    int N, int K, long sA, long sB, long sC,
    float alpha, const float* __restrict__ bias)
{
    extern __shared__ char smem[];
    const int bz = blockIdx.z;
    A += bz * sA; B += bz * sB;
    const long cOff = (long)bz * sC;

    const int tid = threadIdx.x;
    const int wid = tid >> 5, lid = tid & 31;
    const int wm = wid & 3, wn = wid >> 2;
    const int row0 = blockIdx.y * 128;
    const int col0 = blockIdx.x * 128;
    const int T = K / 32;

    const int lr = tid >> 1;
    const int lk = (tid & 1) * 16;

    const uint32_t sBase = smem_u32(smem);
    const uint32_t aS = sBase;
    const uint32_t bS = sBase + 3 * STAGE_B;
    const uint32_t dstOff = (uint32_t)(lr * LDSR + lk) * 2;

    const __half* ag = A + (long)(row0 + lr) * K + lk;
    const __half* bg = B + (long)(col0 + lr) * K + lk;

    auto issue = [&](int it, int buf) {
        const __half* ap = ag + it * 32;
        const __half* bp = bg + it * 32;
        const uint32_t ad = aS + buf * STAGE_B + dstOff;
        const uint32_t bd = bS + buf * STAGE_B + dstOff;
        cp16(ad, ap); cp16(ad + 16, ap + 8);
        cp16(bd, bp); cp16(bd + 16, bp + 8);
    };

    float acc[2][8][4];
#pragma unroll
    for (int i = 0; i < 2; i++)
#pragma unroll
        for (int j = 0; j < 8; j++)
#pragma unroll
            for (int e = 0; e < 4; e++) acc[i][j][e] = 0.f;

    issue(0, 0); CP_COMMIT();
    issue(1, 1); CP_COMMIT();

    const int arow = wm * 32 + (lid & 15);
    const int akof = (lid >> 4) * 8;
    const int brow = wn * 64 + (lid & 7) + (lid >> 4) * 8;
    const int bkof = ((lid >> 3) & 1) * 8;

    int buf = 0;
    for (int it = 0; it < T; ++it) {
        CP_WAIT1();
        __syncthreads();
        if (it + 2 < T) issue(it + 2, (buf + 2 >= 3) ? buf - 1 : buf + 2);
        CP_COMMIT();

        const uint32_t aBase = aS + buf * STAGE_B;
        const uint32_t bBase = bS + buf * STAGE_B;
#pragma unroll
        for (int ks = 0; ks < 2; ks++) {
            uint32_t af[2][4], bfr[4][4];
#pragma unroll
            for (int mt = 0; mt < 2; mt++)
                ldsm4(af[mt], aBase + (uint32_t)(((arow + mt * 16) * LDSR + ks * 16 + akof) * 2));
#pragma unroll
            for (int p = 0; p < 4; p++)
                ldsm4(bfr[p], bBase + (uint32_t)(((brow + p * 16) * LDSR + ks * 16 + bkof) * 2));
#pragma unroll
            for (int mt = 0; mt < 2; mt++)
#pragma unroll
                for (int nt = 0; nt < 8; nt++)
                    mma_f16(acc[mt][nt], af[mt], &bfr[nt >> 1][(nt & 1) * 2]);
        }
        buf = (buf + 1 >= 3) ? 0 : buf + 1;
    }

    const int mrow = row0 + wm * 32;
    const int ncol = col0 + wn * 64;
    const int r4 = lid >> 2, c2 = (lid & 3) * 2;
#pragma unroll
    for (int mt = 0; mt < 2; mt++) {
#pragma unroll
        for (int half = 0; half < 2; half++) {
            const long r = mrow + mt * 16 + r4 + half * 8;
#pragma unroll
            for (int nt = 0; nt < 8; nt++) {
                const int c = ncol + nt * 8 + c2;
                float v0 = alpha * acc[mt][nt][half * 2 + 0] + (bias ? bias[c + 0] : 0.f);
                float v1 = alpha * acc[mt][nt][half * 2 + 1] + (bias ? bias[c + 1] : 0.f);
                if (HALF_OUT) {
                    __half2 hh; hh.x = __float2half(v0); hh.y = __float2half(v1);
                    *(__half2*)&Ch[cOff + r * N + c] = hh;
                } else {
                    float2 o; o.x = v0; o.y = v1;
                    *(float2*)&C[cOff + r * N + c] = o;
                }
            }
        }
    }
}

// ---------------- fused flash attention ----------------
// Per CTA: q-tile 128 rows of batch b. Loop kv tiles of 64.
// agg[b, n, :] = sum_m [ exp(s_nm - M_n - ga*dist_nm) * notmask_m * v_m ] / sum_m exp(s_nm - M_n)
// Q smem [128][256], K tile [64][256], V tile (from vt) [256 d][64 kv], double-buffered.
#define QSTR 528       // Q/K smem row stride in BYTES (264 halves)
#define VSTR 144       // V smem row stride in BYTES (72 halves)
#define FA_QS   0
#define FA_KS0  67584
#define FA_KS1  101376
#define FA_VS0  135168
#define FA_VS1  172032
#define FA_META 208896
#define FA_SMEM 210944

__global__ void __launch_bounds__(256) flash_attn(
    const __half* __restrict__ q16, const __half* __restrict__ k16,
    const __half* __restrict__ vt,  const float* __restrict__ coords,
    const int* __restrict__ mask,   const float* __restrict__ gamma,
    __half* __restrict__ gg)
{
    extern __shared__ char sm[];
    const int b = blockIdx.y;
    const int q0 = blockIdx.x * 128;
    const int tid = threadIdx.x, wid = tid >> 5, lid = tid & 31;

    const uint32_t S = smem_u32(sm);
    const uint32_t Qs = S + FA_QS;
    const uint32_t KsB[2] = {S + FA_KS0, S + FA_KS1};
    const uint32_t VsB[2] = {S + FA_VS0, S + FA_VS1};
    float4* meta = (float4*)(sm + FA_META);   // [2][64] : x, y, sq, notmask

    // ---- issue Q + KV0 (group 0), KV1 (group 1) ----
    {
        const int row = tid >> 1, h = tid & 1;
        const __half* src = q16 + (long)(b * NTOK + q0 + row) * DD + h * 128;
        const uint32_t dst = Qs + row * QSTR + h * 256;
#pragma unroll
        for (int i = 0; i < 16; i++) cp16(dst + i * 16, src + i * 8);
    }
    auto issueKV = [&](int t, int bufi) {
        const int kv0 = t * 64;
        {
            const int row = tid >> 2, q4 = tid & 3;
            const __half* src = k16 + (long)(b * NTOK + kv0 + row) * DD + q4 * 64;
            const uint32_t dst = KsB[bufi] + row * QSTR + q4 * 128;
#pragma unroll
            for (int i = 0; i < 8; i++) cp16(dst + i * 16, src + i * 8);
        }
        {
            const __half* src = vt + ((long)b * DD + tid) * NTOK + kv0;
            const uint32_t dst = VsB[bufi] + tid * VSTR;
#pragma unroll
            for (int i = 0; i < 8; i++) cp16(dst + i * 16, src + i * 8);
        }
    };
    auto metaStore = [&](int t, int bufi) {
        if (tid < 64) {
            const int idx = b * NTOK + t * 64 + tid;
            float2 xy = ((const float2*)coords)[idx];
            int mk = mask[idx];
            meta[bufi * 64 + tid] = make_float4(xy.x, xy.y, xy.x * xy.x + xy.y * xy.y,
                                                mk ? 0.f : 1.f);
        }
    };
    issueKV(0, 0); CP_COMMIT();
    issueKV(1, 1); CP_COMMIT();
    metaStore(0, 0);
    metaStore(1, 1);

    // per-thread row metadata (rows r and r+8 of warp tile)
    const int qrow = q0 + wid * 16 + (lid >> 2);
    const float ga = fabsf(gamma[0]);
    float2 c0v = ((const float2*)coords)[b * NTOK + qrow];
    float2 c1v = ((const float2*)coords)[b * NTOK + qrow + 8];
    const float xn0 = c0v.x, yn0 = c0v.y, sqn0 = c0v.x * c0v.x + c0v.y * c0v.y;
    const float xn1 = c1v.x, yn1 = c1v.y, sqn1 = c1v.x * c1v.x + c1v.y * c1v.y;

    float M0 = -INFINITY, M1 = -INFINITY, Z0 = 0.f, Z1 = 0.f;
    float o[32][4];
#pragma unroll
    for (int i = 0; i < 32; i++)
#pragma unroll
        for (int e = 0; e < 4; e++) o[i][e] = 0.f;

    const int arow = wid * 16 + (lid & 15);
    const int akof = (lid >> 4) * 8;
    const int nrw = (lid & 7) + (lid >> 4) * 8;
    const int nkof = ((lid >> 3) & 1) * 8;

    for (int t = 0; t < 32; ++t) {
        const int cur = t & 1;
        CP_WAIT1();
        __syncthreads();

        // ---- S = Q @ K^T (warp: 16 rows x 64 kv) ----
        float s[8][4];
#pragma unroll
        for (int j = 0; j < 8; j++)
#pragma unroll
            for (int e = 0; e < 4; e++) s[j][e] = 0.f;
        const uint32_t kb = KsB[cur];
#pragma unroll
        for (int ks = 0; ks < 16; ks++) {
            uint32_t af[4], bfr[4][4];
            ldsm4(af, Qs + (uint32_t)(arow * QSTR + (ks * 16 + akof) * 2));
#pragma unroll
            for (int p = 0; p < 4; p++)
                ldsm4(bfr[p], kb + (uint32_t)((p * 16 + nrw) * QSTR + (ks * 16 + nkof) * 2));
#pragma unroll
            for (int nt = 0; nt < 8; nt++)
                mma_f16(s[nt], af, &bfr[nt >> 1][(nt & 1) * 2]);
        }

        // ---- online softmax update ----
        float mx0 = -INFINITY, mx1 = -INFINITY;
#pragma unroll
        for (int j = 0; j < 8; j++) {
            s[j][0] *= 0.0625f; s[j][1] *= 0.0625f; s[j][2] *= 0.0625f; s[j][3] *= 0.0625f;
            mx0 = fmaxf(mx0, fmaxf(s[j][0], s[j][1]));
            mx1 = fmaxf(mx1, fmaxf(s[j][2], s[j][3]));
        }
        mx0 = fmaxf(mx0, __shfl_xor_sync(0xffffffffu, mx0, 1));
        mx0 = fmaxf(mx0, __shfl_xor_sync(0xffffffffu, mx0, 2));
        mx1 = fmaxf(mx1, __shfl_xor_sync(0xffffffffu, mx1, 1));
        mx1 = fmaxf(mx1, __shfl_xor_sync(0xffffffffu, mx1, 2));
        const float Mn0 = fmaxf(M0, mx0), Mn1 = fmaxf(M1, mx1);
        const float sc0 = __expf(M0 - Mn0), sc1 = __expf(M1 - Mn1);
        M0 = Mn0; M1 = Mn1;
        Z0 *= sc0; Z1 *= sc1;
#pragma unroll
        for (int nt = 0; nt < 32; nt++) {
            o[nt][0] *= sc0; o[nt][1] *= sc0; o[nt][2] *= sc1; o[nt][3] *= sc1;
        }

        // ---- P = exp(s - M - ga*dist) * notmask ; Z += exp(s - M) ----
        uint32_t pf[16];
        const float4* mt = meta + cur * 64;
#pragma unroll
        for (int j = 0; j < 8; j++) {
            const int cc = 8 * j + (lid & 3) * 2;
            float4 ma = mt[cc], mb = mt[cc + 1];
            float e00 = __expf(s[j][0] - Mn0), e01 = __expf(s[j][1] - Mn0);
            float e10 = __expf(s[j][2] - Mn1), e11 = __expf(s[j][3] - Mn1);
            Z0 += e00 + e01; Z1 += e10 + e11;
            float d2a0 = fmaxf(sqn0 + ma.z - 2.f * (xn0 * ma.x + yn0 * ma.y), 0.f);
            float d2b0 = fmaxf(sqn0 + mb.z - 2.f * (xn0 * mb.x + yn0 * mb.y), 0.f);
            float d2a1 = fmaxf(sqn1 + ma.z - 2.f * (xn1 * ma.x + yn1 * ma.y), 0.f);
            float d2b1 = fmaxf(sqn1 + mb.z - 2.f * (xn1 * mb.x + yn1 * mb.y), 0.f);
            float n00 = e00 * __expf(-ga * sqrtf(d2a0)) * ma.w;
            float n01 = e01 * __expf(-ga * sqrtf(d2b0)) * mb.w;
            float n10 = e10 * __expf(-ga * sqrtf(d2a1)) * ma.w;
            float n11 = e11 * __expf(-ga * sqrtf(d2b1)) * mb.w;
            __half2 p0; p0.x = __float2half(n00); p0.y = __float2half(n01);
            __half2 p1; p1.x = __float2half(n10); p1.y = __float2half(n11);
            pf[2 * j + 0] = *(uint32_t*)&p0;
            pf[2 * j + 1] = *(uint32_t*)&p1;
        }

        // ---- O += P @ V ----
        const uint32_t vb = VsB[cur];
#pragma unroll
        for (int ks = 0; ks < 4; ks++) {
            uint32_t a[4] = {pf[4 * ks + 0], pf[4 * ks + 1], pf[4 * ks + 2], pf[4 * ks + 3]};
#pragma unroll
            for (int p = 0; p < 16; p++) {
                uint32_t bf4[4];
                ldsm4(bf4, vb + (uint32_t)((p * 16 + nrw) * VSTR + (ks * 16 + nkof) * 2));
                mma_f16(o[2 * p + 0], a, &bf4[0]);
                mma_f16(o[2 * p + 1], a, &bf4[2]);
            }
        }

        __syncthreads();
        if (t + 2 < 32) {
            issueKV(t + 2, cur); CP_COMMIT();
            metaStore(t + 2, cur);
        } else {
            CP_COMMIT();
        }
    }

    // ---- epilogue: normalize by Z, write fp16 agg ----
    Z0 += __shfl_xor_sync(0xffffffffu, Z0, 1);
    Z0 += __shfl_xor_sync(0xffffffffu, Z0, 2);
    Z1 += __shfl_xor_sync(0xffffffffu, Z1, 1);
    Z1 += __shfl_xor_sync(0xffffffffu, Z1, 2);
    const float i0 = 1.f / Z0, i1 = 1.f / Z1;
    const long r0 = (long)(b * NTOK + qrow) * DD;
    const long r1 = (long)(b * NTOK + qrow + 8) * DD;
#pragma unroll
    for (int nt = 0; nt < 32; nt++) {
        const int c = nt * 8 + (lid & 3) * 2;
        __half2 h0; h0.x = __float2half(o[nt][0] * i0); h0.y = __float2half(o[nt][1] * i0);
        __half2 h1; h1.x = __float2half(o[nt][2] * i1); h1.y = __float2half(o[nt][3] * i1);
        *(__half2*)&gg[r0 + c] = h0;
        *(__half2*)&gg[r1 + c] = h1;
    }
}

// ---------------- elementwise fp32 -> fp16 convert ----------------
__global__ void convert_half(const float* __restrict__ X, __half* __restrict__ Y, int n4)
{
    int i = blockIdx.x * blockDim.x + threadIdx.x;
    if (i >= n4) return;
    float4 v = ((const float4*)X)[i];
    __half2 a; a.x = __float2half(v.x); a.y = __float2half(v.y);
    __half2 b; b.x = __float2half(v.z); b.y = __float2half(v.w);
    ((__half2*)Y)[i * 2 + 0] = a;
    ((__half2*)Y)[i * 2 + 1] = b;
}

// ---------------- batched transpose + convert ----------------
__global__ void transpose_half(const float* __restrict__ X, __half* __restrict__ Tt,
                               int R, int Cc)
{
    __shared__ float t[32][33];
    const long boff = (long)blockIdx.z * R * Cc;
    X += boff; Tt += boff;
    const int c0 = blockIdx.x * 32, r0 = blockIdx.y * 32;
    for (int i = threadIdx.y; i < 32; i += 8)
        t[i][threadIdx.x] = X[(long)(r0 + i) * Cc + c0 + threadIdx.x];
    __syncthreads();
    for (int i = threadIdx.y; i < 32; i += 8) {
        long o = (long)(c0 + i) * R + r0 + threadIdx.x;
        Tt[o] = __float2half(t[threadIdx.x][i]);
    }
}

// ---------------- block reductions ----------------
__device__ __forceinline__ float blk_sum(float v) {
    __shared__ float sh[33];
    int lane = threadIdx.x & 31, w = threadIdx.x >> 5;
#pragma unroll
    for (int o = 16; o; o >>= 1) v += __shfl_xor_sync(0xffffffffu, v, o);
    __syncthreads();
    if (lane == 0) sh[w] = v;
    __syncthreads();
    if (threadIdx.x == 0) {
        float s = 0.f; int nw = (blockDim.x + 31) >> 5;
        for (int i = 0; i < nw; i++) s += sh[i];
        sh[32] = s;
    }
    __syncthreads();
    return sh[32];
}

// ---------------- LayerNorm + ReLU ----------------
__global__ void ln_relu_kernel(float* __restrict__ X, const float* __restrict__ g,
                               const float* __restrict__ beta, int D,
                               __half* __restrict__ h16)
{
    const long row = blockIdx.x;
    const int t = threadIdx.x;
    float v = X[row * D + t];
    float mu = blk_sum(v) * (1.f / D);
    float d = v - mu;
    float var = blk_sum(d * d) * (1.f / D);
    float r = d * rsqrtf(var + 1e-5f) * g[t] + beta[t];
    r = fmaxf(r, 0.f);
    if (h16) h16[row * D + t] = __float2half(r);
    else     X[row * D + t] = r;
}

// ---------------- masked mean pool: two stage ----------------
__global__ void pool_part(const float* __restrict__ out, const int* __restrict__ mask,
                          float* __restrict__ pp, float* __restrict__ pc)
{
    const int b = blockIdx.y, ch = blockIdx.x;
    const int t = threadIdx.x;  // 128
    const float* base = out + ((long)b * NTOK + ch * 128) * BDIM;
    const int* mb = mask + b * NTOK + ch * 128;
    float s = 0.f; int cnt = 0;
#pragma unroll 4
    for (int n = 0; n < 128; n++) {
        int mk = mb[n];
        float val = base[(long)n * BDIM + t];
        if (!mk) { s += val; cnt++; }
    }
    pp[(b * 16 + ch) * BDIM + t] = s;
    if (t == 0) pc[b * 16 + ch] = (float)cnt;
}
__global__ void pool_final(const float* __restrict__ pp, const float* __restrict__ pc,
                           float* __restrict__ pooled)
{
    const int b = blockIdx.x, t = threadIdx.x;  // 128
    float s = 0.f, c = 0.f;
#pragma unroll
    for (int ch = 0; ch < 16; ch++) {
        s += pp[(b * 16 + ch) * BDIM + t];
        c += pc[b * 16 + ch];
    }
    pooled[b * BDIM + t] = s / fmaxf(c, 1e-9f);
}

// ---------------- head MLP ----------------
__global__ void head_kernel(const float* __restrict__ pooled,
                            const float* __restrict__ c1w, const float* __restrict__ c1b,
                            const float* __restrict__ c2w, const float* __restrict__ c2b,
                            float* __restrict__ logits)
{
    const int b = blockIdx.x;
    const int t = threadIdx.x;  // 64
    __shared__ float sp[BDIM];
    __shared__ float hid[64];
    for (int i = t; i < BDIM; i += 64) sp[i] = pooled[b * BDIM + i];
    __syncthreads();
    float s = c1b[t];
    for (int i = 0; i < BDIM; i++) s += sp[i] * c1w[i * 64 + t];
    hid[t] = fmaxf(s, 0.f);
    __syncthreads();
    if (t < NCLS) {
        float l = c2b[t];
        for (int j = 0; j < 64; j++) l += hid[j] * c2w[j * NCLS + t];
        logits[b * NCLS + t] = l;
    }
}

// ---------------- launch ----------------
extern "C" void kernel_launch(void* const* d_in, const int* in_sizes, int n_in,
                              void* d_out, int out_size)
{
    const float* local_feat = (const float*)d_in[0];
    const float* coords     = (const float*)d_in[1];
    const int*   mask       = (const int*)d_in[2];
    const float* enc_w      = (const float*)d_in[3];
    const float* enc_b      = (const float*)d_in[4];
    const float* enc_g      = (const float*)d_in[5];
    const float* enc_beta   = (const float*)d_in[6];
    const float* gamma      = (const float*)d_in[7];
    const float* wq         = (const float*)d_in[8];
    const float* bq         = (const float*)d_in[9];
    const float* wk         = (const float*)d_in[10];
    const float* bk         = (const float*)d_in[11];
    const float* wv         = (const float*)d_in[12];
    const float* bv         = (const float*)d_in[13];
    const float* bn_w       = (const float*)d_in[14];
    const float* bn_b       = (const float*)d_in[15];
    const float* bn_g       = (const float*)d_in[16];
    const float* bn_beta    = (const float*)d_in[17];
    const float* c1_w       = (const float*)d_in[18];
    const float* c1_b       = (const float*)d_in[19];
    const float* c2_w       = (const float*)d_in[20];
    const float* c2_b       = (const float*)d_in[21];

    float *hf, *v, *o, *pp, *pc;
    __half *lf, *h16, *q16, *k16, *vt, *gg, *ent, *wqt, *wkt, *wvt, *bnt;
    cudaGetSymbolAddress((void**)&lf,  g_lf);
    cudaGetSymbolAddress((void**)&hf,  g_hf);
    cudaGetSymbolAddress((void**)&h16, g_h16);
    cudaGetSymbolAddress((void**)&q16, g_q16);
    cudaGetSymbolAddress((void**)&k16, g_k16);
    cudaGetSymbolAddress((void**)&v,   g_v);
    cudaGetSymbolAddress((void**)&vt,  g_vt);
    cudaGetSymbolAddress((void**)&gg,  g_gg);
    cudaGetSymbolAddress((void**)&o,   g_o);
    cudaGetSymbolAddress((void**)&ent, g_ent);
    cudaGetSymbolAddress((void**)&wqt, g_wqt);
    cudaGetSymbolAddress((void**)&wkt, g_wkt);
    cudaGetSymbolAddress((void**)&wvt, g_wvt);
    cudaGetSymbolAddress((void**)&bnt, g_bnt);
    cudaGetSymbolAddress((void**)&pp,  g_pp);
    cudaGetSymbolAddress((void**)&pc,  g_pc);

    cudaFuncSetAttribute(gemm_mma<false>, cudaFuncAttributeMaxDynamicSharedMemorySize, GEMM_SMEM);
    cudaFuncSetAttribute(gemm_mma<true>,  cudaFuncAttributeMaxDynamicSharedMemorySize, GEMM_SMEM);
    cudaFuncSetAttribute(flash_attn,      cudaFuncAttributeMaxDynamicSharedMemorySize, FA_SMEM);

    // 0) input conversions
    convert_half<<<(ROWS * CLIPD / 4 + 255) / 256, 256>>>(local_feat, lf, ROWS * CLIPD / 4);
    transpose_half<<<dim3(DD / 32, CLIPD / 32, 1), dim3(32, 8)>>>(enc_w, ent, CLIPD, DD);
    transpose_half<<<dim3(DD / 32, DD / 32, 1),    dim3(32, 8)>>>(wq, wqt, DD, DD);
    transpose_half<<<dim3(DD / 32, DD / 32, 1),    dim3(32, 8)>>>(wk, wkt, DD, DD);
    transpose_half<<<dim3(DD / 32, DD / 32, 1),    dim3(32, 8)>>>(wv, wvt, DD, DD);
    transpose_half<<<dim3(BDIM / 32, DD / 32, 1),  dim3(32, 8)>>>(bn_w, bnt, DD, BDIM);

    // 1) enc GEMM + LN
    gemm_mma<false><<<dim3(DD / 128, ROWS / 128, 1), 256, GEMM_SMEM>>>(
        lf, ent, hf, nullptr, DD, CLIPD, 0, 0, 0, 1.f, enc_b);
    ln_relu_kernel<<<ROWS, DD>>>(hf, enc_g, enc_beta, DD, h16);

    // 2) q, k, v
    gemm_mma<true><<<dim3(DD / 128, ROWS / 128, 1), 256, GEMM_SMEM>>>(
        h16, wqt, nullptr, q16, DD, DD, 0, 0, 0, 1.f, bq);
    gemm_mma<true><<<dim3(DD / 128, ROWS / 128, 1), 256, GEMM_SMEM>>>(
        h16, wkt, nullptr, k16, DD, DD, 0, 0, 0, 1.f, bk);
    gemm_mma<false><<<dim3(DD / 128, ROWS / 128, 1), 256, GEMM_SMEM>>>(
        h16, wvt, v, nullptr, DD, DD, 0, 0, 0, 1.f, bv);
    transpose_half<<<dim3(DD / 32, NTOK / 32, BB), dim3(32, 8)>>>(v, vt, NTOK, DD);

    // 3) fused attention -> agg fp16
    flash_attn<<<dim3(NTOK / 128, BB), 256, FA_SMEM>>>(
        q16, k16, vt, coords, mask, gamma, gg);

    // 4) bn GEMM + LN
    gemm_mma<false><<<dim3(BDIM / 128, ROWS / 128, 1), 256, GEMM_SMEM>>>(
        gg, bnt, o, nullptr, BDIM, DD, 0, 0, 0, 1.f, bn_b);
    ln_relu_kernel<<<ROWS, BDIM>>>(o, bn_g, bn_beta, BDIM, nullptr);

    // 5) masked mean pool -> d_out[80 : 80+1024]
    float* out_f = (float*)d_out;
    pool_part<<<dim3(16, BB), 128>>>(o, mask, pp, pc);
    pool_final<<<BB, 128>>>(pp, pc, out_f + BB * NCLS);

    // 6) MLP head -> d_out[0 : 80]
    head_kernel<<<BB, 64>>>(out_f + BB * NCLS, c1_w, c1_b, c2_w, c2_b, out_f);
}

// round 10
// speedup vs baseline: 3.9780x; 1.0901x over previous
#include <cuda_runtime.h>
#include <cuda_fp16.h>
#include <math.h>
#include <stdint.h>

#define BB 8
#define NTOK 2048
#define CLIPD 512
#define DD 256
#define BDIM 128
#define NCLS 10
#define ROWS (BB * NTOK)   // 16384

// ---------------- scratch (no cudaMalloc allowed) ----------------
__device__ __half g_lf [ROWS * CLIPD];
__device__ float  g_hf [ROWS * DD];            // enc out fp32
__device__ __half g_h16[ROWS * DD];
__device__ __half g_q16[ROWS * DD];
__device__ __half g_k16[ROWS * DD];
__device__ float  g_v  [ROWS * DD];
__device__ __half g_vt [ROWS * DD];            // v transposed [b][d][m]
__device__ __half g_ent[DD * CLIPD];           // enc_w^T
__device__ __half g_wqt[DD * DD];
__device__ __half g_wkt[DD * DD];
__device__ __half g_wvt[DD * DD];
__device__ __half g_bnt[BDIM * DD];            // bn_w^T [128][256]
__device__ float  g_pp [BB * 16 * BDIM];       // pool partials per (b, q-tile)

// ---------------- mma / ldmatrix / cp.async helpers ----------------
__device__ __forceinline__ uint32_t smem_u32(const void* p) {
    uint32_t a;
    asm("{ .reg .u64 t; cvta.to.shared.u64 t, %1; cvt.u32.u64 %0, t; }" : "=r"(a) : "l"(p));
    return a;
}
__device__ __forceinline__ void ldsm4(uint32_t* r, uint32_t addr) {
    asm volatile("ldmatrix.sync.aligned.m8n8.x4.shared.b16 {%0,%1,%2,%3}, [%4];"
                 : "=r"(r[0]), "=r"(r[1]), "=r"(r[2]), "=r"(r[3]) : "r"(addr));
}
__device__ __forceinline__ void mma_f16(float* d, const uint32_t* a, const uint32_t* b) {
    asm volatile(
        "mma.sync.aligned.m16n8k16.row.col.f32.f16.f16.f32 "
        "{%0,%1,%2,%3}, {%4,%5,%6,%7}, {%8,%9}, {%0,%1,%2,%3};"
        : "+f"(d[0]), "+f"(d[1]), "+f"(d[2]), "+f"(d[3])
        : "r"(a[0]), "r"(a[1]), "r"(a[2]), "r"(a[3]), "r"(b[0]), "r"(b[1]));
}
__device__ __forceinline__ void cp16(uint32_t dst, const void* src) {
    asm volatile("cp.async.cg.shared.global [%0], [%1], 16;" :: "r"(dst), "l"(src));
}
#define CP_COMMIT() asm volatile("cp.async.commit_group;" ::: "memory")
#define CP_WAIT1()  asm volatile("cp.async.wait_group 1;" ::: "memory")
#define CP_WAIT0()  asm volatile("cp.async.wait_group 0;" ::: "memory")

// ---------------- fp16 HMMA GEMM, 3-stage cp.async pipeline ----------------
#define LDSR 40
#define STAGE_B (128 * LDSR * 2)
#define GEMM_SMEM (6 * STAGE_B)

template <bool HALF_OUT>
__global__ void __launch_bounds__(256) gemm_mma(
    const __half* __restrict__ A, const __half* __restrict__ B,
    float* __restrict__ C, __half* __restrict__ Ch,
    int N, int K, long sA, long sB, long sC,
    float alpha, const float* __restrict__ bias)
{
    extern __shared__ char smem[];
    const int bz = blockIdx.z;
    A += bz * sA; B += bz * sB;
    const long cOff = (long)bz * sC;

    const int tid = threadIdx.x;
    const int wid = tid >> 5, lid = tid & 31;
    const int wm = wid & 3, wn = wid >> 2;
    const int row0 = blockIdx.y * 128;
    const int col0 = blockIdx.x * 128;
    const int T = K / 32;

    const int lr = tid >> 1;
    const int lk = (tid & 1) * 16;

    const uint32_t sBase = smem_u32(smem);
    const uint32_t aS = sBase;
    const uint32_t bS = sBase + 3 * STAGE_B;
    const uint32_t dstOff = (uint32_t)(lr * LDSR + lk) * 2;

    const __half* ag = A + (long)(row0 + lr) * K + lk;
    const __half* bg = B + (long)(col0 + lr) * K + lk;

    auto issue = [&](int it, int buf) {
        const __half* ap = ag + it * 32;
        const __half* bp = bg + it * 32;
        const uint32_t ad = aS + buf * STAGE_B + dstOff;
        const uint32_t bd = bS + buf * STAGE_B + dstOff;
        cp16(ad, ap); cp16(ad + 16, ap + 8);
        cp16(bd, bp); cp16(bd + 16, bp + 8);
    };

    float acc[2][8][4];
#pragma unroll
    for (int i = 0; i < 2; i++)
#pragma unroll
        for (int j = 0; j < 8; j++)
#pragma unroll
            for (int e = 0; e < 4; e++) acc[i][j][e] = 0.f;

    issue(0, 0); CP_COMMIT();
    issue(1, 1); CP_COMMIT();

    const int arow = wm * 32 + (lid & 15);
    const int akof = (lid >> 4) * 8;
    const int brow = wn * 64 + (lid & 7) + (lid >> 4) * 8;
    const int bkof = ((lid >> 3) & 1) * 8;

    int buf = 0;
    for (int it = 0; it < T; ++it) {
        CP_WAIT1();
        __syncthreads();
        if (it + 2 < T) issue(it + 2, (buf + 2 >= 3) ? buf - 1 : buf + 2);
        CP_COMMIT();

        const uint32_t aBase = aS + buf * STAGE_B;
        const uint32_t bBase = bS + buf * STAGE_B;
#pragma unroll
        for (int ks = 0; ks < 2; ks++) {
            uint32_t af[2][4], bfr[4][4];
#pragma unroll
            for (int mt = 0; mt < 2; mt++)
                ldsm4(af[mt], aBase + (uint32_t)(((arow + mt * 16) * LDSR + ks * 16 + akof) * 2));
#pragma unroll
            for (int p = 0; p < 4; p++)
                ldsm4(bfr[p], bBase + (uint32_t)(((brow + p * 16) * LDSR + ks * 16 + bkof) * 2));
#pragma unroll
            for (int mt = 0; mt < 2; mt++)
#pragma unroll
                for (int nt = 0; nt < 8; nt++)
                    mma_f16(acc[mt][nt], af[mt], &bfr[nt >> 1][(nt & 1) * 2]);
        }
        buf = (buf + 1 >= 3) ? 0 : buf + 1;
    }

    const int mrow = row0 + wm * 32;
    const int ncol = col0 + wn * 64;
    const int r4 = lid >> 2, c2 = (lid & 3) * 2;
#pragma unroll
    for (int mt = 0; mt < 2; mt++) {
#pragma unroll
        for (int half = 0; half < 2; half++) {
            const long r = mrow + mt * 16 + r4 + half * 8;
#pragma unroll
            for (int nt = 0; nt < 8; nt++) {
                const int c = ncol + nt * 8 + c2;
                float v0 = alpha * acc[mt][nt][half * 2 + 0] + (bias ? bias[c + 0] : 0.f);
                float v1 = alpha * acc[mt][nt][half * 2 + 1] + (bias ? bias[c + 1] : 0.f);
                if (HALF_OUT) {
                    __half2 hh; hh.x = __float2half(v0); hh.y = __float2half(v1);
                    *(__half2*)&Ch[cOff + r * N + c] = hh;
                } else {
                    float2 o; o.x = v0; o.y = v1;
                    *(float2*)&C[cOff + r * N + c] = o;
                }
            }
        }
    }
}

// ---------------- mega fused: flash attention + bn GEMM + LN + masked pool ----------------
#define QSTR 528       // Q/K/bn smem row stride in BYTES (264 halves)
#define VSTR 144       // V smem row stride in BYTES (72 halves)
#define FA_QS   0
#define FA_KS0  67584
#define FA_KS1  101376
#define FA_VS0  135168
#define FA_VS1  172032
#define FA_META 208896
#define FA_BIAS 210944   // bn_b[128], bn_g[128], bn_beta[128] fp32
#define FA_POOL 212480   // 8 warps x 128 fp32
#define FA_SMEM 216576

__global__ void __launch_bounds__(256) flash_mega(
    const __half* __restrict__ q16, const __half* __restrict__ k16,
    const __half* __restrict__ vt,  const float* __restrict__ coords,
    const int* __restrict__ mask,   const float* __restrict__ gamma,
    const __half* __restrict__ bnt, const float* __restrict__ bn_b,
    const float* __restrict__ bn_g, const float* __restrict__ bn_beta,
    float* __restrict__ pp)
{
    extern __shared__ char sm[];
    const int b = blockIdx.y;
    const int q0 = blockIdx.x * 128;
    const int tid = threadIdx.x, wid = tid >> 5, lid = tid & 31;

    const uint32_t S = smem_u32(sm);
    const uint32_t Qs = S + FA_QS;
    const uint32_t KsB[2] = {S + FA_KS0, S + FA_KS1};
    const uint32_t VsB[2] = {S + FA_VS0, S + FA_VS1};
    float4* meta = (float4*)(sm + FA_META);

    // ---- issue Q + KV0, KV1 ----
    {
        const int row = tid >> 1, h = tid & 1;
        const __half* src = q16 + (long)(b * NTOK + q0 + row) * DD + h * 128;
        const uint32_t dst = Qs + row * QSTR + h * 256;
#pragma unroll
        for (int i = 0; i < 16; i++) cp16(dst + i * 16, src + i * 8);
    }
    auto issueKV = [&](int t, int bufi) {
        const int kv0 = t * 64;
        {
            const int row = tid >> 2, q4 = tid & 3;
            const __half* src = k16 + (long)(b * NTOK + kv0 + row) * DD + q4 * 64;
            const uint32_t dst = KsB[bufi] + row * QSTR + q4 * 128;
#pragma unroll
            for (int i = 0; i < 8; i++) cp16(dst + i * 16, src + i * 8);
        }
        {
            const __half* src = vt + ((long)b * DD + tid) * NTOK + kv0;
            const uint32_t dst = VsB[bufi] + tid * VSTR;
#pragma unroll
            for (int i = 0; i < 8; i++) cp16(dst + i * 16, src + i * 8);
        }
    };
    auto metaStore = [&](int t, int bufi) {
        if (tid < 64) {
            const int idx = b * NTOK + t * 64 + tid;
            float2 xy = ((const float2*)coords)[idx];
            int mk = mask[idx];
            meta[bufi * 64 + tid] = make_float4(xy.x, xy.y, xy.x * xy.x + xy.y * xy.y,
                                                mk ? 0.f : 1.f);
        }
    };
    issueKV(0, 0); CP_COMMIT();
    issueKV(1, 1); CP_COMMIT();
    metaStore(0, 0);
    metaStore(1, 1);

    const int qrow = q0 + wid * 16 + (lid >> 2);
    const float ga = fabsf(gamma[0]);
    float2 c0v = ((const float2*)coords)[b * NTOK + qrow];
    float2 c1v = ((const float2*)coords)[b * NTOK + qrow + 8];
    const float xn0 = c0v.x, yn0 = c0v.y, sqn0 = c0v.x * c0v.x + c0v.y * c0v.y;
    const float xn1 = c1v.x, yn1 = c1v.y, sqn1 = c1v.x * c1v.x + c1v.y * c1v.y;

    float M0 = -INFINITY, M1 = -INFINITY, Z0 = 0.f, Z1 = 0.f;
    float o[32][4];
#pragma unroll
    for (int i = 0; i < 32; i++)
#pragma unroll
        for (int e = 0; e < 4; e++) o[i][e] = 0.f;

    const int arow = wid * 16 + (lid & 15);
    const int akof = (lid >> 4) * 8;
    const int nrw = (lid & 7) + (lid >> 4) * 8;
    const int nkof = ((lid >> 3) & 1) * 8;

    for (int t = 0; t < 32; ++t) {
        const int cur = t & 1;
        CP_WAIT1();
        __syncthreads();

        // ---- S = Q @ K^T ----
        float s[8][4];
#pragma unroll
        for (int j = 0; j < 8; j++)
#pragma unroll
            for (int e = 0; e < 4; e++) s[j][e] = 0.f;
        const uint32_t kb = KsB[cur];
#pragma unroll
        for (int ks = 0; ks < 16; ks++) {
            uint32_t af[4], bfr[4][4];
            ldsm4(af, Qs + (uint32_t)(arow * QSTR + (ks * 16 + akof) * 2));
#pragma unroll
            for (int p = 0; p < 4; p++)
                ldsm4(bfr[p], kb + (uint32_t)((p * 16 + nrw) * QSTR + (ks * 16 + nkof) * 2));
#pragma unroll
            for (int nt = 0; nt < 8; nt++)
                mma_f16(s[nt], af, &bfr[nt >> 1][(nt & 1) * 2]);
        }

        // ---- online softmax ----
        float mx0 = -INFINITY, mx1 = -INFINITY;
#pragma unroll
        for (int j = 0; j < 8; j++) {
            s[j][0] *= 0.0625f; s[j][1] *= 0.0625f; s[j][2] *= 0.0625f; s[j][3] *= 0.0625f;
            mx0 = fmaxf(mx0, fmaxf(s[j][0], s[j][1]));
            mx1 = fmaxf(mx1, fmaxf(s[j][2], s[j][3]));
        }
        mx0 = fmaxf(mx0, __shfl_xor_sync(0xffffffffu, mx0, 1));
        mx0 = fmaxf(mx0, __shfl_xor_sync(0xffffffffu, mx0, 2));
        mx1 = fmaxf(mx1, __shfl_xor_sync(0xffffffffu, mx1, 1));
        mx1 = fmaxf(mx1, __shfl_xor_sync(0xffffffffu, mx1, 2));
        const float Mn0 = fmaxf(M0, mx0), Mn1 = fmaxf(M1, mx1);
        const float sc0 = __expf(M0 - Mn0), sc1 = __expf(M1 - Mn1);
        M0 = Mn0; M1 = Mn1;
        Z0 *= sc0; Z1 *= sc1;
        if (sc0 != 1.f || sc1 != 1.f) {
#pragma unroll
            for (int nt = 0; nt < 32; nt++) {
                o[nt][0] *= sc0; o[nt][1] *= sc0; o[nt][2] *= sc1; o[nt][3] *= sc1;
            }
        }

        // ---- P and Z ----
        uint32_t pf[16];
        const float4* mt = meta + cur * 64;
#pragma unroll
        for (int j = 0; j < 8; j++) {
            const int cc = 8 * j + (lid & 3) * 2;
            float4 ma = mt[cc], mb = mt[cc + 1];
            float e00 = __expf(s[j][0] - Mn0), e01 = __expf(s[j][1] - Mn0);
            float e10 = __expf(s[j][2] - Mn1), e11 = __expf(s[j][3] - Mn1);
            Z0 += e00 + e01; Z1 += e10 + e11;
            float d2a0 = fmaxf(sqn0 + ma.z - 2.f * (xn0 * ma.x + yn0 * ma.y), 0.f);
            float d2b0 = fmaxf(sqn0 + mb.z - 2.f * (xn0 * mb.x + yn0 * mb.y), 0.f);
            float d2a1 = fmaxf(sqn1 + ma.z - 2.f * (xn1 * ma.x + yn1 * ma.y), 0.f);
            float d2b1 = fmaxf(sqn1 + mb.z - 2.f * (xn1 * mb.x + yn1 * mb.y), 0.f);
            float n00 = e00 * __expf(-ga * sqrtf(d2a0)) * ma.w;
            float n01 = e01 * __expf(-ga * sqrtf(d2b0)) * mb.w;
            float n10 = e10 * __expf(-ga * sqrtf(d2a1)) * ma.w;
            float n11 = e11 * __expf(-ga * sqrtf(d2b1)) * mb.w;
            __half2 p0; p0.x = __float2half(n00); p0.y = __float2half(n01);
            __half2 p1; p1.x = __float2half(n10); p1.y = __float2half(n11);
            pf[2 * j + 0] = *(uint32_t*)&p0;
            pf[2 * j + 1] = *(uint32_t*)&p1;
        }

        // ---- O += P @ V ----
        const uint32_t vb = VsB[cur];
#pragma unroll
        for (int ks = 0; ks < 4; ks++) {
            uint32_t a[4] = {pf[4 * ks + 0], pf[4 * ks + 1], pf[4 * ks + 2], pf[4 * ks + 3]};
#pragma unroll
            for (int p = 0; p < 16; p++) {
                uint32_t bf4[4];
                ldsm4(bf4, vb + (uint32_t)((p * 16 + nrw) * VSTR + (ks * 16 + nkof) * 2));
                mma_f16(o[2 * p + 0], a, &bf4[0]);
                mma_f16(o[2 * p + 1], a, &bf4[2]);
            }
        }

        __syncthreads();
        if (t + 2 < 32) {
            issueKV(t + 2, cur); CP_COMMIT();
            metaStore(t + 2, cur);
        } else {
            CP_COMMIT();
        }
    }

    // ---- finalize Z ----
    Z0 += __shfl_xor_sync(0xffffffffu, Z0, 1);
    Z0 += __shfl_xor_sync(0xffffffffu, Z0, 2);
    Z1 += __shfl_xor_sync(0xffffffffu, Z1, 1);
    Z1 += __shfl_xor_sync(0xffffffffu, Z1, 2);
    const float i0 = 1.f / Z0, i1 = 1.f / Z1;

    // ---- load bn_w^T into Q region + biases into smem ----
    CP_WAIT0();
    __syncthreads();
    {
        const int row = tid >> 1, h = tid & 1;
        const __half* src = bnt + (long)row * DD + h * 128;
        const uint32_t dst = Qs + row * QSTR + h * 256;
#pragma unroll
        for (int i = 0; i < 16; i++) cp16(dst + i * 16, src + i * 8);
        CP_COMMIT();
        float* bb = (float*)(sm + FA_BIAS);
        if (tid < 128)      bb[tid] = bn_b[tid];
        else                bb[tid] = bn_g[tid - 128];     // tid 128..255 -> g[0..127]
        if (tid < 128)      bb[256 + tid] = bn_beta[tid];
    }
    CP_WAIT0();
    __syncthreads();

    // ---- out = (O/Z) @ bn_w + bn_b   (per warp: 16 rows x 128 out-cols) ----
    float acc[16][4];
#pragma unroll
    for (int nt = 0; nt < 16; nt++)
#pragma unroll
        for (int e = 0; e < 4; e++) acc[nt][e] = 0.f;

#pragma unroll
    for (int ks = 0; ks < 16; ks++) {
        __half2 t0 = __floats2half2_rn(o[2 * ks][0] * i0, o[2 * ks][1] * i0);
        __half2 t1 = __floats2half2_rn(o[2 * ks][2] * i1, o[2 * ks][3] * i1);
        __half2 t2 = __floats2half2_rn(o[2 * ks + 1][0] * i0, o[2 * ks + 1][1] * i0);
        __half2 t3 = __floats2half2_rn(o[2 * ks + 1][2] * i1, o[2 * ks + 1][3] * i1);
        uint32_t a[4] = {*(uint32_t*)&t0, *(uint32_t*)&t1, *(uint32_t*)&t2, *(uint32_t*)&t3};
#pragma unroll
        for (int p = 0; p < 8; p++) {
            uint32_t bf4[4];
            ldsm4(bf4, Qs + (uint32_t)((p * 16 + nrw) * QSTR + (ks * 16 + nkof) * 2));
            mma_f16(acc[2 * p + 0], a, &bf4[0]);
            mma_f16(acc[2 * p + 1], a, &bf4[2]);
        }
    }

    // ---- add bias, LayerNorm(128) + ReLU, masked pool contribution ----
    const float* bb = (const float*)(sm + FA_BIAS);
    const int cbase = (lid & 3) * 2;
    float mu0 = 0.f, mu1 = 0.f;
#pragma unroll
    for (int nt = 0; nt < 16; nt++) {
        const int c = 8 * nt + cbase;
        acc[nt][0] += bb[c]; acc[nt][1] += bb[c + 1];
        acc[nt][2] += bb[c]; acc[nt][3] += bb[c + 1];
        mu0 += acc[nt][0] + acc[nt][1];
        mu1 += acc[nt][2] + acc[nt][3];
    }
    mu0 += __shfl_xor_sync(0xffffffffu, mu0, 1);
    mu0 += __shfl_xor_sync(0xffffffffu, mu0, 2);
    mu1 += __shfl_xor_sync(0xffffffffu, mu1, 1);
    mu1 += __shfl_xor_sync(0xffffffffu, mu1, 2);
    mu0 *= (1.f / 128.f); mu1 *= (1.f / 128.f);

    float var0 = 0.f, var1 = 0.f;
#pragma unroll
    for (int nt = 0; nt < 16; nt++) {
        float d0 = acc[nt][0] - mu0, d1 = acc[nt][1] - mu0;
        float d2 = acc[nt][2] - mu1, d3 = acc[nt][3] - mu1;
        var0 += d0 * d0 + d1 * d1;
        var1 += d2 * d2 + d3 * d3;
    }
    var0 += __shfl_xor_sync(0xffffffffu, var0, 1);
    var0 += __shfl_xor_sync(0xffffffffu, var0, 2);
    var1 += __shfl_xor_sync(0xffffffffu, var1, 1);
    var1 += __shfl_xor_sync(0xffffffffu, var1, 2);
    const float rs0 = rsqrtf(var0 * (1.f / 128.f) + 1e-5f);
    const float rs1 = rsqrtf(var1 * (1.f / 128.f) + 1e-5f);

    const float m0 = mask[b * NTOK + qrow] ? 0.f : 1.f;
    const float m1 = mask[b * NTOK + qrow + 8] ? 0.f : 1.f;

    float contrib[16][2];
#pragma unroll
    for (int nt = 0; nt < 16; nt++) {
        const int c = 8 * nt + cbase;
        const float g0 = bb[128 + c], g1 = bb[128 + c + 1];
        const float be0 = bb[256 + c], be1 = bb[256 + c + 1];
        float r00 = fmaxf((acc[nt][0] - mu0) * rs0 * g0 + be0, 0.f);
        float r01 = fmaxf((acc[nt][1] - mu0) * rs0 * g1 + be1, 0.f);
        float r10 = fmaxf((acc[nt][2] - mu1) * rs1 * g0 + be0, 0.f);
        float r11 = fmaxf((acc[nt][3] - mu1) * rs1 * g1 + be1, 0.f);
        contrib[nt][0] = r00 * m0 + r10 * m1;
        contrib[nt][1] = r01 * m0 + r11 * m1;
    }
    // reduce over the 8 row-groups (lanes differing in lid>>2)
#pragma unroll
    for (int nt = 0; nt < 16; nt++) {
#pragma unroll
        for (int off = 4; off < 32; off <<= 1) {
            contrib[nt][0] += __shfl_xor_sync(0xffffffffu, contrib[nt][0], off);
            contrib[nt][1] += __shfl_xor_sync(0xffffffffu, contrib[nt][1], off);
        }
    }
    float* poolw = (float*)(sm + FA_POOL);
    if ((lid >> 2) == 0) {
#pragma unroll
        for (int nt = 0; nt < 16; nt++)
            *(float2*)&poolw[wid * 128 + 8 * nt + cbase] =
                make_float2(contrib[nt][0], contrib[nt][1]);
    }
    __syncthreads();
    if (tid < 128) {
        float s = 0.f;
#pragma unroll
        for (int w = 0; w < 8; w++) s += poolw[w * 128 + tid];
        pp[((long)b * 16 + blockIdx.x) * 128 + tid] = s;
    }
}

// ---------------- elementwise fp32 -> fp16 convert ----------------
__global__ void convert_half(const float* __restrict__ X, __half* __restrict__ Y, int n4)
{
    int i = blockIdx.x * blockDim.x + threadIdx.x;
    if (i >= n4) return;
    float4 v = ((const float4*)X)[i];
    __half2 a; a.x = __float2half(v.x); a.y = __float2half(v.y);
    __half2 b; b.x = __float2half(v.z); b.y = __float2half(v.w);
    ((__half2*)Y)[i * 2 + 0] = a;
    ((__half2*)Y)[i * 2 + 1] = b;
}

// ---------------- transpose helpers ----------------
__device__ __forceinline__ void tr_tile(const float* __restrict__ X, __half* __restrict__ Tt,
                                        int R, int Cc, int txi, int tyi)
{
    __shared__ float t[32][33];
    const int c0 = txi * 32, r0 = tyi * 32;
    for (int i = threadIdx.y; i < 32; i += 8)
        t[i][threadIdx.x] = X[(long)(r0 + i) * Cc + c0 + threadIdx.x];
    __syncthreads();
    for (int i = threadIdx.y; i < 32; i += 8) {
        long o = (long)(c0 + i) * R + r0 + threadIdx.x;
        Tt[o] = __float2half(t[threadIdx.x][i]);
    }
}

// one kernel for all 5 weight transposes (352 tiles)
__global__ void transpose_weights(
    const float* __restrict__ enc_w, const float* __restrict__ wq,
    const float* __restrict__ wk, const float* __restrict__ wv,
    const float* __restrict__ bn_w,
    __half* __restrict__ ent, __half* __restrict__ wqt, __half* __restrict__ wkt,
    __half* __restrict__ wvt, __half* __restrict__ bnt)
{
    const int t = blockIdx.x;
    if (t < 128)        tr_tile(enc_w, ent, CLIPD, DD, t & 7, t >> 3);
    else if (t < 192) { int i = t - 128; tr_tile(wq, wqt, DD, DD, i & 7, i >> 3); }
    else if (t < 256) { int i = t - 192; tr_tile(wk, wkt, DD, DD, i & 7, i >> 3); }
    else if (t < 320) { int i = t - 256; tr_tile(wv, wvt, DD, DD, i & 7, i >> 3); }
    else              { int i = t - 320; tr_tile(bn_w, bnt, DD, BDIM, i & 3, i >> 2); }
}

// batched v transpose: [b][m][d] -> [b][d][m]
__global__ void transpose_half(const float* __restrict__ X, __half* __restrict__ Tt,
                               int R, int Cc)
{
    const long boff = (long)blockIdx.z * R * Cc;
    tr_tile(X + boff, Tt + boff, R, Cc, blockIdx.x, blockIdx.y);
}

// ---------------- block reduction ----------------
__device__ __forceinline__ float blk_sum(float v) {
    __shared__ float sh[33];
    int lane = threadIdx.x & 31, w = threadIdx.x >> 5;
#pragma unroll
    for (int o = 16; o; o >>= 1) v += __shfl_xor_sync(0xffffffffu, v, o);
    __syncthreads();
    if (lane == 0) sh[w] = v;
    __syncthreads();
    if (threadIdx.x == 0) {
        float s = 0.f; int nw = (blockDim.x + 31) >> 5;
        for (int i = 0; i < nw; i++) s += sh[i];
        sh[32] = s;
    }
    __syncthreads();
    return sh[32];
}

// ---------------- LayerNorm + ReLU (enc) ----------------
__global__ void ln_relu_kernel(float* __restrict__ X, const float* __restrict__ g,
                               const float* __restrict__ beta, int D,
                               __half* __restrict__ h16)
{
    const long row = blockIdx.x;
    const int t = threadIdx.x;
    float v = X[row * D + t];
    float mu = blk_sum(v) * (1.f / D);
    float d = v - mu;
    float var = blk_sum(d * d) * (1.f / D);
    float r = d * rsqrtf(var + 1e-5f) * g[t] + beta[t];
    r = fmaxf(r, 0.f);
    h16[row * D + t] = __float2half(r);
}

// ---------------- final: pooled + head MLP ----------------
__global__ void head_kernel(const float* __restrict__ pp, const int* __restrict__ mask,
                            const float* __restrict__ c1w, const float* __restrict__ c1b,
                            const float* __restrict__ c2w, const float* __restrict__ c2b,
                            float* __restrict__ out_f)
{
    const int b = blockIdx.x;
    const int t = threadIdx.x;  // 128
    __shared__ float sp[BDIM];
    __shared__ float hid[64];

    float cf = 0.f;
    for (int n = t; n < NTOK; n += 128) cf += mask[b * NTOK + n] ? 0.f : 1.f;
    const float cnt = fmaxf(blk_sum(cf), 1e-9f);

    float s = 0.f;
#pragma unroll
    for (int ch = 0; ch < 16; ch++) s += pp[((long)b * 16 + ch) * 128 + t];
    const float pooled = s / cnt;
    out_f[BB * NCLS + b * BDIM + t] = pooled;
    sp[t] = pooled;
    __syncthreads();

    if (t < 64) {
        float h = c1b[t];
        for (int i = 0; i < BDIM; i++) h += sp[i] * c1w[i * 64 + t];
        hid[t] = fmaxf(h, 0.f);
    }
    __syncthreads();
    if (t < NCLS) {
        float l = c2b[t];
        for (int j = 0; j < 64; j++) l += hid[j] * c2w[j * NCLS + t];
        out_f[b * NCLS + t] = l;
    }
}

// ---------------- launch ----------------
extern "C" void kernel_launch(void* const* d_in, const int* in_sizes, int n_in,
                              void* d_out, int out_size)
{
    const float* local_feat = (const float*)d_in[0];
    const float* coords     = (const float*)d_in[1];
    const int*   mask       = (const int*)d_in[2];
    const float* enc_w      = (const float*)d_in[3];
    const float* enc_b      = (const float*)d_in[4];
    const float* enc_g      = (const float*)d_in[5];
    const float* enc_beta   = (const float*)d_in[6];
    const float* gamma      = (const float*)d_in[7];
    const float* wq         = (const float*)d_in[8];
    const float* bq         = (const float*)d_in[9];
    const float* wk         = (const float*)d_in[10];
    const float* bk         = (const float*)d_in[11];
    const float* wv         = (const float*)d_in[12];
    const float* bv         = (const float*)d_in[13];
    const float* bn_w       = (const float*)d_in[14];
    const float* bn_b       = (const float*)d_in[15];
    const float* bn_g       = (const float*)d_in[16];
    const float* bn_beta    = (const float*)d_in[17];
    const float* c1_w       = (const float*)d_in[18];
    const float* c1_b       = (const float*)d_in[19];
    const float* c2_w       = (const float*)d_in[20];
    const float* c2_b       = (const float*)d_in[21];

    float *hf, *v, *pp;
    __half *lf, *h16, *q16, *k16, *vt, *ent, *wqt, *wkt, *wvt, *bnt;
    cudaGetSymbolAddress((void**)&lf,  g_lf);
    cudaGetSymbolAddress((void**)&hf,  g_hf);
    cudaGetSymbolAddress((void**)&h16, g_h16);
    cudaGetSymbolAddress((void**)&q16, g_q16);
    cudaGetSymbolAddress((void**)&k16, g_k16);
    cudaGetSymbolAddress((void**)&v,   g_v);
    cudaGetSymbolAddress((void**)&vt,  g_vt);
    cudaGetSymbolAddress((void**)&ent, g_ent);
    cudaGetSymbolAddress((void**)&wqt, g_wqt);
    cudaGetSymbolAddress((void**)&wkt, g_wkt);
    cudaGetSymbolAddress((void**)&wvt, g_wvt);
    cudaGetSymbolAddress((void**)&bnt, g_bnt);
    cudaGetSymbolAddress((void**)&pp,  g_pp);

    cudaFuncSetAttribute(gemm_mma<false>, cudaFuncAttributeMaxDynamicSharedMemorySize, GEMM_SMEM);
    cudaFuncSetAttribute(gemm_mma<true>,  cudaFuncAttributeMaxDynamicSharedMemorySize, GEMM_SMEM);
    cudaFuncSetAttribute(flash_mega,      cudaFuncAttributeMaxDynamicSharedMemorySize, FA_SMEM);

    // 0) conversions
    convert_half<<<(ROWS * CLIPD / 4 + 255) / 256, 256>>>(local_feat, lf, ROWS * CLIPD / 4);
    transpose_weights<<<352, dim3(32, 8)>>>(enc_w, wq, wk, wv, bn_w, ent, wqt, wkt, wvt, bnt);

    // 1) enc GEMM + LN
    gemm_mma<false><<<dim3(DD / 128, ROWS / 128, 1), 256, GEMM_SMEM>>>(
        lf, ent, hf, nullptr, DD, CLIPD, 0, 0, 0, 1.f, enc_b);
    ln_relu_kernel<<<ROWS, DD>>>(hf, enc_g, enc_beta, DD, h16);

    // 2) q, k, v
    gemm_mma<true><<<dim3(DD / 128, ROWS / 128, 1), 256, GEMM_SMEM>>>(
        h16, wqt, nullptr, q16, DD, DD, 0, 0, 0, 1.f, bq);
    gemm_mma<true><<<dim3(DD / 128, ROWS / 128, 1), 256, GEMM_SMEM>>>(
        h16, wkt, nullptr, k16, DD, DD, 0, 0, 0, 1.f, bk);
    gemm_mma<false><<<dim3(DD / 128, ROWS / 128, 1), 256, GEMM_SMEM>>>(
        h16, wvt, v, nullptr, DD, DD, 0, 0, 0, 1.f, bv);
    transpose_half<<<dim3(DD / 32, NTOK / 32, BB), dim3(32, 8)>>>(v, vt, NTOK, DD);

    // 3) mega fused attention + bn + LN + pool partials
    flash_mega<<<dim3(NTOK / 128, BB), 256, FA_SMEM>>>(
        q16, k16, vt, coords, mask, gamma, bnt, bn_b, bn_g, bn_beta, pp);

    // 4) pooled + head -> d_out
    head_kernel<<<BB, 128>>>(pp, mask, c1_w, c1_b, c2_w, c2_b, (float*)d_out);
}

// round 11
// speedup vs baseline: 4.2804x; 1.0760x over previous
#include <cuda_runtime.h>
#include <cuda_fp16.h>
#include <math.h>
#include <stdint.h>

#define BB 8
#define NTOK 2048
#define CLIPD 512
#define DD 256
#define BDIM 128
#define NCLS 10
#define ROWS (BB * NTOK)   // 16384
#define QKVN 768

// ---------------- scratch (no cudaMalloc allowed) ----------------
__device__ __half g_lf  [ROWS * CLIPD];
__device__ float  g_hf  [ROWS * DD];           // enc out fp32
__device__ __half g_h16 [ROWS * DD];
__device__ __half g_qkv [ROWS * QKVN];         // q | k | v fp16, row stride 768
__device__ __half g_ent [DD * CLIPD];          // enc_w^T
__device__ __half g_wqkvt[QKVN * DD];          // [wq^T ; wk^T ; wv^T]
__device__ float  g_bqkv[QKVN];
__device__ __half g_bnt [BDIM * DD];           // bn_w^T [128][256]
__device__ float  g_pp  [BB * 16 * BDIM];      // pool partials per (b, q-tile)

// ---------------- mma / ldmatrix / cp.async helpers ----------------
__device__ __forceinline__ uint32_t smem_u32(const void* p) {
    uint32_t a;
    asm("{ .reg .u64 t; cvta.to.shared.u64 t, %1; cvt.u32.u64 %0, t; }" : "=r"(a) : "l"(p));
    return a;
}
__device__ __forceinline__ void ldsm4(uint32_t* r, uint32_t addr) {
    asm volatile("ldmatrix.sync.aligned.m8n8.x4.shared.b16 {%0,%1,%2,%3}, [%4];"
                 : "=r"(r[0]), "=r"(r[1]), "=r"(r[2]), "=r"(r[3]) : "r"(addr));
}
__device__ __forceinline__ void ldsm4t(uint32_t* r, uint32_t addr) {
    asm volatile("ldmatrix.sync.aligned.m8n8.x4.trans.shared.b16 {%0,%1,%2,%3}, [%4];"
                 : "=r"(r[0]), "=r"(r[1]), "=r"(r[2]), "=r"(r[3]) : "r"(addr));
}
__device__ __forceinline__ void mma_f16(float* d, const uint32_t* a, const uint32_t* b) {
    asm volatile(
        "mma.sync.aligned.m16n8k16.row.col.f32.f16.f16.f32 "
        "{%0,%1,%2,%3}, {%4,%5,%6,%7}, {%8,%9}, {%0,%1,%2,%3};"
        : "+f"(d[0]), "+f"(d[1]), "+f"(d[2]), "+f"(d[3])
        : "r"(a[0]), "r"(a[1]), "r"(a[2]), "r"(a[3]), "r"(b[0]), "r"(b[1]));
}
__device__ __forceinline__ void cp16(uint32_t dst, const void* src) {
    asm volatile("cp.async.cg.shared.global [%0], [%1], 16;" :: "r"(dst), "l"(src));
}
#define CP_COMMIT() asm volatile("cp.async.commit_group;" ::: "memory")
#define CP_WAIT1()  asm volatile("cp.async.wait_group 1;" ::: "memory")
#define CP_WAIT0()  asm volatile("cp.async.wait_group 0;" ::: "memory")

// ---------------- fp16 HMMA GEMM, 3-stage cp.async pipeline ----------------
#define LDSR 40
#define STAGE_B (128 * LDSR * 2)
#define GEMM_SMEM (6 * STAGE_B)

template <bool HALF_OUT>
__global__ void __launch_bounds__(256) gemm_mma(
    const __half* __restrict__ A, const __half* __restrict__ B,
    float* __restrict__ C, __half* __restrict__ Ch,
    int N, int K, float alpha, const float* __restrict__ bias)
{
    extern __shared__ char smem[];
    const int tid = threadIdx.x;
    const int wid = tid >> 5, lid = tid & 31;
    const int wm = wid & 3, wn = wid >> 2;
    const int row0 = blockIdx.y * 128;
    const int col0 = blockIdx.x * 128;
    const int T = K / 32;

    const int lr = tid >> 1;
    const int lk = (tid & 1) * 16;

    const uint32_t sBase = smem_u32(smem);
    const uint32_t aS = sBase;
    const uint32_t bS = sBase + 3 * STAGE_B;
    const uint32_t dstOff = (uint32_t)(lr * LDSR + lk) * 2;

    const __half* ag = A + (long)(row0 + lr) * K + lk;
    const __half* bg = B + (long)(col0 + lr) * K + lk;

    auto issue = [&](int it, int buf) {
        const __half* ap = ag + it * 32;
        const __half* bp = bg + it * 32;
        const uint32_t ad = aS + buf * STAGE_B + dstOff;
        const uint32_t bd = bS + buf * STAGE_B + dstOff;
        cp16(ad, ap); cp16(ad + 16, ap + 8);
        cp16(bd, bp); cp16(bd + 16, bp + 8);
    };

    float acc[2][8][4];
#pragma unroll
    for (int i = 0; i < 2; i++)
#pragma unroll
        for (int j = 0; j < 8; j++)
#pragma unroll
            for (int e = 0; e < 4; e++) acc[i][j][e] = 0.f;

    issue(0, 0); CP_COMMIT();
    issue(1, 1); CP_COMMIT();

    const int arow = wm * 32 + (lid & 15);
    const int akof = (lid >> 4) * 8;
    const int brow = wn * 64 + (lid & 7) + (lid >> 4) * 8;
    const int bkof = ((lid >> 3) & 1) * 8;

    int buf = 0;
    for (int it = 0; it < T; ++it) {
        CP_WAIT1();
        __syncthreads();
        if (it + 2 < T) issue(it + 2, (buf + 2 >= 3) ? buf - 1 : buf + 2);
        CP_COMMIT();

        const uint32_t aBase = aS + buf * STAGE_B;
        const uint32_t bBase = bS + buf * STAGE_B;
#pragma unroll
        for (int ks = 0; ks < 2; ks++) {
            uint32_t af[2][4], bfr[4][4];
#pragma unroll
            for (int mt = 0; mt < 2; mt++)
                ldsm4(af[mt], aBase + (uint32_t)(((arow + mt * 16) * LDSR + ks * 16 + akof) * 2));
#pragma unroll
            for (int p = 0; p < 4; p++)
                ldsm4(bfr[p], bBase + (uint32_t)(((brow + p * 16) * LDSR + ks * 16 + bkof) * 2));
#pragma unroll
            for (int mt = 0; mt < 2; mt++)
#pragma unroll
                for (int nt = 0; nt < 8; nt++)
                    mma_f16(acc[mt][nt], af[mt], &bfr[nt >> 1][(nt & 1) * 2]);
        }
        buf = (buf + 1 >= 3) ? 0 : buf + 1;
    }

    const int mrow = row0 + wm * 32;
    const int ncol = col0 + wn * 64;
    const int r4 = lid >> 2, c2 = (lid & 3) * 2;
#pragma unroll
    for (int mt = 0; mt < 2; mt++) {
#pragma unroll
        for (int half = 0; half < 2; half++) {
            const long r = mrow + mt * 16 + r4 + half * 8;
#pragma unroll
            for (int nt = 0; nt < 8; nt++) {
                const int c = ncol + nt * 8 + c2;
                float v0 = alpha * acc[mt][nt][half * 2 + 0] + (bias ? bias[c + 0] : 0.f);
                float v1 = alpha * acc[mt][nt][half * 2 + 1] + (bias ? bias[c + 1] : 0.f);
                if (HALF_OUT) {
                    __half2 hh; hh.x = __float2half(v0); hh.y = __float2half(v1);
                    *(__half2*)&Ch[r * N + c] = hh;
                } else {
                    float2 o; o.x = v0; o.y = v1;
                    *(float2*)&C[r * N + c] = o;
                }
            }
        }
    }
}

// ---------------- mega fused: flash attention + bn GEMM + LN + masked pool ----------------
// Q/K/V all read from qkv [rows][768]: q at col 0, k at 256, v at 512.
// K, V tiles both stored [64 kv rows][256], row stride 528 bytes.
#define QSTR 528
#define KVTILE 33792     // 64 * 528
#define FA_QS   0
#define FA_KS0  67584
#define FA_KS1  (FA_KS0 + KVTILE)
#define FA_VS0  (FA_KS1 + KVTILE)
#define FA_VS1  (FA_VS0 + KVTILE)
#define FA_META (FA_VS1 + KVTILE)      // 202752
#define FA_BIAS (FA_META + 2048)       // 204800: bn_b[128], bn_g[128], bn_beta[128]
#define FA_POOL (FA_BIAS + 1536)       // 206336: 8 warps x 128 fp32
#define FA_SMEM (FA_POOL + 4096)       // 210432

__global__ void __launch_bounds__(256) flash_mega(
    const __half* __restrict__ qkv, const float* __restrict__ coords,
    const int* __restrict__ mask,   const float* __restrict__ gamma,
    const __half* __restrict__ bnt, const float* __restrict__ bn_b,
    const float* __restrict__ bn_g, const float* __restrict__ bn_beta,
    float* __restrict__ pp)
{
    extern __shared__ char sm[];
    const int b = blockIdx.y;
    const int q0 = blockIdx.x * 128;
    const int tid = threadIdx.x, wid = tid >> 5, lid = tid & 31;

    const uint32_t S = smem_u32(sm);
    const uint32_t Qs = S + FA_QS;
    const uint32_t KsB[2] = {S + FA_KS0, S + FA_KS1};
    const uint32_t VsB[2] = {S + FA_VS0, S + FA_VS1};
    float4* meta = (float4*)(sm + FA_META);

    // ---- issue Q + KV0, KV1 ----
    {
        const int row = tid >> 1, h = tid & 1;
        const __half* src = qkv + (long)(b * NTOK + q0 + row) * QKVN + h * 128;
        const uint32_t dst = Qs + row * QSTR + h * 256;
#pragma unroll
        for (int i = 0; i < 16; i++) cp16(dst + i * 16, src + i * 8);
    }
    auto issueKV = [&](int t, int bufi) {
        const int kv0 = t * 64;
        const int row = tid >> 2, q4 = tid & 3;
        const __half* base = qkv + (long)(b * NTOK + kv0 + row) * QKVN;
        {
            const __half* src = base + 256 + q4 * 64;
            const uint32_t dst = KsB[bufi] + row * QSTR + q4 * 128;
#pragma unroll
            for (int i = 0; i < 8; i++) cp16(dst + i * 16, src + i * 8);
        }
        {
            const __half* src = base + 512 + q4 * 64;
            const uint32_t dst = VsB[bufi] + row * QSTR + q4 * 128;
#pragma unroll
            for (int i = 0; i < 8; i++) cp16(dst + i * 16, src + i * 8);
        }
    };
    auto metaStore = [&](int t, int bufi) {
        if (tid < 64) {
            const int idx = b * NTOK + t * 64 + tid;
            float2 xy = ((const float2*)coords)[idx];
            int mk = mask[idx];
            meta[bufi * 64 + tid] = make_float4(xy.x, xy.y, xy.x * xy.x + xy.y * xy.y,
                                                mk ? 0.f : 1.f);
        }
    };
    issueKV(0, 0); CP_COMMIT();
    issueKV(1, 1); CP_COMMIT();
    metaStore(0, 0);
    metaStore(1, 1);

    const int qrow = q0 + wid * 16 + (lid >> 2);
    const float ga = fabsf(gamma[0]);
    float2 c0v = ((const float2*)coords)[b * NTOK + qrow];
    float2 c1v = ((const float2*)coords)[b * NTOK + qrow + 8];
    const float xn0 = c0v.x, yn0 = c0v.y, sqn0 = c0v.x * c0v.x + c0v.y * c0v.y;
    const float xn1 = c1v.x, yn1 = c1v.y, sqn1 = c1v.x * c1v.x + c1v.y * c1v.y;

    float M0 = -INFINITY, M1 = -INFINITY, Z0 = 0.f, Z1 = 0.f;
    float o[32][4];
#pragma unroll
    for (int i = 0; i < 32; i++)
#pragma unroll
        for (int e = 0; e < 4; e++) o[i][e] = 0.f;

    const int arow = wid * 16 + (lid & 15);
    const int akof = (lid >> 4) * 8;
    const int nrw = (lid & 7) + (lid >> 4) * 8;
    const int nkof = ((lid >> 3) & 1) * 8;
    // V trans-ldmatrix lane mapping: rows k0..k15 (lanes 0-15 / 16-31), col n0 / n0+8
    const int vrow = lid & 15;
    const int vcb  = (lid >> 4) * 16;   // col offset in bytes

    for (int t = 0; t < 32; ++t) {
        const int cur = t & 1;
        CP_WAIT1();
        __syncthreads();

        // ---- S = Q @ K^T ----
        float s[8][4];
#pragma unroll
        for (int j = 0; j < 8; j++)
#pragma unroll
            for (int e = 0; e < 4; e++) s[j][e] = 0.f;
        const uint32_t kb = KsB[cur];
#pragma unroll
        for (int ks = 0; ks < 16; ks++) {
            uint32_t af[4], bfr[4][4];
            ldsm4(af, Qs + (uint32_t)(arow * QSTR + (ks * 16 + akof) * 2));
#pragma unroll
            for (int p = 0; p < 4; p++)
                ldsm4(bfr[p], kb + (uint32_t)((p * 16 + nrw) * QSTR + (ks * 16 + nkof) * 2));
#pragma unroll
            for (int nt = 0; nt < 8; nt++)
                mma_f16(s[nt], af, &bfr[nt >> 1][(nt & 1) * 2]);
        }

        // ---- online softmax ----
        float mx0 = -INFINITY, mx1 = -INFINITY;
#pragma unroll
        for (int j = 0; j < 8; j++) {
            s[j][0] *= 0.0625f; s[j][1] *= 0.0625f; s[j][2] *= 0.0625f; s[j][3] *= 0.0625f;
            mx0 = fmaxf(mx0, fmaxf(s[j][0], s[j][1]));
            mx1 = fmaxf(mx1, fmaxf(s[j][2], s[j][3]));
        }
        mx0 = fmaxf(mx0, __shfl_xor_sync(0xffffffffu, mx0, 1));
        mx0 = fmaxf(mx0, __shfl_xor_sync(0xffffffffu, mx0, 2));
        mx1 = fmaxf(mx1, __shfl_xor_sync(0xffffffffu, mx1, 1));
        mx1 = fmaxf(mx1, __shfl_xor_sync(0xffffffffu, mx1, 2));
        const float Mn0 = fmaxf(M0, mx0), Mn1 = fmaxf(M1, mx1);
        const float sc0 = __expf(M0 - Mn0), sc1 = __expf(M1 - Mn1);
        M0 = Mn0; M1 = Mn1;
        Z0 *= sc0; Z1 *= sc1;
        if (sc0 != 1.f || sc1 != 1.f) {
#pragma unroll
            for (int nt = 0; nt < 32; nt++) {
                o[nt][0] *= sc0; o[nt][1] *= sc0; o[nt][2] *= sc1; o[nt][3] *= sc1;
            }
        }

        // ---- P and Z ----
        uint32_t pf[16];
        const float4* mt = meta + cur * 64;
#pragma unroll
        for (int j = 0; j < 8; j++) {
            const int cc = 8 * j + (lid & 3) * 2;
            float4 ma = mt[cc], mb = mt[cc + 1];
            float e00 = __expf(s[j][0] - Mn0), e01 = __expf(s[j][1] - Mn0);
            float e10 = __expf(s[j][2] - Mn1), e11 = __expf(s[j][3] - Mn1);
            Z0 += e00 + e01; Z1 += e10 + e11;
            float d2a0 = fmaxf(sqn0 + ma.z - 2.f * (xn0 * ma.x + yn0 * ma.y), 0.f);
            float d2b0 = fmaxf(sqn0 + mb.z - 2.f * (xn0 * mb.x + yn0 * mb.y), 0.f);
            float d2a1 = fmaxf(sqn1 + ma.z - 2.f * (xn1 * ma.x + yn1 * ma.y), 0.f);
            float d2b1 = fmaxf(sqn1 + mb.z - 2.f * (xn1 * mb.x + yn1 * mb.y), 0.f);
            float n00 = e00 * __expf(-ga * sqrtf(d2a0)) * ma.w;
            float n01 = e01 * __expf(-ga * sqrtf(d2b0)) * mb.w;
            float n10 = e10 * __expf(-ga * sqrtf(d2a1)) * ma.w;
            float n11 = e11 * __expf(-ga * sqrtf(d2b1)) * mb.w;
            __half2 p0; p0.x = __float2half(n00); p0.y = __float2half(n01);
            __half2 p1; p1.x = __float2half(n10); p1.y = __float2half(n11);
            pf[2 * j + 0] = *(uint32_t*)&p0;
            pf[2 * j + 1] = *(uint32_t*)&p1;
        }

        // ---- O += P @ V  (V row-major [kv][d], B frags via ldmatrix.trans) ----
        const uint32_t vb = VsB[cur];
#pragma unroll
        for (int ks = 0; ks < 4; ks++) {
            uint32_t a[4] = {pf[4 * ks + 0], pf[4 * ks + 1], pf[4 * ks + 2], pf[4 * ks + 3]};
            const uint32_t rowb = vb + (uint32_t)((ks * 16 + vrow) * QSTR + vcb);
#pragma unroll
            for (int p = 0; p < 16; p++) {
                uint32_t bf4[4];
                ldsm4t(bf4, rowb + (uint32_t)(p * 32));
                mma_f16(o[2 * p + 0], a, &bf4[0]);
                mma_f16(o[2 * p + 1], a, &bf4[2]);
            }
        }

        __syncthreads();
        if (t + 2 < 32) {
            issueKV(t + 2, cur); CP_COMMIT();
            metaStore(t + 2, cur);
        } else {
            CP_COMMIT();
        }
    }

    // ---- finalize Z ----
    Z0 += __shfl_xor_sync(0xffffffffu, Z0, 1);
    Z0 += __shfl_xor_sync(0xffffffffu, Z0, 2);
    Z1 += __shfl_xor_sync(0xffffffffu, Z1, 1);
    Z1 += __shfl_xor_sync(0xffffffffu, Z1, 2);
    const float i0 = 1.f / Z0, i1 = 1.f / Z1;

    // ---- load bn_w^T into Q region + biases into smem ----
    CP_WAIT0();
    __syncthreads();
    {
        const int row = tid >> 1, h = tid & 1;
        const __half* src = bnt + (long)row * DD + h * 128;
        const uint32_t dst = Qs + row * QSTR + h * 256;
#pragma unroll
        for (int i = 0; i < 16; i++) cp16(dst + i * 16, src + i * 8);
        CP_COMMIT();
        float* bb = (float*)(sm + FA_BIAS);
        if (tid < 128)      bb[tid] = bn_b[tid];
        else                bb[tid] = bn_g[tid - 128];
        if (tid < 128)      bb[256 + tid] = bn_beta[tid];
    }
    CP_WAIT0();
    __syncthreads();

    // ---- out = (O/Z) @ bn_w + bn_b ----
    float acc[16][4];
#pragma unroll
    for (int nt = 0; nt < 16; nt++)
#pragma unroll
        for (int e = 0; e < 4; e++) acc[nt][e] = 0.f;

#pragma unroll
    for (int ks = 0; ks < 16; ks++) {
        __half2 t0 = __floats2half2_rn(o[2 * ks][0] * i0, o[2 * ks][1] * i0);
        __half2 t1 = __floats2half2_rn(o[2 * ks][2] * i1, o[2 * ks][3] * i1);
        __half2 t2 = __floats2half2_rn(o[2 * ks + 1][0] * i0, o[2 * ks + 1][1] * i0);
        __half2 t3 = __floats2half2_rn(o[2 * ks + 1][2] * i1, o[2 * ks + 1][3] * i1);
        uint32_t a[4] = {*(uint32_t*)&t0, *(uint32_t*)&t1, *(uint32_t*)&t2, *(uint32_t*)&t3};
#pragma unroll
        for (int p = 0; p < 8; p++) {
            uint32_t bf4[4];
            ldsm4(bf4, Qs + (uint32_t)((p * 16 + nrw) * QSTR + (ks * 16 + nkof) * 2));
            mma_f16(acc[2 * p + 0], a, &bf4[0]);
            mma_f16(acc[2 * p + 1], a, &bf4[2]);
        }
    }

    // ---- bias, LayerNorm(128) + ReLU, masked pool ----
    const float* bb = (const float*)(sm + FA_BIAS);
    const int cbase = (lid & 3) * 2;
    float mu0 = 0.f, mu1 = 0.f;
#pragma unroll
    for (int nt = 0; nt < 16; nt++) {
        const int c = 8 * nt + cbase;
        acc[nt][0] += bb[c]; acc[nt][1] += bb[c + 1];
        acc[nt][2] += bb[c]; acc[nt][3] += bb[c + 1];
        mu0 += acc[nt][0] + acc[nt][1];
        mu1 += acc[nt][2] + acc[nt][3];
    }
    mu0 += __shfl_xor_sync(0xffffffffu, mu0, 1);
    mu0 += __shfl_xor_sync(0xffffffffu, mu0, 2);
    mu1 += __shfl_xor_sync(0xffffffffu, mu1, 1);
    mu1 += __shfl_xor_sync(0xffffffffu, mu1, 2);
    mu0 *= (1.f / 128.f); mu1 *= (1.f / 128.f);

    float var0 = 0.f, var1 = 0.f;
#pragma unroll
    for (int nt = 0; nt < 16; nt++) {
        float d0 = acc[nt][0] - mu0, d1 = acc[nt][1] - mu0;
        float d2 = acc[nt][2] - mu1, d3 = acc[nt][3] - mu1;
        var0 += d0 * d0 + d1 * d1;
        var1 += d2 * d2 + d3 * d3;
    }
    var0 += __shfl_xor_sync(0xffffffffu, var0, 1);
    var0 += __shfl_xor_sync(0xffffffffu, var0, 2);
    var1 += __shfl_xor_sync(0xffffffffu, var1, 1);
    var1 += __shfl_xor_sync(0xffffffffu, var1, 2);
    const float rs0 = rsqrtf(var0 * (1.f / 128.f) + 1e-5f);
    const float rs1 = rsqrtf(var1 * (1.f / 128.f) + 1e-5f);

    const float m0 = mask[b * NTOK + qrow] ? 0.f : 1.f;
    const float m1 = mask[b * NTOK + qrow + 8] ? 0.f : 1.f;

    float contrib[16][2];
#pragma unroll
    for (int nt = 0; nt < 16; nt++) {
        const int c = 8 * nt + cbase;
        const float g0 = bb[128 + c], g1 = bb[128 + c + 1];
        const float be0 = bb[256 + c], be1 = bb[256 + c + 1];
        float r00 = fmaxf((acc[nt][0] - mu0) * rs0 * g0 + be0, 0.f);
        float r01 = fmaxf((acc[nt][1] - mu0) * rs0 * g1 + be1, 0.f);
        float r10 = fmaxf((acc[nt][2] - mu1) * rs1 * g0 + be0, 0.f);
        float r11 = fmaxf((acc[nt][3] - mu1) * rs1 * g1 + be1, 0.f);
        contrib[nt][0] = r00 * m0 + r10 * m1;
        contrib[nt][1] = r01 * m0 + r11 * m1;
    }
#pragma unroll
    for (int nt = 0; nt < 16; nt++) {
#pragma unroll
        for (int off = 4; off < 32; off <<= 1) {
            contrib[nt][0] += __shfl_xor_sync(0xffffffffu, contrib[nt][0], off);
            contrib[nt][1] += __shfl_xor_sync(0xffffffffu, contrib[nt][1], off);
        }
    }
    float* poolw = (float*)(sm + FA_POOL);
    if ((lid >> 2) == 0) {
#pragma unroll
        for (int nt = 0; nt < 16; nt++)
            *(float2*)&poolw[wid * 128 + 8 * nt + cbase] =
                make_float2(contrib[nt][0], contrib[nt][1]);
    }
    __syncthreads();
    if (tid < 128) {
        float s = 0.f;
#pragma unroll
        for (int w = 0; w < 8; w++) s += poolw[w * 128 + tid];
        pp[((long)b * 16 + blockIdx.x) * 128 + tid] = s;
    }
}

// ---------------- elementwise fp32 -> fp16 convert ----------------
__global__ void convert_half(const float* __restrict__ X, __half* __restrict__ Y, int n4)
{
    int i = blockIdx.x * blockDim.x + threadIdx.x;
    if (i >= n4) return;
    float4 v = ((const float4*)X)[i];
    __half2 a; a.x = __float2half(v.x); a.y = __float2half(v.y);
    __half2 b; b.x = __float2half(v.z); b.y = __float2half(v.w);
    ((__half2*)Y)[i * 2 + 0] = a;
    ((__half2*)Y)[i * 2 + 1] = b;
}

// ---------------- transpose helpers ----------------
__device__ __forceinline__ void tr_tile(const float* __restrict__ X, __half* __restrict__ Tt,
                                        int R, int Cc, int txi, int tyi)
{
    __shared__ float t[32][33];
    const int c0 = txi * 32, r0 = tyi * 32;
    for (int i = threadIdx.y; i < 32; i += 8)
        t[i][threadIdx.x] = X[(long)(r0 + i) * Cc + c0 + threadIdx.x];
    __syncthreads();
    for (int i = threadIdx.y; i < 32; i += 8) {
        long o = (long)(c0 + i) * R + r0 + threadIdx.x;
        Tt[o] = __float2half(t[threadIdx.x][i]);
    }
}

// all weight transposes + qkv bias concat in one kernel (353 blocks)
__global__ void transpose_weights(
    const float* __restrict__ enc_w, const float* __restrict__ wq,
    const float* __restrict__ wk, const float* __restrict__ wv,
    const float* __restrict__ bn_w,
    const float* __restrict__ bq, const float* __restrict__ bk,
    const float* __restrict__ bv,
    __half* __restrict__ ent, __half* __restrict__ wqkvt, __half* __restrict__ bnt,
    float* __restrict__ bqkv)
{
    const int t = blockIdx.x;
    if (t < 128)        tr_tile(enc_w, ent, CLIPD, DD, t & 7, t >> 3);
    else if (t < 192) { int i = t - 128; tr_tile(wq, wqkvt,            DD, DD, i & 7, i >> 3); }
    else if (t < 256) { int i = t - 192; tr_tile(wk, wqkvt + 256 * DD, DD, DD, i & 7, i >> 3); }
    else if (t < 320) { int i = t - 256; tr_tile(wv, wqkvt + 512 * DD, DD, DD, i & 7, i >> 3); }
    else if (t < 352) { int i = t - 320; tr_tile(bn_w, bnt, DD, BDIM, i & 3, i >> 2); }
    else {
        const int id = threadIdx.y * 32 + threadIdx.x;  // 0..255
        bqkv[id]       = bq[id];
        bqkv[256 + id] = bk[id];
        bqkv[512 + id] = bv[id];
    }
}

// ---------------- warp-per-row LayerNorm + ReLU (D=256) ----------------
__global__ void __launch_bounds__(256) ln_relu_kernel(
    const float* __restrict__ X, const float* __restrict__ g,
    const float* __restrict__ beta, __half* __restrict__ h16)
{
    const int wid = threadIdx.x >> 5, lid = threadIdx.x & 31;
    const long row = (long)blockIdx.x * 8 + wid;
    const float4* xr = (const float4*)(X + row * DD);
    float4 v0 = xr[lid], v1 = xr[lid + 32];

    float s = v0.x + v0.y + v0.z + v0.w + v1.x + v1.y + v1.z + v1.w;
#pragma unroll
    for (int o = 16; o; o >>= 1) s += __shfl_xor_sync(0xffffffffu, s, o);
    const float mu = s * (1.f / 256.f);

    float d0x = v0.x - mu, d0y = v0.y - mu, d0z = v0.z - mu, d0w = v0.w - mu;
    float d1x = v1.x - mu, d1y = v1.y - mu, d1z = v1.z - mu, d1w = v1.w - mu;
    float vs = d0x * d0x + d0y * d0y + d0z * d0z + d0w * d0w
             + d1x * d1x + d1y * d1y + d1z * d1z + d1w * d1w;
#pragma unroll
    for (int o = 16; o; o >>= 1) vs += __shfl_xor_sync(0xffffffffu, vs, o);
    const float rstd = rsqrtf(vs * (1.f / 256.f) + 1e-5f);

    float4 g0 = ((const float4*)g)[lid],    g1 = ((const float4*)g)[lid + 32];
    float4 b0 = ((const float4*)beta)[lid], b1 = ((const float4*)beta)[lid + 32];

    __half2 h0, h1, h2, h3;
    h0.x = __float2half(fmaxf(d0x * rstd * g0.x + b0.x, 0.f));
    h0.y = __float2half(fmaxf(d0y * rstd * g0.y + b0.y, 0.f));
    h1.x = __float2half(fmaxf(d0z * rstd * g0.z + b0.z, 0.f));
    h1.y = __float2half(fmaxf(d0w * rstd * g0.w + b0.w, 0.f));
    h2.x = __float2half(fmaxf(d1x * rstd * g1.x + b1.x, 0.f));
    h2.y = __float2half(fmaxf(d1y * rstd * g1.y + b1.y, 0.f));
    h3.x = __float2half(fmaxf(d1z * rstd * g1.z + b1.z, 0.f));
    h3.y = __float2half(fmaxf(d1w * rstd * g1.w + b1.w, 0.f));
    __half2* yr = (__half2*)(h16 + row * DD);
    yr[lid * 2 + 0] = h0; yr[lid * 2 + 1] = h1;
    yr[64 + lid * 2 + 0] = h2; yr[64 + lid * 2 + 1] = h3;
}

// ---------------- block reduction (head) ----------------
__device__ __forceinline__ float blk_sum(float v) {
    __shared__ float sh[33];
    int lane = threadIdx.x & 31, w = threadIdx.x >> 5;
#pragma unroll
    for (int o = 16; o; o >>= 1) v += __shfl_xor_sync(0xffffffffu, v, o);
    __syncthreads();
    if (lane == 0) sh[w] = v;
    __syncthreads();
    if (threadIdx.x == 0) {
        float s = 0.f; int nw = (blockDim.x + 31) >> 5;
        for (int i = 0; i < nw; i++) s += sh[i];
        sh[32] = s;
    }
    __syncthreads();
    return sh[32];
}

// ---------------- final: pooled + head MLP ----------------
__global__ void head_kernel(const float* __restrict__ pp, const int* __restrict__ mask,
                            const float* __restrict__ c1w, const float* __restrict__ c1b,
                            const float* __restrict__ c2w, const float* __restrict__ c2b,
                            float* __restrict__ out_f)
{
    const int b = blockIdx.x;
    const int t = threadIdx.x;  // 128
    __shared__ float sp[BDIM];
    __shared__ float hid[64];

    float cf = 0.f;
    for (int n = t; n < NTOK; n += 128) cf += mask[b * NTOK + n] ? 0.f : 1.f;
    const float cnt = fmaxf(blk_sum(cf), 1e-9f);

    float s = 0.f;
#pragma unroll
    for (int ch = 0; ch < 16; ch++) s += pp[((long)b * 16 + ch) * 128 + t];
    const float pooled = s / cnt;
    out_f[BB * NCLS + b * BDIM + t] = pooled;
    sp[t] = pooled;
    __syncthreads();

    if (t < 64) {
        float h = c1b[t];
        for (int i = 0; i < BDIM; i++) h += sp[i] * c1w[i * 64 + t];
        hid[t] = fmaxf(h, 0.f);
    }
    __syncthreads();
    if (t < NCLS) {
        float l = c2b[t];
        for (int j = 0; j < 64; j++) l += hid[j] * c2w[j * NCLS + t];
        out_f[b * NCLS + t] = l;
    }
}

// ---------------- launch ----------------
extern "C" void kernel_launch(void* const* d_in, const int* in_sizes, int n_in,
                              void* d_out, int out_size)
{
    const float* local_feat = (const float*)d_in[0];
    const float* coords     = (const float*)d_in[1];
    const int*   mask       = (const int*)d_in[2];
    const float* enc_w      = (const float*)d_in[3];
    const float* enc_b      = (const float*)d_in[4];
    const float* enc_g      = (const float*)d_in[5];
    const float* enc_beta   = (const float*)d_in[6];
    const float* gamma      = (const float*)d_in[7];
    const float* wq         = (const float*)d_in[8];
    const float* bq         = (const float*)d_in[9];
    const float* wk         = (const float*)d_in[10];
    const float* bk         = (const float*)d_in[11];
    const float* wv         = (const float*)d_in[12];
    const float* bv         = (const float*)d_in[13];
    const float* bn_w       = (const float*)d_in[14];
    const float* bn_b       = (const float*)d_in[15];
    const float* bn_g       = (const float*)d_in[16];
    const float* bn_beta    = (const float*)d_in[17];
    const float* c1_w       = (const float*)d_in[18];
    const float* c1_b       = (const float*)d_in[19];
    const float* c2_w       = (const float*)d_in[20];
    const float* c2_b       = (const float*)d_in[21];

    float *hf, *pp, *bqkv;
    __half *lf, *h16, *qkv, *ent, *wqkvt, *bnt;
    cudaGetSymbolAddress((void**)&lf,    g_lf);
    cudaGetSymbolAddress((void**)&hf,    g_hf);
    cudaGetSymbolAddress((void**)&h16,   g_h16);
    cudaGetSymbolAddress((void**)&qkv,   g_qkv);
    cudaGetSymbolAddress((void**)&ent,   g_ent);
    cudaGetSymbolAddress((void**)&wqkvt, g_wqkvt);
    cudaGetSymbolAddress((void**)&bqkv,  g_bqkv);
    cudaGetSymbolAddress((void**)&bnt,   g_bnt);
    cudaGetSymbolAddress((void**)&pp,    g_pp);

    cudaFuncSetAttribute(gemm_mma<false>, cudaFuncAttributeMaxDynamicSharedMemorySize, GEMM_SMEM);
    cudaFuncSetAttribute(gemm_mma<true>,  cudaFuncAttributeMaxDynamicSharedMemorySize, GEMM_SMEM);
    cudaFuncSetAttribute(flash_mega,      cudaFuncAttributeMaxDynamicSharedMemorySize, FA_SMEM);

    // 0) conversions
    convert_half<<<(ROWS * CLIPD / 4 + 255) / 256, 256>>>(local_feat, lf, ROWS * CLIPD / 4);
    transpose_weights<<<353, dim3(32, 8)>>>(enc_w, wq, wk, wv, bn_w, bq, bk, bv,
                                            ent, wqkvt, bnt, bqkv);

    // 1) enc GEMM + LN
    gemm_mma<false><<<dim3(DD / 128, ROWS / 128), 256, GEMM_SMEM>>>(
        lf, ent, hf, nullptr, DD, CLIPD, 1.f, enc_b);
    ln_relu_kernel<<<ROWS / 8, 256>>>(hf, enc_g, enc_beta, h16);

    // 2) fused qkv GEMM  (M=16384, N=768, K=256) -> qkv fp16 [rows][768]
    gemm_mma<true><<<dim3(QKVN / 128, ROWS / 128), 256, GEMM_SMEM>>>(
        h16, wqkvt, nullptr, qkv, QKVN, DD, 1.f, bqkv);

    // 3) mega fused attention + bn + LN + pool partials
    flash_mega<<<dim3(NTOK / 128, BB), 256, FA_SMEM>>>(
        qkv, coords, mask, gamma, bnt, bn_b, bn_g, bn_beta, pp);

    // 4) pooled + head -> d_out
    head_kernel<<<BB, 128>>>(pp, mask, c1_w, c1_b, c2_w, c2_b, (float*)d_out);
}